// round 6
// baseline (speedup 1.0000x reference)
#include <cuda_runtime.h>
#include <cuda_bf16.h>
#include <stdint.h>

#define Bz 64
#define Sz 256
#define Ez 512
#define Hz 1024
#define G4 4096   // 4*Hz
#define Dz 512
#define Cz 2

// ---------------- device scratch (no cudaMalloc allowed) ----------------
__device__ __align__(128) float g_xw2[(size_t)Sz * G4 * Bz];        // [s][n'][b]
__device__ __align__(128) __nv_bfloat16 g_wt_hi[(size_t)G4 * Hz];   // Wh^T [n'][k]
__device__ __align__(128) __nv_bfloat16 g_wt_lo[(size_t)G4 * Hz];
__device__ __align__(128) __nv_bfloat16 g_wx_hi[(size_t)G4 * Ez];   // Wx^T [n'][k]
__device__ __align__(128) __nv_bfloat16 g_wx_lo[(size_t)G4 * Ez];
__device__ __align__(128) __nv_bfloat16 g_a_hi[(size_t)Sz * Bz * Ez]; // gathered emb [m][k]
__device__ __align__(128) __nv_bfloat16 g_a_lo[(size_t)Sz * Bz * Ez];
__device__ __align__(128) __nv_bfloat16 g_h_hi[2][(size_t)Bz * Hz];  // h [b][k] ping-pong
__device__ __align__(128) __nv_bfloat16 g_h_lo[2][(size_t)Bz * Hz];
__device__ __align__(128) float g_bias2[G4];                         // permuted bias
__device__ __align__(128) float g_c[Hz * Bz];                        // cell [c][b]
__device__ __align__(128) float g_final[(size_t)Bz * Hz];            // [b][h]
__device__ __align__(128) float g_dense[Bz * Dz];
__device__ __align__(128) int g_leaf[8];                             // tree barrier leaves
__device__ int g_root;                                               // tree barrier root
__device__ int g_flag;                                               // release flag

// ================= PTX helpers (non-'a' features only) =================
__device__ __forceinline__ uint32_t smem_u32(const void* p) {
    uint32_t a;
    asm("{ .reg .u64 t; cvta.to.shared.u64 t, %1; cvt.u32.u64 %0, t; }" : "=r"(a) : "l"(p));
    return a;
}
#define CP16(dst, src) \
    asm volatile("cp.async.cg.shared.global [%0], [%1], 16;" :: "r"((uint32_t)(dst)), "l"(src))
#define CP_COMMIT() asm volatile("cp.async.commit_group;" ::: "memory")
#define CP_WAITN(n) asm volatile("cp.async.wait_group %0;" :: "n"(n) : "memory")

#define LDSM4(r, addr) \
    asm volatile("ldmatrix.sync.aligned.m8n8.x4.shared.b16 {%0,%1,%2,%3}, [%4];" \
        : "=r"((r)[0]), "=r"((r)[1]), "=r"((r)[2]), "=r"((r)[3]) : "r"(addr))
#define LDSM2(r, addr) \
    asm volatile("ldmatrix.sync.aligned.m8n8.x2.shared.b16 {%0,%1}, [%2];" \
        : "=r"((r)[0]), "=r"((r)[1]) : "r"(addr))
#define MMA(d, a, b) \
    asm volatile("mma.sync.aligned.m16n8k16.row.col.f32.bf16.bf16.f32 " \
        "{%0,%1,%2,%3},{%4,%5,%6,%7},{%8,%9},{%0,%1,%2,%3};" \
        : "+f"((d)[0]), "+f"((d)[1]), "+f"((d)[2]), "+f"((d)[3]) \
        : "r"((a)[0]), "r"((a)[1]), "r"((a)[2]), "r"((a)[3]), "r"((b)[0]), "r"((b)[1]))

__device__ __forceinline__ float sigm(float x) { return 1.f / (1.f + __expf(-x)); }
__device__ __forceinline__ float tanh_f(float x) { return 1.f - 2.f / (__expf(2.f * x) + 1.f); }

// ---------------- geometry ----------------
// xw kernel (128 threads, 2-stage, 64x64 tiles)
#define ROWB 272
#define MATB (64 * ROWB)      // 17408
#define BUFB (4 * MATB)       // 69632 (Ah, Al, Bh, Bl)
#define SMEM_XW (2 * BUFB)    // 139264

// persistent step kernel (256 threads)
#define WROWB 2064                       // 1024 bf16 + 16B pad
#define WMATB (32 * WROWB)               // 66048
#define W_HI 0
#define W_LO WMATB                       // 66048
#define ASTG (2 * WMATB)                 // 132096
// A stage: 8 sub-tiles (4 K-quarters x hi/lo), each 64 rows x 32 bf16 (80B rows)
#define QSUB 5120                        // 64 * 80
#define ASTGB (8 * QSUB)                 // 40960 per stage
#define GS_OFF (ASTG + 2 * ASTGB)        // 214016 ; Gs = 32 x 68 f32 = 8704
#define HS_OFF (GS_OFF + 8704)           // 222720 ; Hs hi/lo = 2048
#define SMEM_ST (HS_OFF + 2048)          // 224768

// ---------------- init: zero h and c, reset barrier ----------------
__global__ void init_kernel() {
    int i = blockIdx.x * blockDim.x + threadIdx.x;
    if (i == 0) { g_root = 0; g_flag = 0; }
    if (i < 8) g_leaf[i] = 0;
    if (i < Bz * Hz) {
        __nv_bfloat16 z = __float2bfloat16(0.f);
        g_h_hi[0][i] = z; g_h_hi[1][i] = z;
        g_h_lo[0][i] = z; g_h_lo[1][i] = z;
        g_c[i] = 0.f;
    }
}

// ---------------- prep: transpose+split W -> [n'=c*4+g][k] bf16 hi/lo ----------------
__global__ __launch_bounds__(256) void prep_tr(const float* __restrict__ src, int K, int sel) {
    __shared__ float tile[32][33];
    int n0 = blockIdx.x * 32, k0 = blockIdx.y * 32;
    int tx = threadIdx.x & 31, ty = threadIdx.x >> 5;   // 32 x 8
#pragma unroll
    for (int r = 0; r < 4; r++)
        tile[ty + r * 8][tx] = src[(size_t)(k0 + ty + r * 8) * G4 + n0 + tx];
    __syncthreads();
    __nv_bfloat16* dh = sel ? g_wt_hi : g_wx_hi;
    __nv_bfloat16* dl = sel ? g_wt_lo : g_wx_lo;
#pragma unroll
    for (int r = 0; r < 4; r++) {
        int n = n0 + ty + r * 8;
        int np = (n & 1023) * 4 + (n >> 10);
        float v = tile[tx][ty + r * 8];
        __nv_bfloat16 hi = __float2bfloat16(v);
        dh[(size_t)np * K + k0 + tx] = hi;
        dl[(size_t)np * K + k0 + tx] = __float2bfloat16(v - __bfloat162float(hi));
    }
}

// ---------------- prep: gather emb rows, split to bf16 hi/lo [m][k] ----------------
__global__ void prep_emb(const int* __restrict__ X, const float* __restrict__ emb) {
    int m = blockIdx.x;                 // m = s*64+b
    int s = m >> 6, b = m & 63;
    int row = X[b * Sz + s];
    const float4* src = (const float4*)(emb + (size_t)row * Ez);
    int k4 = threadIdx.x;
    float4 v = src[k4];
    __nv_bfloat16 hx = __float2bfloat16(v.x), hy = __float2bfloat16(v.y);
    __nv_bfloat16 hz = __float2bfloat16(v.z), hw = __float2bfloat16(v.w);
    __nv_bfloat162* dh = (__nv_bfloat162*)(g_a_hi + (size_t)m * Ez);
    __nv_bfloat162* dl = (__nv_bfloat162*)(g_a_lo + (size_t)m * Ez);
    dh[k4 * 2]     = __nv_bfloat162(hx, hy);
    dh[k4 * 2 + 1] = __nv_bfloat162(hz, hw);
    dl[k4 * 2]     = __nv_bfloat162(__float2bfloat16(v.x - __bfloat162float(hx)),
                                    __float2bfloat16(v.y - __bfloat162float(hy)));
    dl[k4 * 2 + 1] = __nv_bfloat162(__float2bfloat16(v.z - __bfloat162float(hz)),
                                    __float2bfloat16(v.w - __bfloat162float(hw)));
}

__global__ void prep_bias(const float* __restrict__ bias) {
    int n = blockIdx.x * blockDim.x + threadIdx.x;
    if (n < G4) g_bias2[(n & 1023) * 4 + (n >> 10)] = bias[n];
}

// ---------------- xw GEMM building blocks (128 threads) ----------------
__device__ __forceinline__ void load_mat(uint32_t dst, const __nv_bfloat16* src,
                                         int stride_elems, int tid) {
#pragma unroll
    for (int i = 0; i < 8; i++) {
        int idx = i * 128 + tid;
        int row = idx >> 4, seg = idx & 15;
        CP16(dst + row * ROWB + seg * 16,
             (const char*)(src + (size_t)row * stride_elems) + seg * 16);
    }
}

__device__ __forceinline__ void compute_chunk(uint32_t buf, int lane, int mbase, int nbase,
                                              float acc[2][4][4]) {
    const uint32_t aH = buf, aL = buf + MATB, bH = buf + 2 * MATB, bL = buf + 3 * MATB;
    const int g = lane >> 3;
    const int arow = (lane & 7) + ((g & 1) << 3);
    const int ahalf = (g >> 1) * 16;
    const int brow = lane & 7;
    const int bhalf = ((lane >> 3) & 1) * 16;
#pragma unroll
    for (int k16 = 0; k16 < 8; k16++) {
        const uint32_t kb = k16 * 32;
        uint32_t ah[2][4], al[2][4], bh[4][2], bl[4][2];
#pragma unroll
        for (int mt = 0; mt < 2; mt++) {
            uint32_t ao = (uint32_t)((mbase + mt * 16 + arow) * ROWB) + kb + ahalf;
            LDSM4(ah[mt], aH + ao);
            LDSM4(al[mt], aL + ao);
        }
#pragma unroll
        for (int nt = 0; nt < 4; nt++) {
            uint32_t bo = (uint32_t)((nbase + nt * 8 + brow) * ROWB) + kb + bhalf;
            LDSM2(bh[nt], bH + bo);
            LDSM2(bl[nt], bL + bo);
        }
#pragma unroll
        for (int mt = 0; mt < 2; mt++)
#pragma unroll
            for (int nt = 0; nt < 4; nt++) {
                MMA(acc[mt][nt], ah[mt], bh[nt]);
                MMA(acc[mt][nt], ah[mt], bl[nt]);
                MMA(acc[mt][nt], al[mt], bh[nt]);
            }
    }
}

__device__ __forceinline__ void store_frags_to_Gs(float* Gs, int lane, int mbase, int nbase,
                                                  float acc[2][4][4]) {
    const int r = lane >> 2, c2 = (lane & 3) * 2;
#pragma unroll
    for (int mt = 0; mt < 2; mt++)
#pragma unroll
        for (int nt = 0; nt < 4; nt++) {
            int m = mbase + mt * 16 + r;
            int n = nbase + nt * 8 + c2;
            Gs[n * 68 + m]           = acc[mt][nt][0];
            Gs[(n + 1) * 68 + m]     = acc[mt][nt][1];
            Gs[n * 68 + m + 8]       = acc[mt][nt][2];
            Gs[(n + 1) * 68 + m + 8] = acc[mt][nt][3];
        }
}

// ---------------- xw GEMM: g_xw2[s][n'][b] = emb_m @ Wx^T + bias (bf16x3) ----------------
__global__ __launch_bounds__(128, 1) void xw_mma() {
    extern __shared__ char smem[];
    const uint32_t sb = smem_u32(smem);
    const int tid = threadIdx.x, lane = tid & 31, w = tid >> 5;
    const int np0 = blockIdx.x * 64;
    const int s = blockIdx.y;
    const __nv_bfloat16* Ah = g_a_hi + (size_t)s * Bz * Ez;
    const __nv_bfloat16* Al = g_a_lo + (size_t)s * Bz * Ez;
    const __nv_bfloat16* Bh = g_wx_hi + (size_t)np0 * Ez;
    const __nv_bfloat16* Bl = g_wx_lo + (size_t)np0 * Ez;

    float acc[2][4][4] = {};
    const int mbase = (w & 1) * 32, nbase = (w >> 1) * 32;

    load_mat(sb, Ah, Ez, tid);
    load_mat(sb + MATB, Al, Ez, tid);
    load_mat(sb + 2 * MATB, Bh, Ez, tid);
    load_mat(sb + 3 * MATB, Bl, Ez, tid);
    CP_COMMIT();

    for (int c = 0; c < 4; c++) {
        if (c < 3) {
            int kc = (c + 1) * 128;
            uint32_t buf = sb + ((c + 1) & 1) * BUFB;
            load_mat(buf, Ah + kc, Ez, tid);
            load_mat(buf + MATB, Al + kc, Ez, tid);
            load_mat(buf + 2 * MATB, Bh + kc, Ez, tid);
            load_mat(buf + 3 * MATB, Bl + kc, Ez, tid);
            CP_COMMIT();
            CP_WAITN(1);
        } else {
            CP_WAITN(0);
        }
        __syncthreads();
        compute_chunk(sb + (c & 1) * BUFB, lane, mbase, nbase, acc);
        __syncthreads();
    }

    float* Gs = (float*)smem;   // [64][68]
    store_frags_to_Gs(Gs, lane, mbase, nbase, acc);
    __syncthreads();

    float* outb = g_xw2 + ((size_t)s * G4 + np0) * Bz;
#pragma unroll
    for (int i = 0; i < 32; i++) {
        int e = i * 128 + tid;               // e = n'local*64 + b
        int nl = e >> 6, b = e & 63;
        outb[e] = Gs[nl * 68 + b] + g_bias2[np0 + nl];
    }
}

// ---------------- persistent LSTM recurrence ----------------
// 128 CTAs x 256 threads. CTA owns 32 n' (8 h-cols). W smem-resident.
// Warps: ksec = w&3 (K quarter, 256 wide), mh = w>>2 (32 batch rows). Tile 32x32.
__device__ __forceinline__ void gbar_tree(int t, int tid, int blk) {
    __syncthreads();
    if (tid == 0) {
        int grp = blk >> 4;
        int old;
        asm volatile("atom.add.acq_rel.gpu.global.s32 %0, [%1], 1;"
                     : "=r"(old) : "l"(&g_leaf[grp]) : "memory");
        if (old == 16 * t - 1) {
            int rold;
            asm volatile("atom.add.acq_rel.gpu.global.s32 %0, [%1], 1;"
                         : "=r"(rold) : "l"(&g_root) : "memory");
            if (rold == 8 * t - 1) {
                asm volatile("st.release.gpu.global.s32 [%0], %1;"
                             :: "l"(&g_flag), "r"(t) : "memory");
            }
        }
        int f;
        do {
            asm volatile("ld.acquire.gpu.global.s32 %0, [%1];" : "=r"(f) : "l"(&g_flag));
        } while (f < t);
    }
    __syncthreads();
}

// load one stage: 32-wide K slice for all 4 quarters, hi+lo (2048 CP16 / 256 thr)
__device__ __forceinline__ void load_stage(uint32_t dst, int cs,
                                           const __nv_bfloat16* h_hi,
                                           const __nv_bfloat16* h_lo, int tid) {
#pragma unroll
    for (int i = 0; i < 8; i++) {
        int idx = i * 256 + tid;           // 0..2047
        int sub = idx >> 8;                // 0..7 = quarter*2 + hi/lo
        int r = (idx >> 2) & 63;
        int seg = idx & 3;
        int q = sub >> 1;
        const __nv_bfloat16* src = (sub & 1) ? h_lo : h_hi;
        CP16(dst + (uint32_t)sub * QSUB + (uint32_t)r * 80 + seg * 16,
             (const char*)(src + (size_t)r * Hz + q * 256 + cs * 32) + seg * 16);
    }
}

__global__ __launch_bounds__(256, 1) void steps_persistent(const int* __restrict__ seqlen) {
    extern __shared__ char smem[];
    const uint32_t sb = smem_u32(smem);
    const int tid = threadIdx.x, lane = tid & 31, w = tid >> 5;
    const int blk = blockIdx.x;
    const int np0 = blk * 32, c0 = blk * 8;
    const int ksec = w & 3;              // K quarter
    const int mh = w >> 2;               // batch half (0/1)
    const int sl_b = __ldg(seqlen + (tid & 63));

    // ---- load W resident: 32 rows x 1024 k, hi+lo ----
#pragma unroll
    for (int i = 0; i < 16; i++) {
        int idx = i * 256 + tid;
        int row = idx >> 7, seg = idx & 127;
        CP16(sb + W_HI + row * WROWB + seg * 16,
             (const char*)(g_wt_hi + (size_t)(np0 + row) * Hz) + seg * 16);
    }
#pragma unroll
    for (int i = 0; i < 16; i++) {
        int idx = i * 256 + tid;
        int row = idx >> 7, seg = idx & 127;
        CP16(sb + W_LO + row * WROWB + seg * 16,
             (const char*)(g_wt_lo + (size_t)(np0 + row) * Hz) + seg * 16);
    }
    CP_COMMIT();

    float* Gs = (float*)(smem + GS_OFF);                     // [32 n'][68 m]
    __nv_bfloat16* HsH = (__nv_bfloat16*)(smem + HS_OFF);    // [64][8]
    __nv_bfloat16* HsL = (__nv_bfloat16*)(smem + HS_OFF + 1024);

    for (int t = 0; t < Sz; t++) {
        const __nv_bfloat16* h_hi = g_h_hi[t & 1];
        const __nv_bfloat16* h_lo = g_h_lo[t & 1];
        __nv_bfloat16* o_hi = g_h_hi[(t + 1) & 1];
        __nv_bfloat16* o_lo = g_h_lo[(t + 1) & 1];

        // epilogue operand prefetch (xw static, c CTA-local) — before barrier
        const float* xwb = g_xw2 + ((size_t)t * G4 + np0) * Bz;
        float xg[2][4], cold[2];
        {
            const int b = tid & 63;
#pragma unroll
            for (int i = 0; i < 2; i++) {
                int col = (i * 256 + tid) >> 6;
#pragma unroll
                for (int g = 0; g < 4; g++)
                    xg[i][g] = __ldg(xwb + (col * 4 + g) * Bz + b);
                cold[i] = g_c[(c0 + col) * Bz + b];
            }
        }

        if (t > 0) gbar_tree(t, tid, blk);                   // all CTAs finished t-1

        // zero Gs (consumed by red-adds after the K loop)
#pragma unroll
        for (int i = 0; i < 9; i++) {
            int idx = i * 256 + tid;
            if (idx < 32 * 68) Gs[idx] = 0.f;
        }

        load_stage(sb + ASTG, 0, h_hi, h_lo, tid);
        CP_COMMIT();

        float acc[2][4][4] = {};                             // [mt][nt][4]
        for (int cs = 0; cs < 8; cs++) {
            if (cs < 7) {
                load_stage(sb + ASTG + (uint32_t)((cs + 1) & 1) * ASTGB,
                           cs + 1, h_hi, h_lo, tid);
                CP_COMMIT();
                CP_WAITN(1);
            } else {
                CP_WAITN(0);
            }
            __syncthreads();

            const uint32_t aq = sb + ASTG + (uint32_t)(cs & 1) * ASTGB
                                + (uint32_t)(ksec * 2) * QSUB;
#pragma unroll
            for (int kk = 0; kk < 2; kk++) {
                uint32_t ah[2][4], al[2][4], bh[4][2], bl[4][2];
#pragma unroll
                for (int mt = 0; mt < 2; mt++) {
                    uint32_t ao = (uint32_t)((mh * 32 + mt * 16 + (lane & 15)) * 80)
                                  + kk * 32 + (lane >> 4) * 16;
                    LDSM4(ah[mt], aq + ao);
                    LDSM4(al[mt], aq + QSUB + ao);
                }
                uint32_t kb = (uint32_t)(ksec * 256 + cs * 32 + kk * 16) * 2
                              + ((lane >> 3) & 1) * 16;
#pragma unroll
                for (int nt = 0; nt < 4; nt++) {
                    uint32_t bo = (uint32_t)((nt * 8 + (lane & 7)) * WROWB) + kb;
                    LDSM2(bh[nt], sb + W_HI + bo);
                    LDSM2(bl[nt], sb + W_LO + bo);
                }
#pragma unroll
                for (int mt = 0; mt < 2; mt++)
#pragma unroll
                    for (int nt = 0; nt < 4; nt++) {
                        MMA(acc[mt][nt], ah[mt], bh[nt]);
                        MMA(acc[mt][nt], ah[mt], bl[nt]);
                        MMA(acc[mt][nt], al[mt], bh[nt]);
                    }
            }
            __syncthreads();
        }

        // combine K quarters: red-add fragments into Gs
        {
            const int r = lane >> 2, c2 = (lane & 3) * 2;
#pragma unroll
            for (int mt = 0; mt < 2; mt++)
#pragma unroll
                for (int nt = 0; nt < 4; nt++) {
                    int m = mh * 32 + mt * 16 + r;
                    int n = nt * 8 + c2;
                    atomicAdd(&Gs[n * 68 + m],           acc[mt][nt][0]);
                    atomicAdd(&Gs[(n + 1) * 68 + m],     acc[mt][nt][1]);
                    atomicAdd(&Gs[n * 68 + m + 8],       acc[mt][nt][2]);
                    atomicAdd(&Gs[(n + 1) * 68 + m + 8], acc[mt][nt][3]);
                }
        }
        __syncthreads();

        // pointwise LSTM for 8 cols x 64 batch
        const bool is_last = (t == sl_b - 1);
#pragma unroll
        for (int i = 0; i < 2; i++) {
            int e = i * 256 + tid;
            int col = e >> 6, b = e & 63;
            float ig = Gs[(col * 4 + 0) * 68 + b] + xg[i][0];
            float jg = Gs[(col * 4 + 1) * 68 + b] + xg[i][1];
            float fg = Gs[(col * 4 + 2) * 68 + b] + xg[i][2];
            float og = Gs[(col * 4 + 3) * 68 + b] + xg[i][3];
            float cn = cold[i] * sigm(fg + 1.0f) + sigm(ig) * tanh_f(jg);
            float hn = tanh_f(cn) * sigm(og);
            g_c[(c0 + col) * Bz + b] = cn;
            __nv_bfloat16 hi = __float2bfloat16(hn);
            HsH[b * 8 + col] = hi;
            HsL[b * 8 + col] = __float2bfloat16(hn - __bfloat162float(hi));
            if (is_last) g_final[(size_t)b * Hz + c0 + col] = hn;
        }
        __syncthreads();

        // coalesced 16B h writes
        if (tid < 64) {
            *(uint4*)(o_hi + (size_t)tid * Hz + c0) = *(uint4*)(HsH + tid * 8);
        } else if (tid < 128) {
            int b = tid - 64;
            *(uint4*)(o_lo + (size_t)b * Hz + c0) = *(uint4*)(HsL + b * 8);
        }
    }
}

// ---------------- dense = relu(final @ dense_w + dense_b) ----------------
__global__ void dense_kernel(const float* __restrict__ dw, const float* __restrict__ db) {
    int b = blockIdx.x;
    int d = threadIdx.x;    // 512 threads
    const float* f = g_final + (size_t)b * Hz;
    float s0 = 0.f, s1 = 0.f, s2 = 0.f, s3 = 0.f;
#pragma unroll 4
    for (int k = 0; k < Hz; k += 4) {
        s0 += f[k]     * dw[(size_t)(k)     * Dz + d];
        s1 += f[k + 1] * dw[(size_t)(k + 1) * Dz + d];
        s2 += f[k + 2] * dw[(size_t)(k + 2) * Dz + d];
        s3 += f[k + 3] * dw[(size_t)(k + 3) * Dz + d];
    }
    float s = (s0 + s1) + (s2 + s3) + db[d];
    g_dense[(size_t)b * Dz + d] = fmaxf(s, 0.f);
}

// ---------------- logits = dense @ pred_w + pred_b ----------------
__global__ void logits_kernel(const float* __restrict__ pw, const float* __restrict__ pb,
                              float* __restrict__ out) {
    int tid = threadIdx.x;
    if (tid >= Bz * Cz) return;
    int b = tid >> 1;
    int cc = tid & 1;
    const float* dn = g_dense + (size_t)b * Dz;
    float s = 0.f;
#pragma unroll 4
    for (int d = 0; d < Dz; d++) s += dn[d] * pw[(size_t)d * Cz + cc];
    out[b * Cz + cc] = s + pb[cc];
}

// ---------------- launch ----------------
extern "C" void kernel_launch(void* const* d_in, const int* in_sizes, int n_in,
                              void* d_out, int out_size) {
    const int*   X      = (const int*)d_in[0];
    const int*   seqlen = (const int*)d_in[1];
    const float* emb    = (const float*)d_in[2];
    const float* Wf     = (const float*)d_in[3];   // [1536, 4096]
    const float* bias   = (const float*)d_in[4];
    const float* dw     = (const float*)d_in[5];
    const float* db     = (const float*)d_in[6];
    const float* pw     = (const float*)d_in[7];
    const float* pb     = (const float*)d_in[8];
    float* out = (float*)d_out;

    cudaFuncSetAttribute(xw_mma, cudaFuncAttributeMaxDynamicSharedMemorySize, SMEM_XW);
    cudaFuncSetAttribute(steps_persistent, cudaFuncAttributeMaxDynamicSharedMemorySize, SMEM_ST);

    init_kernel<<<(Bz * Hz + 255) / 256, 256>>>();
    prep_tr<<<dim3(G4 / 32, Ez / 32), 256>>>(Wf, Ez, 0);                   // Wx
    prep_tr<<<dim3(G4 / 32, Hz / 32), 256>>>(Wf + (size_t)Ez * G4, Hz, 1); // Wh
    prep_emb<<<Sz * Bz, 128>>>(X, emb);
    prep_bias<<<G4 / 256, 256>>>(bias);

    xw_mma<<<dim3(G4 / 64, Sz), 128, SMEM_XW>>>();

    steps_persistent<<<128, 256, SMEM_ST>>>(seqlen);

    dense_kernel<<<Bz, Dz>>>(dw, db);
    logits_kernel<<<1, 128>>>(pw, pb, out);
}

// round 7
// speedup vs baseline: 1.1343x; 1.1343x over previous
#include <cuda_runtime.h>
#include <cuda_bf16.h>
#include <stdint.h>

#define Bz 64
#define Sz 256
#define Ez 512
#define Hz 1024
#define G4 4096   // 4*Hz
#define Dz 512
#define Cz 2

// ---------------- device scratch (no cudaMalloc allowed) ----------------
__device__ __align__(128) float g_xw2[(size_t)Sz * G4 * Bz];        // [s][n'][b]
__device__ __align__(128) __nv_bfloat16 g_wt_hi[(size_t)G4 * Hz];   // Wh^T [n'][k]
__device__ __align__(128) __nv_bfloat16 g_wt_lo[(size_t)G4 * Hz];
__device__ __align__(128) __nv_bfloat16 g_wx_hi[(size_t)G4 * Ez];   // Wx^T [n'][k]
__device__ __align__(128) __nv_bfloat16 g_wx_lo[(size_t)G4 * Ez];
__device__ __align__(128) __nv_bfloat16 g_a_hi[(size_t)Sz * Bz * Ez]; // gathered emb [m][k]
__device__ __align__(128) __nv_bfloat16 g_a_lo[(size_t)Sz * Bz * Ez];
__device__ __align__(128) __nv_bfloat16 g_h_hi[2][(size_t)Bz * Hz];  // h [b][k] ping-pong
__device__ __align__(128) __nv_bfloat16 g_h_lo[2][(size_t)Bz * Hz];
__device__ __align__(128) float g_bias2[G4];                         // permuted bias
__device__ __align__(128) float g_c[Hz * Bz];                        // cell [c][b]
__device__ __align__(128) float g_final[(size_t)Bz * Hz];            // [b][h]
__device__ __align__(128) float g_dense[Bz * Dz];
__device__ __align__(128) int g_kflag[8];   // per-chunk monotonic producer counters

// ================= PTX helpers (non-'a' features only) =================
__device__ __forceinline__ uint32_t smem_u32(const void* p) {
    uint32_t a;
    asm("{ .reg .u64 t; cvta.to.shared.u64 t, %1; cvt.u32.u64 %0, t; }" : "=r"(a) : "l"(p));
    return a;
}
#define CP16(dst, src) \
    asm volatile("cp.async.cg.shared.global [%0], [%1], 16;" :: "r"((uint32_t)(dst)), "l"(src))
#define CP_COMMIT() asm volatile("cp.async.commit_group;" ::: "memory")
#define CP_WAITN(n) asm volatile("cp.async.wait_group %0;" :: "n"(n) : "memory")

#define LDSM4(r, addr) \
    asm volatile("ldmatrix.sync.aligned.m8n8.x4.shared.b16 {%0,%1,%2,%3}, [%4];" \
        : "=r"((r)[0]), "=r"((r)[1]), "=r"((r)[2]), "=r"((r)[3]) : "r"(addr))
#define LDSM2(r, addr) \
    asm volatile("ldmatrix.sync.aligned.m8n8.x2.shared.b16 {%0,%1}, [%2];" \
        : "=r"((r)[0]), "=r"((r)[1]) : "r"(addr))
#define MMA(d, a, b) \
    asm volatile("mma.sync.aligned.m16n8k16.row.col.f32.bf16.bf16.f32 " \
        "{%0,%1,%2,%3},{%4,%5,%6,%7},{%8,%9},{%0,%1,%2,%3};" \
        : "+f"((d)[0]), "+f"((d)[1]), "+f"((d)[2]), "+f"((d)[3]) \
        : "r"((a)[0]), "r"((a)[1]), "r"((a)[2]), "r"((a)[3]), "r"((b)[0]), "r"((b)[1]))

__device__ __forceinline__ float sigm(float x) { return 1.f / (1.f + __expf(-x)); }
__device__ __forceinline__ float tanh_f(float x) { return 1.f - 2.f / (__expf(2.f * x) + 1.f); }

// ---------------- geometry ----------------
// xw kernel (128 threads, 2-stage, 64x64 tiles)
#define ROWB 272
#define MATB (64 * ROWB)      // 17408
#define BUFB (4 * MATB)       // 69632 (Ah, Al, Bh, Bl)
#define SMEM_XW (2 * BUFB)    // 139264

// persistent step kernel (256 threads): W resident + 2-stage A + staging
#define WROWB 2064                       // 1024 bf16 + 16B pad
#define WMATB (32 * WROWB)               // 66048
#define W_HI 0
#define W_LO WMATB                       // 66048
#define ASTG (2 * WMATB)                 // 132096
#define ASTGB (2 * MATB)                 // 34816 per stage (hi+lo)
#define GS_OFF (ASTG + 2 * ASTGB)        // 201728 ; Gs = 32 x 68 f32 = 8704
#define HS_OFF (GS_OFF + 8704)           // 210432 ; Hs hi/lo = 2048
#define SMEM_ST (HS_OFF + 2048)          // 212480

// ---------------- init: zero h and c, reset flags ----------------
__global__ void init_kernel() {
    int i = blockIdx.x * blockDim.x + threadIdx.x;
    if (i < 8) g_kflag[i] = 0;
    if (i < Bz * Hz) {
        __nv_bfloat16 z = __float2bfloat16(0.f);
        g_h_hi[0][i] = z; g_h_hi[1][i] = z;
        g_h_lo[0][i] = z; g_h_lo[1][i] = z;
        g_c[i] = 0.f;
    }
}

// ---------------- prep: transpose+split W -> [n'=c*4+g][k] bf16 hi/lo ----------------
__global__ __launch_bounds__(256) void prep_tr(const float* __restrict__ src, int K, int sel) {
    __shared__ float tile[32][33];
    int n0 = blockIdx.x * 32, k0 = blockIdx.y * 32;
    int tx = threadIdx.x & 31, ty = threadIdx.x >> 5;   // 32 x 8
#pragma unroll
    for (int r = 0; r < 4; r++)
        tile[ty + r * 8][tx] = src[(size_t)(k0 + ty + r * 8) * G4 + n0 + tx];
    __syncthreads();
    __nv_bfloat16* dh = sel ? g_wt_hi : g_wx_hi;
    __nv_bfloat16* dl = sel ? g_wt_lo : g_wx_lo;
#pragma unroll
    for (int r = 0; r < 4; r++) {
        int n = n0 + ty + r * 8;
        int np = (n & 1023) * 4 + (n >> 10);
        float v = tile[tx][ty + r * 8];
        __nv_bfloat16 hi = __float2bfloat16(v);
        dh[(size_t)np * K + k0 + tx] = hi;
        dl[(size_t)np * K + k0 + tx] = __float2bfloat16(v - __bfloat162float(hi));
    }
}

// ---------------- prep: gather emb rows, split to bf16 hi/lo [m][k] ----------------
__global__ void prep_emb(const int* __restrict__ X, const float* __restrict__ emb) {
    int m = blockIdx.x;                 // m = s*64+b
    int s = m >> 6, b = m & 63;
    int row = X[b * Sz + s];
    const float4* src = (const float4*)(emb + (size_t)row * Ez);
    int k4 = threadIdx.x;
    float4 v = src[k4];
    __nv_bfloat16 hx = __float2bfloat16(v.x), hy = __float2bfloat16(v.y);
    __nv_bfloat16 hz = __float2bfloat16(v.z), hw = __float2bfloat16(v.w);
    __nv_bfloat162* dh = (__nv_bfloat162*)(g_a_hi + (size_t)m * Ez);
    __nv_bfloat162* dl = (__nv_bfloat162*)(g_a_lo + (size_t)m * Ez);
    dh[k4 * 2]     = __nv_bfloat162(hx, hy);
    dh[k4 * 2 + 1] = __nv_bfloat162(hz, hw);
    dl[k4 * 2]     = __nv_bfloat162(__float2bfloat16(v.x - __bfloat162float(hx)),
                                    __float2bfloat16(v.y - __bfloat162float(hy)));
    dl[k4 * 2 + 1] = __nv_bfloat162(__float2bfloat16(v.z - __bfloat162float(hz)),
                                    __float2bfloat16(v.w - __bfloat162float(hw)));
}

__global__ void prep_bias(const float* __restrict__ bias) {
    int n = blockIdx.x * blockDim.x + threadIdx.x;
    if (n < G4) g_bias2[(n & 1023) * 4 + (n >> 10)] = bias[n];
}

// ---------------- xw GEMM building blocks (128 threads) ----------------
__device__ __forceinline__ void load_mat(uint32_t dst, const __nv_bfloat16* src,
                                         int stride_elems, int tid) {
#pragma unroll
    for (int i = 0; i < 8; i++) {
        int idx = i * 128 + tid;
        int row = idx >> 4, seg = idx & 15;
        CP16(dst + row * ROWB + seg * 16,
             (const char*)(src + (size_t)row * stride_elems) + seg * 16);
    }
}

__device__ __forceinline__ void compute_chunk(uint32_t buf, int lane, int mbase, int nbase,
                                              float acc[2][4][4]) {
    const uint32_t aH = buf, aL = buf + MATB, bH = buf + 2 * MATB, bL = buf + 3 * MATB;
    const int g = lane >> 3;
    const int arow = (lane & 7) + ((g & 1) << 3);
    const int ahalf = (g >> 1) * 16;
    const int brow = lane & 7;
    const int bhalf = ((lane >> 3) & 1) * 16;
#pragma unroll
    for (int k16 = 0; k16 < 8; k16++) {
        const uint32_t kb = k16 * 32;
        uint32_t ah[2][4], al[2][4], bh[4][2], bl[4][2];
#pragma unroll
        for (int mt = 0; mt < 2; mt++) {
            uint32_t ao = (uint32_t)((mbase + mt * 16 + arow) * ROWB) + kb + ahalf;
            LDSM4(ah[mt], aH + ao);
            LDSM4(al[mt], aL + ao);
        }
#pragma unroll
        for (int nt = 0; nt < 4; nt++) {
            uint32_t bo = (uint32_t)((nbase + nt * 8 + brow) * ROWB) + kb + bhalf;
            LDSM2(bh[nt], bH + bo);
            LDSM2(bl[nt], bL + bo);
        }
#pragma unroll
        for (int mt = 0; mt < 2; mt++)
#pragma unroll
            for (int nt = 0; nt < 4; nt++) {
                MMA(acc[mt][nt], ah[mt], bh[nt]);
                MMA(acc[mt][nt], ah[mt], bl[nt]);
                MMA(acc[mt][nt], al[mt], bh[nt]);
            }
    }
}

__device__ __forceinline__ void store_frags_to_Gs(float* Gs, int lane, int mbase, int nbase,
                                                  float acc[2][4][4]) {
    const int r = lane >> 2, c2 = (lane & 3) * 2;
#pragma unroll
    for (int mt = 0; mt < 2; mt++)
#pragma unroll
        for (int nt = 0; nt < 4; nt++) {
            int m = mbase + mt * 16 + r;
            int n = nbase + nt * 8 + c2;
            Gs[n * 68 + m]           = acc[mt][nt][0];
            Gs[(n + 1) * 68 + m]     = acc[mt][nt][1];
            Gs[n * 68 + m + 8]       = acc[mt][nt][2];
            Gs[(n + 1) * 68 + m + 8] = acc[mt][nt][3];
        }
}

// ---------------- xw GEMM: g_xw2[s][n'][b] = emb_m @ Wx^T + bias (bf16x3) ----------------
__global__ __launch_bounds__(128, 1) void xw_mma() {
    extern __shared__ char smem[];
    const uint32_t sb = smem_u32(smem);
    const int tid = threadIdx.x, lane = tid & 31, w = tid >> 5;
    const int np0 = blockIdx.x * 64;
    const int s = blockIdx.y;
    const __nv_bfloat16* Ah = g_a_hi + (size_t)s * Bz * Ez;
    const __nv_bfloat16* Al = g_a_lo + (size_t)s * Bz * Ez;
    const __nv_bfloat16* Bh = g_wx_hi + (size_t)np0 * Ez;
    const __nv_bfloat16* Bl = g_wx_lo + (size_t)np0 * Ez;

    float acc[2][4][4] = {};
    const int mbase = (w & 1) * 32, nbase = (w >> 1) * 32;

    load_mat(sb, Ah, Ez, tid);
    load_mat(sb + MATB, Al, Ez, tid);
    load_mat(sb + 2 * MATB, Bh, Ez, tid);
    load_mat(sb + 3 * MATB, Bl, Ez, tid);
    CP_COMMIT();

    for (int c = 0; c < 4; c++) {
        if (c < 3) {
            int kc = (c + 1) * 128;
            uint32_t buf = sb + ((c + 1) & 1) * BUFB;
            load_mat(buf, Ah + kc, Ez, tid);
            load_mat(buf + MATB, Al + kc, Ez, tid);
            load_mat(buf + 2 * MATB, Bh + kc, Ez, tid);
            load_mat(buf + 3 * MATB, Bl + kc, Ez, tid);
            CP_COMMIT();
            CP_WAITN(1);
        } else {
            CP_WAITN(0);
        }
        __syncthreads();
        compute_chunk(sb + (c & 1) * BUFB, lane, mbase, nbase, acc);
        __syncthreads();
    }

    float* Gs = (float*)smem;   // [64][68]
    store_frags_to_Gs(Gs, lane, mbase, nbase, acc);
    __syncthreads();

    float* outb = g_xw2 + ((size_t)s * G4 + np0) * Bz;
#pragma unroll
    for (int i = 0; i < 32; i++) {
        int e = i * 128 + tid;               // e = n'local*64 + b
        int nl = e >> 6, b = e & 63;
        outb[e] = Gs[nl * 68 + b] + g_bias2[np0 + nl];
    }
}

// ---------------- persistent LSTM recurrence ----------------
// 128 CTAs x 256 threads. CTA owns 32 n' (8 h-cols). W smem-resident.
// Sync: per-chunk dataflow flags (g_kflag[c] += 16 per step by chunk-c producers).
__device__ __forceinline__ void wait_flag(int c, int target) {
    int f;
    do {
        asm volatile("ld.acquire.gpu.global.s32 %0, [%1];"
                     : "=r"(f) : "l"(&g_kflag[c]));
    } while (f < target);
}

// load one 64x128 bf16 A tile (256 threads, 4 CP16 each)
__device__ __forceinline__ void load_A(uint32_t dst, const __nv_bfloat16* src, int tid) {
#pragma unroll
    for (int i = 0; i < 4; i++) {
        int idx = i * 256 + tid;
        int row = idx >> 4, seg = idx & 15;
        CP16(dst + row * ROWB + seg * 16,
             (const char*)(src + (size_t)row * Hz) + seg * 16);
    }
}

__global__ __launch_bounds__(256, 1) void steps_persistent(const int* __restrict__ seqlen) {
    extern __shared__ char smem[];
    const uint32_t sb = smem_u32(smem);
    const int tid = threadIdx.x, lane = tid & 31, w = tid >> 5;
    const int blk = blockIdx.x;
    const int np0 = blk * 32, c0 = blk * 8;
    const int mbase = (w & 3) * 16;      // batch rows
    const int nbase = (w >> 2) * 16;     // n' cols
    const int sl_b = __ldg(seqlen + (tid & 63));
    const int my_flag = blk >> 4;        // this CTA produces h inside chunk my_flag

    // ---- load W resident: 32 rows x 1024 k, hi+lo ----
#pragma unroll
    for (int i = 0; i < 16; i++) {
        int idx = i * 256 + tid;
        int row = idx >> 7, seg = idx & 127;
        CP16(sb + W_HI + row * WROWB + seg * 16,
             (const char*)(g_wt_hi + (size_t)(np0 + row) * Hz) + seg * 16);
    }
#pragma unroll
    for (int i = 0; i < 16; i++) {
        int idx = i * 256 + tid;
        int row = idx >> 7, seg = idx & 127;
        CP16(sb + W_LO + row * WROWB + seg * 16,
             (const char*)(g_wt_lo + (size_t)(np0 + row) * Hz) + seg * 16);
    }
    CP_COMMIT();

    float* Gs = (float*)(smem + GS_OFF);                     // [32 n'][68]
    __nv_bfloat16* HsH = (__nv_bfloat16*)(smem + HS_OFF);    // [64][8]
    __nv_bfloat16* HsL = (__nv_bfloat16*)(smem + HS_OFF + 1024);

    for (int t = 0; t < Sz; t++) {
        const __nv_bfloat16* h_hi = g_h_hi[t & 1];
        const __nv_bfloat16* h_lo = g_h_lo[t & 1];
        __nv_bfloat16* o_hi = g_h_hi[(t + 1) & 1];
        __nv_bfloat16* o_lo = g_h_lo[(t + 1) & 1];
        const int tgt = 16 * t;                              // flag target for h(t)

        // epilogue operand prefetch (xw static, c CTA-local) — independent of flags
        const float* xwb = g_xw2 + ((size_t)t * G4 + np0) * Bz;
        float xg[2][4], cold[2];
        {
            const int b = tid & 63;
#pragma unroll
            for (int i = 0; i < 2; i++) {
                int col = (i * 256 + tid) >> 6;
#pragma unroll
                for (int g = 0; g < 4; g++)
                    xg[i][g] = __ldg(xwb + (col * 4 + g) * Bz + b);
                cold[i] = g_c[(c0 + col) * Bz + b];
            }
        }

        // chunk 0: wait for its 16 producers, then load
        wait_flag(0, tgt);
        load_A(sb + ASTG, h_hi, tid);
        load_A(sb + ASTG + MATB, h_lo, tid);
        CP_COMMIT();

        float acc[2][4] = {};                                // [nt][4], warp tile 16x16
#pragma unroll
        for (int c = 0; c < 8; c++) {
            if (c < 7) {
                wait_flag(c + 1, tgt);
                uint32_t buf = sb + ASTG + (uint32_t)((c + 1) & 1) * ASTGB;
                load_A(buf, h_hi + (c + 1) * 128, tid);
                load_A(buf + MATB, h_lo + (c + 1) * 128, tid);
                CP_COMMIT();
                CP_WAITN(1);
            } else {
                CP_WAITN(0);
            }
            __syncthreads();

            // compute chunk c from stage (c&1) + resident W
            {
                const uint32_t abuf = sb + ASTG + (uint32_t)(c & 1) * ASTGB;
                const int arow = mbase + (lane & 15);
                const int ahalf = (lane >> 4) * 16;
                const int brow = lane & 7;
                const int bhalf = ((lane >> 3) & 1) * 16;
                const uint32_t kwb = (uint32_t)c * 256;      // W k-offset bytes
#pragma unroll
                for (int k16 = 0; k16 < 8; k16++) {
                    uint32_t ah[4], al[4], bh[2][2], bl[2][2];
                    uint32_t ao = (uint32_t)(arow * ROWB) + k16 * 32 + ahalf;
                    LDSM4(ah, abuf + ao);
                    LDSM4(al, abuf + MATB + ao);
#pragma unroll
                    for (int nt = 0; nt < 2; nt++) {
                        uint32_t bo = (uint32_t)((nbase + nt * 8 + brow) * WROWB)
                                      + kwb + k16 * 32 + bhalf;
                        LDSM2(bh[nt], sb + W_HI + bo);
                        LDSM2(bl[nt], sb + W_LO + bo);
                    }
#pragma unroll
                    for (int nt = 0; nt < 2; nt++) {
                        MMA(acc[nt], ah, bh[nt]);
                        MMA(acc[nt], ah, bl[nt]);
                        MMA(acc[nt], al, bh[nt]);
                    }
                }
            }
            __syncthreads();
        }

        // stage gate tile to smem
        {
            const int r = lane >> 2, c2 = (lane & 3) * 2;
#pragma unroll
            for (int nt = 0; nt < 2; nt++) {
                int m = mbase + r;
                int n = nbase + nt * 8 + c2;
                Gs[n * 68 + m]           = acc[nt][0];
                Gs[(n + 1) * 68 + m]     = acc[nt][1];
                Gs[n * 68 + m + 8]       = acc[nt][2];
                Gs[(n + 1) * 68 + m + 8] = acc[nt][3];
            }
        }
        __syncthreads();

        // pointwise LSTM for 8 cols x 64 batch
        const bool is_last = (t == sl_b - 1);
#pragma unroll
        for (int i = 0; i < 2; i++) {
            int e = i * 256 + tid;
            int col = e >> 6, b = e & 63;
            float ig = Gs[(col * 4 + 0) * 68 + b] + xg[i][0];
            float jg = Gs[(col * 4 + 1) * 68 + b] + xg[i][1];
            float fg = Gs[(col * 4 + 2) * 68 + b] + xg[i][2];
            float og = Gs[(col * 4 + 3) * 68 + b] + xg[i][3];
            float cn = cold[i] * sigm(fg + 1.0f) + sigm(ig) * tanh_f(jg);
            float hn = tanh_f(cn) * sigm(og);
            g_c[(c0 + col) * Bz + b] = cn;
            __nv_bfloat16 hi = __float2bfloat16(hn);
            HsH[b * 8 + col] = hi;
            HsL[b * 8 + col] = __float2bfloat16(hn - __bfloat162float(hi));
            if (is_last) g_final[(size_t)b * Hz + c0 + col] = hn;
        }
        __syncthreads();

        // coalesced 16B h writes, then fence + publish
        if (tid < 64) {
            *(uint4*)(o_hi + (size_t)tid * Hz + c0) = *(uint4*)(HsH + tid * 8);
        } else if (tid < 128) {
            int b = tid - 64;
            *(uint4*)(o_lo + (size_t)b * Hz + c0) = *(uint4*)(HsL + b * 8);
        }
        asm volatile("membar.gl;" ::: "memory");
        __syncthreads();
        if (tid == 0) {
            asm volatile("red.add.release.gpu.global.s32 [%0], 1;"
                         :: "l"(&g_kflag[my_flag]) : "memory");
        }
    }
}

// ---------------- dense = relu(final @ dense_w + dense_b) ----------------
__global__ void dense_kernel(const float* __restrict__ dw, const float* __restrict__ db) {
    int b = blockIdx.x;
    int d = threadIdx.x;    // 512 threads
    const float* f = g_final + (size_t)b * Hz;
    float s0 = 0.f, s1 = 0.f, s2 = 0.f, s3 = 0.f;
#pragma unroll 4
    for (int k = 0; k < Hz; k += 4) {
        s0 += f[k]     * dw[(size_t)(k)     * Dz + d];
        s1 += f[k + 1] * dw[(size_t)(k + 1) * Dz + d];
        s2 += f[k + 2] * dw[(size_t)(k + 2) * Dz + d];
        s3 += f[k + 3] * dw[(size_t)(k + 3) * Dz + d];
    }
    float s = (s0 + s1) + (s2 + s3) + db[d];
    g_dense[(size_t)b * Dz + d] = fmaxf(s, 0.f);
}

// ---------------- logits = dense @ pred_w + pred_b ----------------
__global__ void logits_kernel(const float* __restrict__ pw, const float* __restrict__ pb,
                              float* __restrict__ out) {
    int tid = threadIdx.x;
    if (tid >= Bz * Cz) return;
    int b = tid >> 1;
    int cc = tid & 1;
    const float* dn = g_dense + (size_t)b * Dz;
    float s = 0.f;
#pragma unroll 4
    for (int d = 0; d < Dz; d++) s += dn[d] * pw[(size_t)d * Cz + cc];
    out[b * Cz + cc] = s + pb[cc];
}

// ---------------- launch ----------------
extern "C" void kernel_launch(void* const* d_in, const int* in_sizes, int n_in,
                              void* d_out, int out_size) {
    const int*   X      = (const int*)d_in[0];
    const int*   seqlen = (const int*)d_in[1];
    const float* emb    = (const float*)d_in[2];
    const float* Wf     = (const float*)d_in[3];   // [1536, 4096]
    const float* bias   = (const float*)d_in[4];
    const float* dw     = (const float*)d_in[5];
    const float* db     = (const float*)d_in[6];
    const float* pw     = (const float*)d_in[7];
    const float* pb     = (const float*)d_in[8];
    float* out = (float*)d_out;

    cudaFuncSetAttribute(xw_mma, cudaFuncAttributeMaxDynamicSharedMemorySize, SMEM_XW);
    cudaFuncSetAttribute(steps_persistent, cudaFuncAttributeMaxDynamicSharedMemorySize, SMEM_ST);

    init_kernel<<<(Bz * Hz + 255) / 256, 256>>>();
    prep_tr<<<dim3(G4 / 32, Ez / 32), 256>>>(Wf, Ez, 0);                   // Wx
    prep_tr<<<dim3(G4 / 32, Hz / 32), 256>>>(Wf + (size_t)Ez * G4, Hz, 1); // Wh
    prep_emb<<<Sz * Bz, 128>>>(X, emb);
    prep_bias<<<G4 / 256, 256>>>(bias);

    xw_mma<<<dim3(G4 / 64, Sz), 128, SMEM_XW>>>();

    steps_persistent<<<128, 256, SMEM_ST>>>(seqlen);

    dense_kernel<<<Bz, Dz>>>(dw, db);
    logits_kernel<<<1, 128>>>(pw, pb, out);
}

// round 8
// speedup vs baseline: 1.2342x; 1.0881x over previous
#include <cuda_runtime.h>
#include <cuda_bf16.h>
#include <stdint.h>

#define Bz 64
#define Sz 256
#define Ez 512
#define Hz 1024
#define G4 4096   // 4*Hz
#define Dz 512
#define Cz 2

// ---------------- device scratch (no cudaMalloc allowed) ----------------
__device__ __align__(128) float g_xw2[(size_t)Sz * G4 * Bz];        // [s][n'][b]
__device__ __align__(128) __nv_bfloat16 g_wt_hi[(size_t)G4 * Hz];   // Wh^T [n'][k]
__device__ __align__(128) __nv_bfloat16 g_wt_lo[(size_t)G4 * Hz];
__device__ __align__(128) __nv_bfloat16 g_wx_hi[(size_t)G4 * Ez];   // Wx^T [n'][k]
__device__ __align__(128) __nv_bfloat16 g_wx_lo[(size_t)G4 * Ez];
__device__ __align__(128) __nv_bfloat16 g_a_hi[(size_t)Sz * Bz * Ez]; // gathered emb [m][k]
__device__ __align__(128) __nv_bfloat16 g_a_lo[(size_t)Sz * Bz * Ez];
__device__ __align__(128) __nv_bfloat16 g_h_hi[2][(size_t)Bz * Hz];  // h [b][k] ping-pong
__device__ __align__(128) __nv_bfloat16 g_h_lo[2][(size_t)Bz * Hz];
__device__ __align__(128) float g_bias2[G4];                         // permuted bias
__device__ __align__(128) float g_c[Hz * Bz];                        // cell [c][b]
__device__ __align__(128) float g_final[(size_t)Bz * Hz];            // [b][h]
__device__ __align__(128) float g_dense[Bz * Dz];
__device__ __align__(128) int g_leaf[8];                             // tree barrier leaves
__device__ int g_root;                                               // tree barrier root
__device__ int g_flag;                                               // release flag

// ================= PTX helpers (non-'a' features only) =================
__device__ __forceinline__ uint32_t smem_u32(const void* p) {
    uint32_t a;
    asm("{ .reg .u64 t; cvta.to.shared.u64 t, %1; cvt.u32.u64 %0, t; }" : "=r"(a) : "l"(p));
    return a;
}
#define CP16(dst, src) \
    asm volatile("cp.async.cg.shared.global [%0], [%1], 16;" :: "r"((uint32_t)(dst)), "l"(src))
#define CP_COMMIT() asm volatile("cp.async.commit_group;" ::: "memory")
#define CP_WAITN(n) asm volatile("cp.async.wait_group %0;" :: "n"(n) : "memory")

#define LDSM4(r, addr) \
    asm volatile("ldmatrix.sync.aligned.m8n8.x4.shared.b16 {%0,%1,%2,%3}, [%4];" \
        : "=r"((r)[0]), "=r"((r)[1]), "=r"((r)[2]), "=r"((r)[3]) : "r"(addr))
#define LDSM2(r, addr) \
    asm volatile("ldmatrix.sync.aligned.m8n8.x2.shared.b16 {%0,%1}, [%2];" \
        : "=r"((r)[0]), "=r"((r)[1]) : "r"(addr))
#define MMA(d, a, b) \
    asm volatile("mma.sync.aligned.m16n8k16.row.col.f32.bf16.bf16.f32 " \
        "{%0,%1,%2,%3},{%4,%5,%6,%7},{%8,%9},{%0,%1,%2,%3};" \
        : "+f"((d)[0]), "+f"((d)[1]), "+f"((d)[2]), "+f"((d)[3]) \
        : "r"((a)[0]), "r"((a)[1]), "r"((a)[2]), "r"((a)[3]), "r"((b)[0]), "r"((b)[1]))

__device__ __forceinline__ float sigm(float x) { return 1.f / (1.f + __expf(-x)); }
__device__ __forceinline__ float tanh_f(float x) { return 1.f - 2.f / (__expf(2.f * x) + 1.f); }

// ---------------- geometry ----------------
// xw kernel (128 threads, 2-stage, 64x64 tiles)
#define ROWB 272
#define MATB (64 * ROWB)      // 17408
#define BUFB (4 * MATB)       // 69632 (Ah, Al, Bh, Bl)
#define SMEM_XW (2 * BUFB)    // 139264

// persistent step kernel (256 threads): W resident + 2-stage A; Gs aliases stage 0
#define WROWB 2064                       // 1024 bf16 + 16B pad
#define WMATB (32 * WROWB)               // 66048
#define W_HI 0
#define W_LO WMATB                       // 66048
#define ASTG (2 * WMATB)                 // 132096
#define ASTGB (2 * MATB)                 // 34816 per stage (hi+lo)
#define GS_OFF ASTG                      // Gs [4][32][68] f32 = 34816 — aliases stage 0
#define HS_OFF (ASTG + 2 * ASTGB)        // 201728 ; Hs hi/lo = 2048
#define SMEM_ST (HS_OFF + 2048)          // 203776

// ---------------- init: zero h and c, reset barrier ----------------
__global__ void init_kernel() {
    int i = blockIdx.x * blockDim.x + threadIdx.x;
    if (i == 0) { g_root = 0; g_flag = 0; }
    if (i < 8) g_leaf[i] = 0;
    if (i < Bz * Hz) {
        __nv_bfloat16 z = __float2bfloat16(0.f);
        g_h_hi[0][i] = z; g_h_hi[1][i] = z;
        g_h_lo[0][i] = z; g_h_lo[1][i] = z;
        g_c[i] = 0.f;
    }
}

// ---------------- prep: transpose+split W -> [n'=c*4+g][k] bf16 hi/lo ----------------
__global__ __launch_bounds__(256) void prep_tr(const float* __restrict__ src, int K, int sel) {
    __shared__ float tile[32][33];
    int n0 = blockIdx.x * 32, k0 = blockIdx.y * 32;
    int tx = threadIdx.x & 31, ty = threadIdx.x >> 5;   // 32 x 8
#pragma unroll
    for (int r = 0; r < 4; r++)
        tile[ty + r * 8][tx] = src[(size_t)(k0 + ty + r * 8) * G4 + n0 + tx];
    __syncthreads();
    __nv_bfloat16* dh = sel ? g_wt_hi : g_wx_hi;
    __nv_bfloat16* dl = sel ? g_wt_lo : g_wx_lo;
#pragma unroll
    for (int r = 0; r < 4; r++) {
        int n = n0 + ty + r * 8;
        int np = (n & 1023) * 4 + (n >> 10);
        float v = tile[tx][ty + r * 8];
        __nv_bfloat16 hi = __float2bfloat16(v);
        dh[(size_t)np * K + k0 + tx] = hi;
        dl[(size_t)np * K + k0 + tx] = __float2bfloat16(v - __bfloat162float(hi));
    }
}

// ---------------- prep: gather emb rows, split to bf16 hi/lo [m][k] ----------------
__global__ void prep_emb(const int* __restrict__ X, const float* __restrict__ emb) {
    int m = blockIdx.x;                 // m = s*64+b
    int s = m >> 6, b = m & 63;
    int row = X[b * Sz + s];
    const float4* src = (const float4*)(emb + (size_t)row * Ez);
    int k4 = threadIdx.x;
    float4 v = src[k4];
    __nv_bfloat16 hx = __float2bfloat16(v.x), hy = __float2bfloat16(v.y);
    __nv_bfloat16 hz = __float2bfloat16(v.z), hw = __float2bfloat16(v.w);
    __nv_bfloat162* dh = (__nv_bfloat162*)(g_a_hi + (size_t)m * Ez);
    __nv_bfloat162* dl = (__nv_bfloat162*)(g_a_lo + (size_t)m * Ez);
    dh[k4 * 2]     = __nv_bfloat162(hx, hy);
    dh[k4 * 2 + 1] = __nv_bfloat162(hz, hw);
    dl[k4 * 2]     = __nv_bfloat162(__float2bfloat16(v.x - __bfloat162float(hx)),
                                    __float2bfloat16(v.y - __bfloat162float(hy)));
    dl[k4 * 2 + 1] = __nv_bfloat162(__float2bfloat16(v.z - __bfloat162float(hz)),
                                    __float2bfloat16(v.w - __bfloat162float(hw)));
}

__global__ void prep_bias(const float* __restrict__ bias) {
    int n = blockIdx.x * blockDim.x + threadIdx.x;
    if (n < G4) g_bias2[(n & 1023) * 4 + (n >> 10)] = bias[n];
}

// ---------------- xw GEMM building blocks (128 threads) ----------------
__device__ __forceinline__ void load_mat(uint32_t dst, const __nv_bfloat16* src,
                                         int stride_elems, int tid) {
#pragma unroll
    for (int i = 0; i < 8; i++) {
        int idx = i * 128 + tid;
        int row = idx >> 4, seg = idx & 15;
        CP16(dst + row * ROWB + seg * 16,
             (const char*)(src + (size_t)row * stride_elems) + seg * 16);
    }
}

__device__ __forceinline__ void compute_chunk(uint32_t buf, int lane, int mbase, int nbase,
                                              float acc[2][4][4]) {
    const uint32_t aH = buf, aL = buf + MATB, bH = buf + 2 * MATB, bL = buf + 3 * MATB;
    const int g = lane >> 3;
    const int arow = (lane & 7) + ((g & 1) << 3);
    const int ahalf = (g >> 1) * 16;
    const int brow = lane & 7;
    const int bhalf = ((lane >> 3) & 1) * 16;
#pragma unroll
    for (int k16 = 0; k16 < 8; k16++) {
        const uint32_t kb = k16 * 32;
        uint32_t ah[2][4], al[2][4], bh[4][2], bl[4][2];
#pragma unroll
        for (int mt = 0; mt < 2; mt++) {
            uint32_t ao = (uint32_t)((mbase + mt * 16 + arow) * ROWB) + kb + ahalf;
            LDSM4(ah[mt], aH + ao);
            LDSM4(al[mt], aL + ao);
        }
#pragma unroll
        for (int nt = 0; nt < 4; nt++) {
            uint32_t bo = (uint32_t)((nbase + nt * 8 + brow) * ROWB) + kb + bhalf;
            LDSM2(bh[nt], bH + bo);
            LDSM2(bl[nt], bL + bo);
        }
#pragma unroll
        for (int mt = 0; mt < 2; mt++)
#pragma unroll
            for (int nt = 0; nt < 4; nt++) {
                MMA(acc[mt][nt], ah[mt], bh[nt]);
                MMA(acc[mt][nt], ah[mt], bl[nt]);
                MMA(acc[mt][nt], al[mt], bh[nt]);
            }
    }
}

__device__ __forceinline__ void store_frags_to_Gs(float* Gs, int lane, int mbase, int nbase,
                                                  float acc[2][4][4]) {
    const int r = lane >> 2, c2 = (lane & 3) * 2;
#pragma unroll
    for (int mt = 0; mt < 2; mt++)
#pragma unroll
        for (int nt = 0; nt < 4; nt++) {
            int m = mbase + mt * 16 + r;
            int n = nbase + nt * 8 + c2;
            Gs[n * 68 + m]           = acc[mt][nt][0];
            Gs[(n + 1) * 68 + m]     = acc[mt][nt][1];
            Gs[n * 68 + m + 8]       = acc[mt][nt][2];
            Gs[(n + 1) * 68 + m + 8] = acc[mt][nt][3];
        }
}

// ---------------- xw GEMM: g_xw2[s][n'][b] = emb_m @ Wx^T + bias (bf16x3) ----------------
__global__ __launch_bounds__(128, 1) void xw_mma() {
    extern __shared__ char smem[];
    const uint32_t sb = smem_u32(smem);
    const int tid = threadIdx.x, lane = tid & 31, w = tid >> 5;
    const int np0 = blockIdx.x * 64;
    const int s = blockIdx.y;
    const __nv_bfloat16* Ah = g_a_hi + (size_t)s * Bz * Ez;
    const __nv_bfloat16* Al = g_a_lo + (size_t)s * Bz * Ez;
    const __nv_bfloat16* Bh = g_wx_hi + (size_t)np0 * Ez;
    const __nv_bfloat16* Bl = g_wx_lo + (size_t)np0 * Ez;

    float acc[2][4][4] = {};
    const int mbase = (w & 1) * 32, nbase = (w >> 1) * 32;

    load_mat(sb, Ah, Ez, tid);
    load_mat(sb + MATB, Al, Ez, tid);
    load_mat(sb + 2 * MATB, Bh, Ez, tid);
    load_mat(sb + 3 * MATB, Bl, Ez, tid);
    CP_COMMIT();

    for (int c = 0; c < 4; c++) {
        if (c < 3) {
            int kc = (c + 1) * 128;
            uint32_t buf = sb + ((c + 1) & 1) * BUFB;
            load_mat(buf, Ah + kc, Ez, tid);
            load_mat(buf + MATB, Al + kc, Ez, tid);
            load_mat(buf + 2 * MATB, Bh + kc, Ez, tid);
            load_mat(buf + 3 * MATB, Bl + kc, Ez, tid);
            CP_COMMIT();
            CP_WAITN(1);
        } else {
            CP_WAITN(0);
        }
        __syncthreads();
        compute_chunk(sb + (c & 1) * BUFB, lane, mbase, nbase, acc);
        __syncthreads();
    }

    float* Gs = (float*)smem;   // [64][68]
    store_frags_to_Gs(Gs, lane, mbase, nbase, acc);
    __syncthreads();

    float* outb = g_xw2 + ((size_t)s * G4 + np0) * Bz;
#pragma unroll
    for (int i = 0; i < 32; i++) {
        int e = i * 128 + tid;               // e = n'local*64 + b
        int nl = e >> 6, b = e & 63;
        outb[e] = Gs[nl * 68 + b] + g_bias2[np0 + nl];
    }
}

// ---------------- persistent LSTM recurrence ----------------
// 128 CTAs x 256 threads. CTA owns 32 n' (8 h-cols). W smem-resident.
// Warps: mh = w&1 (32 batch rows), ksub = w>>1 (K quarter). Warp tile 32m x 32n'.
// Partials per K quarter go to private Gs strips; epilogue sums 4 strips.
__device__ __forceinline__ void gbar_tree(int t, int tid, int blk) {
    __syncthreads();
    if (tid == 0) {
        int grp = blk >> 4;
        int old;
        asm volatile("atom.add.acq_rel.gpu.global.s32 %0, [%1], 1;"
                     : "=r"(old) : "l"(&g_leaf[grp]) : "memory");
        if (old == 16 * t - 1) {
            int rold;
            asm volatile("atom.add.acq_rel.gpu.global.s32 %0, [%1], 1;"
                         : "=r"(rold) : "l"(&g_root) : "memory");
            if (rold == 8 * t - 1) {
                asm volatile("st.release.gpu.global.s32 [%0], %1;"
                             :: "l"(&g_flag), "r"(t) : "memory");
            }
        }
        int f;
        do {
            asm volatile("ld.acquire.gpu.global.s32 %0, [%1];" : "=r"(f) : "l"(&g_flag));
        } while (f < t);
    }
    __syncthreads();
}

// load one 64x128 bf16 A tile (256 threads, 4 CP16 each)
__device__ __forceinline__ void load_A(uint32_t dst, const __nv_bfloat16* src, int tid) {
#pragma unroll
    for (int i = 0; i < 4; i++) {
        int idx = i * 256 + tid;
        int row = idx >> 4, seg = idx & 15;
        CP16(dst + row * ROWB + seg * 16,
             (const char*)(src + (size_t)row * Hz) + seg * 16);
    }
}

__global__ __launch_bounds__(256, 1) void steps_persistent(const int* __restrict__ seqlen) {
    extern __shared__ char smem[];
    const uint32_t sb = smem_u32(smem);
    const int tid = threadIdx.x, lane = tid & 31, w = tid >> 5;
    const int blk = blockIdx.x;
    const int np0 = blk * 32, c0 = blk * 8;
    const int mh = w & 1;                // batch half (32 rows)
    const int ksub = w >> 1;             // K quarter (256 k)
    const int sl_b = __ldg(seqlen + (tid & 63));

    // ---- load W resident: 32 rows x 1024 k, hi+lo ----
#pragma unroll
    for (int i = 0; i < 16; i++) {
        int idx = i * 256 + tid;
        int row = idx >> 7, seg = idx & 127;
        CP16(sb + W_HI + row * WROWB + seg * 16,
             (const char*)(g_wt_hi + (size_t)(np0 + row) * Hz) + seg * 16);
    }
#pragma unroll
    for (int i = 0; i < 16; i++) {
        int idx = i * 256 + tid;
        int row = idx >> 7, seg = idx & 127;
        CP16(sb + W_LO + row * WROWB + seg * 16,
             (const char*)(g_wt_lo + (size_t)(np0 + row) * Hz) + seg * 16);
    }
    CP_COMMIT();

    float* Gs = (float*)(smem + GS_OFF);                     // [4 ksub][32 n'][68 m]
    __nv_bfloat16* HsH = (__nv_bfloat16*)(smem + HS_OFF);    // [64][8]
    __nv_bfloat16* HsL = (__nv_bfloat16*)(smem + HS_OFF + 1024);

    for (int t = 0; t < Sz; t++) {
        const __nv_bfloat16* h_hi = g_h_hi[t & 1];
        const __nv_bfloat16* h_lo = g_h_lo[t & 1];
        __nv_bfloat16* o_hi = g_h_hi[(t + 1) & 1];
        __nv_bfloat16* o_lo = g_h_lo[(t + 1) & 1];

        // epilogue operand prefetch (xw static, c CTA-local) — before barrier
        const float* xwb = g_xw2 + ((size_t)t * G4 + np0) * Bz;
        float xg[2][4], cold[2];
        {
            const int b = tid & 63;
#pragma unroll
            for (int i = 0; i < 2; i++) {
                int col = (i * 256 + tid) >> 6;
#pragma unroll
                for (int g = 0; g < 4; g++)
                    xg[i][g] = __ldg(xwb + (col * 4 + g) * Bz + b);
                cold[i] = g_c[(c0 + col) * Bz + b];
            }
        }

        if (t > 0) gbar_tree(t, tid, blk);                   // all CTAs finished t-1

        load_A(sb + ASTG, h_hi, tid);
        load_A(sb + ASTG + MATB, h_lo, tid);
        CP_COMMIT();

        float acc[2][4][4] = {};                             // [mt][nt][4], tile 32x32
#pragma unroll
        for (int c = 0; c < 8; c++) {
            if (c < 7) {
                uint32_t buf = sb + ASTG + (uint32_t)((c + 1) & 1) * ASTGB;
                load_A(buf, h_hi + (c + 1) * 128, tid);
                load_A(buf + MATB, h_lo + (c + 1) * 128, tid);
                CP_COMMIT();
                CP_WAITN(1);
            } else {
                CP_WAITN(0);
            }
            __syncthreads();

            // compute: this warp covers k16 = {2*ksub, 2*ksub+1} of chunk c
            {
                const uint32_t abuf = sb + ASTG + (uint32_t)(c & 1) * ASTGB;
                const int arow = lane & 15;
                const int ahalf = (lane >> 4) * 16;
                const int brow = lane & 7;
                const int bhalf = ((lane >> 3) & 1) * 16;
#pragma unroll
                for (int kk = 0; kk < 2; kk++) {
                    const int k16 = ksub * 2 + kk;           // within chunk
                    uint32_t ah[2][4], al[2][4], bh[4][2], bl[4][2];
#pragma unroll
                    for (int mt = 0; mt < 2; mt++) {
                        uint32_t ao = (uint32_t)((mh * 32 + mt * 16 + arow) * ROWB)
                                      + k16 * 32 + ahalf;
                        LDSM4(ah[mt], abuf + ao);
                        LDSM4(al[mt], abuf + MATB + ao);
                    }
                    const uint32_t kwb = (uint32_t)(c * 128 + k16 * 16) * 2 + bhalf;
#pragma unroll
                    for (int nt = 0; nt < 4; nt++) {
                        uint32_t bo = (uint32_t)((nt * 8 + brow) * WROWB) + kwb;
                        LDSM2(bh[nt], sb + W_HI + bo);
                        LDSM2(bl[nt], sb + W_LO + bo);
                    }
#pragma unroll
                    for (int mt = 0; mt < 2; mt++)
#pragma unroll
                        for (int nt = 0; nt < 4; nt++) {
                            MMA(acc[mt][nt], ah[mt], bh[nt]);
                            MMA(acc[mt][nt], ah[mt], bl[nt]);
                            MMA(acc[mt][nt], al[mt], bh[nt]);
                        }
                }
            }
            __syncthreads();
        }

        // write partials to private strip (Gs aliases stage-0 buffer, dead now)
        {
            float* strip = Gs + ksub * (32 * 68);
            const int r = lane >> 2, c2 = (lane & 3) * 2;
#pragma unroll
            for (int mt = 0; mt < 2; mt++)
#pragma unroll
                for (int nt = 0; nt < 4; nt++) {
                    int m = mh * 32 + mt * 16 + r;
                    int n = nt * 8 + c2;
                    strip[n * 68 + m]           = acc[mt][nt][0];
                    strip[(n + 1) * 68 + m]     = acc[mt][nt][1];
                    strip[n * 68 + m + 8]       = acc[mt][nt][2];
                    strip[(n + 1) * 68 + m + 8] = acc[mt][nt][3];
                }
        }
        __syncthreads();

        // pointwise LSTM: sum 4 K-quarter strips + xw, 8 cols x 64 batch
        const bool is_last = (t == sl_b - 1);
#pragma unroll
        for (int i = 0; i < 2; i++) {
            int e = i * 256 + tid;
            int col = e >> 6, b = e & 63;
            float gg[4];
#pragma unroll
            for (int g = 0; g < 4; g++) {
                int off = (col * 4 + g) * 68 + b;
                gg[g] = (Gs[off] + Gs[off + 2176])
                      + (Gs[off + 2 * 2176] + Gs[off + 3 * 2176]) + xg[i][g];
            }
            float cn = cold[i] * sigm(gg[2] + 1.0f) + sigm(gg[0]) * tanh_f(gg[1]);
            float hn = tanh_f(cn) * sigm(gg[3]);
            g_c[(c0 + col) * Bz + b] = cn;
            __nv_bfloat16 hi = __float2bfloat16(hn);
            HsH[b * 8 + col] = hi;
            HsL[b * 8 + col] = __float2bfloat16(hn - __bfloat162float(hi));
            if (is_last) g_final[(size_t)b * Hz + c0 + col] = hn;
        }
        __syncthreads();

        // coalesced 16B h writes
        if (tid < 64) {
            *(uint4*)(o_hi + (size_t)tid * Hz + c0) = *(uint4*)(HsH + tid * 8);
        } else if (tid < 128) {
            int b = tid - 64;
            *(uint4*)(o_lo + (size_t)b * Hz + c0) = *(uint4*)(HsL + b * 8);
        }
    }
}

// ---------------- dense = relu(final @ dense_w + dense_b) ----------------
__global__ void dense_kernel(const float* __restrict__ dw, const float* __restrict__ db) {
    int b = blockIdx.x;
    int d = threadIdx.x;    // 512 threads
    const float* f = g_final + (size_t)b * Hz;
    float s0 = 0.f, s1 = 0.f, s2 = 0.f, s3 = 0.f;
#pragma unroll 4
    for (int k = 0; k < Hz; k += 4) {
        s0 += f[k]     * dw[(size_t)(k)     * Dz + d];
        s1 += f[k + 1] * dw[(size_t)(k + 1) * Dz + d];
        s2 += f[k + 2] * dw[(size_t)(k + 2) * Dz + d];
        s3 += f[k + 3] * dw[(size_t)(k + 3) * Dz + d];
    }
    float s = (s0 + s1) + (s2 + s3) + db[d];
    g_dense[(size_t)b * Dz + d] = fmaxf(s, 0.f);
}

// ---------------- logits = dense @ pred_w + pred_b ----------------
__global__ void logits_kernel(const float* __restrict__ pw, const float* __restrict__ pb,
                              float* __restrict__ out) {
    int tid = threadIdx.x;
    if (tid >= Bz * Cz) return;
    int b = tid >> 1;
    int cc = tid & 1;
    const float* dn = g_dense + (size_t)b * Dz;
    float s = 0.f;
#pragma unroll 4
    for (int d = 0; d < Dz; d++) s += dn[d] * pw[(size_t)d * Cz + cc];
    out[b * Cz + cc] = s + pb[cc];
}

// ---------------- launch ----------------
extern "C" void kernel_launch(void* const* d_in, const int* in_sizes, int n_in,
                              void* d_out, int out_size) {
    const int*   X      = (const int*)d_in[0];
    const int*   seqlen = (const int*)d_in[1];
    const float* emb    = (const float*)d_in[2];
    const float* Wf     = (const float*)d_in[3];   // [1536, 4096]
    const float* bias   = (const float*)d_in[4];
    const float* dw     = (const float*)d_in[5];
    const float* db     = (const float*)d_in[6];
    const float* pw     = (const float*)d_in[7];
    const float* pb     = (const float*)d_in[8];
    float* out = (float*)d_out;

    cudaFuncSetAttribute(xw_mma, cudaFuncAttributeMaxDynamicSharedMemorySize, SMEM_XW);
    cudaFuncSetAttribute(steps_persistent, cudaFuncAttributeMaxDynamicSharedMemorySize, SMEM_ST);

    init_kernel<<<(Bz * Hz + 255) / 256, 256>>>();
    prep_tr<<<dim3(G4 / 32, Ez / 32), 256>>>(Wf, Ez, 0);                   // Wx
    prep_tr<<<dim3(G4 / 32, Hz / 32), 256>>>(Wf + (size_t)Ez * G4, Hz, 1); // Wh
    prep_emb<<<Sz * Bz, 128>>>(X, emb);
    prep_bias<<<G4 / 256, 256>>>(bias);

    xw_mma<<<dim3(G4 / 64, Sz), 128, SMEM_XW>>>();

    steps_persistent<<<128, 256, SMEM_ST>>>(seqlen);

    dense_kernel<<<Bz, Dz>>>(dw, db);
    logits_kernel<<<1, 128>>>(pw, pb, out);
}

// round 9
// speedup vs baseline: 1.2710x; 1.0298x over previous
#include <cuda_runtime.h>
#include <cuda_bf16.h>
#include <stdint.h>

#define Bz 64
#define Sz 256
#define Ez 512
#define Hz 1024
#define G4 4096   // 4*Hz
#define Dz 512
#define Cz 2

// ---------------- device scratch (no cudaMalloc allowed) ----------------
__device__ __align__(128) float g_xw2[(size_t)Sz * G4 * Bz];        // [s][n'][b]
__device__ __align__(128) __nv_bfloat16 g_wt_hi[(size_t)G4 * Hz];   // Wh^T [n'][k]
__device__ __align__(128) __nv_bfloat16 g_wt_lo[(size_t)G4 * Hz];
__device__ __align__(128) __nv_bfloat16 g_wx_hi[(size_t)G4 * Ez];   // Wx^T [n'][k]
__device__ __align__(128) __nv_bfloat16 g_wx_lo[(size_t)G4 * Ez];
__device__ __align__(128) __nv_bfloat16 g_a_hi[(size_t)Sz * Bz * Ez]; // gathered emb [m][k]
__device__ __align__(128) __nv_bfloat16 g_a_lo[(size_t)Sz * Bz * Ez];
__device__ __align__(128) __nv_bfloat16 g_h_hi[2][(size_t)Bz * Hz];  // h [b][k] ping-pong
__device__ __align__(128) __nv_bfloat16 g_h_lo[2][(size_t)Bz * Hz];
__device__ __align__(128) float g_bias2[G4];                         // permuted bias
__device__ __align__(128) float g_c[Hz * Bz];                        // cell [c][b]
__device__ __align__(128) float g_final[(size_t)Bz * Hz];            // [b][h]
__device__ __align__(128) float g_dense[Bz * Dz];
__device__ __align__(128) int g_leaf[8];                             // tree barrier leaves
__device__ int g_root;                                               // tree barrier root
__device__ int g_flag;                                               // release flag

// ================= PTX helpers (non-'a' features only) =================
__device__ __forceinline__ uint32_t smem_u32(const void* p) {
    uint32_t a;
    asm("{ .reg .u64 t; cvta.to.shared.u64 t, %1; cvt.u32.u64 %0, t; }" : "=r"(a) : "l"(p));
    return a;
}
#define CP16(dst, src) \
    asm volatile("cp.async.cg.shared.global [%0], [%1], 16;" :: "r"((uint32_t)(dst)), "l"(src))
#define CP_COMMIT() asm volatile("cp.async.commit_group;" ::: "memory")
#define CP_WAITN(n) asm volatile("cp.async.wait_group %0;" :: "n"(n) : "memory")

#define LDSM4(r, addr) \
    asm volatile("ldmatrix.sync.aligned.m8n8.x4.shared.b16 {%0,%1,%2,%3}, [%4];" \
        : "=r"((r)[0]), "=r"((r)[1]), "=r"((r)[2]), "=r"((r)[3]) : "r"(addr))
#define LDSM2(r, addr) \
    asm volatile("ldmatrix.sync.aligned.m8n8.x2.shared.b16 {%0,%1}, [%2];" \
        : "=r"((r)[0]), "=r"((r)[1]) : "r"(addr))
#define MMA(d, a, b) \
    asm volatile("mma.sync.aligned.m16n8k16.row.col.f32.bf16.bf16.f32 " \
        "{%0,%1,%2,%3},{%4,%5,%6,%7},{%8,%9},{%0,%1,%2,%3};" \
        : "+f"((d)[0]), "+f"((d)[1]), "+f"((d)[2]), "+f"((d)[3]) \
        : "r"((a)[0]), "r"((a)[1]), "r"((a)[2]), "r"((a)[3]), "r"((b)[0]), "r"((b)[1]))

__device__ __forceinline__ float sigm(float x) { return 1.f / (1.f + __expf(-x)); }
__device__ __forceinline__ float tanh_f(float x) { return 1.f - 2.f / (__expf(2.f * x) + 1.f); }

// ---------------- geometry ----------------
// xw kernel (128 threads, 2-stage, 64x64 tiles)
#define ROWB 272
#define MATB (64 * ROWB)      // 17408
#define BUFB (4 * MATB)       // 69632 (Ah, Al, Bh, Bl)
#define SMEM_XW (2 * BUFB)    // 139264

// persistent step kernel (512 threads): W resident + 2-stage A; Gs aliases both stages
#define WROWB 2064                       // 1024 bf16 + 16B pad
#define WMATB (32 * WROWB)               // 66048
#define W_HI 0
#define W_LO WMATB                       // 66048
#define ASTG (2 * WMATB)                 // 132096
#define ASTGB (2 * MATB)                 // 34816 per stage (hi+lo)
#define GS_OFF ASTG                      // Gs [8][32][68] f32 = 69632 — aliases both stages
#define HS_OFF (ASTG + 2 * ASTGB)        // 201728 ; Hs hi/lo = 2048
#define SMEM_ST (HS_OFF + 2048)          // 203776

// ---------------- init: zero h and c, reset barrier ----------------
__global__ void init_kernel() {
    int i = blockIdx.x * blockDim.x + threadIdx.x;
    if (i == 0) { g_root = 0; g_flag = 0; }
    if (i < 8) g_leaf[i] = 0;
    if (i < Bz * Hz) {
        __nv_bfloat16 z = __float2bfloat16(0.f);
        g_h_hi[0][i] = z; g_h_hi[1][i] = z;
        g_h_lo[0][i] = z; g_h_lo[1][i] = z;
        g_c[i] = 0.f;
    }
}

// ---------------- prep: transpose+split W -> [n'=c*4+g][k] bf16 hi/lo ----------------
__global__ __launch_bounds__(256) void prep_tr(const float* __restrict__ src, int K, int sel) {
    __shared__ float tile[32][33];
    int n0 = blockIdx.x * 32, k0 = blockIdx.y * 32;
    int tx = threadIdx.x & 31, ty = threadIdx.x >> 5;   // 32 x 8
#pragma unroll
    for (int r = 0; r < 4; r++)
        tile[ty + r * 8][tx] = src[(size_t)(k0 + ty + r * 8) * G4 + n0 + tx];
    __syncthreads();
    __nv_bfloat16* dh = sel ? g_wt_hi : g_wx_hi;
    __nv_bfloat16* dl = sel ? g_wt_lo : g_wx_lo;
#pragma unroll
    for (int r = 0; r < 4; r++) {
        int n = n0 + ty + r * 8;
        int np = (n & 1023) * 4 + (n >> 10);
        float v = tile[tx][ty + r * 8];
        __nv_bfloat16 hi = __float2bfloat16(v);
        dh[(size_t)np * K + k0 + tx] = hi;
        dl[(size_t)np * K + k0 + tx] = __float2bfloat16(v - __bfloat162float(hi));
    }
}

// ---------------- prep: gather emb rows, split to bf16 hi/lo [m][k] ----------------
__global__ void prep_emb(const int* __restrict__ X, const float* __restrict__ emb) {
    int m = blockIdx.x;                 // m = s*64+b
    int s = m >> 6, b = m & 63;
    int row = X[b * Sz + s];
    const float4* src = (const float4*)(emb + (size_t)row * Ez);
    int k4 = threadIdx.x;
    float4 v = src[k4];
    __nv_bfloat16 hx = __float2bfloat16(v.x), hy = __float2bfloat16(v.y);
    __nv_bfloat16 hz = __float2bfloat16(v.z), hw = __float2bfloat16(v.w);
    __nv_bfloat162* dh = (__nv_bfloat162*)(g_a_hi + (size_t)m * Ez);
    __nv_bfloat162* dl = (__nv_bfloat162*)(g_a_lo + (size_t)m * Ez);
    dh[k4 * 2]     = __nv_bfloat162(hx, hy);
    dh[k4 * 2 + 1] = __nv_bfloat162(hz, hw);
    dl[k4 * 2]     = __nv_bfloat162(__float2bfloat16(v.x - __bfloat162float(hx)),
                                    __float2bfloat16(v.y - __bfloat162float(hy)));
    dl[k4 * 2 + 1] = __nv_bfloat162(__float2bfloat16(v.z - __bfloat162float(hz)),
                                    __float2bfloat16(v.w - __bfloat162float(hw)));
}

__global__ void prep_bias(const float* __restrict__ bias) {
    int n = blockIdx.x * blockDim.x + threadIdx.x;
    if (n < G4) g_bias2[(n & 1023) * 4 + (n >> 10)] = bias[n];
}

// ---------------- xw GEMM building blocks (128 threads) ----------------
__device__ __forceinline__ void load_mat(uint32_t dst, const __nv_bfloat16* src,
                                         int stride_elems, int tid) {
#pragma unroll
    for (int i = 0; i < 8; i++) {
        int idx = i * 128 + tid;
        int row = idx >> 4, seg = idx & 15;
        CP16(dst + row * ROWB + seg * 16,
             (const char*)(src + (size_t)row * stride_elems) + seg * 16);
    }
}

__device__ __forceinline__ void compute_chunk(uint32_t buf, int lane, int mbase, int nbase,
                                              float acc[2][4][4]) {
    const uint32_t aH = buf, aL = buf + MATB, bH = buf + 2 * MATB, bL = buf + 3 * MATB;
    const int g = lane >> 3;
    const int arow = (lane & 7) + ((g & 1) << 3);
    const int ahalf = (g >> 1) * 16;
    const int brow = lane & 7;
    const int bhalf = ((lane >> 3) & 1) * 16;
#pragma unroll
    for (int k16 = 0; k16 < 8; k16++) {
        const uint32_t kb = k16 * 32;
        uint32_t ah[2][4], al[2][4], bh[4][2], bl[4][2];
#pragma unroll
        for (int mt = 0; mt < 2; mt++) {
            uint32_t ao = (uint32_t)((mbase + mt * 16 + arow) * ROWB) + kb + ahalf;
            LDSM4(ah[mt], aH + ao);
            LDSM4(al[mt], aL + ao);
        }
#pragma unroll
        for (int nt = 0; nt < 4; nt++) {
            uint32_t bo = (uint32_t)((nbase + nt * 8 + brow) * ROWB) + kb + bhalf;
            LDSM2(bh[nt], bH + bo);
            LDSM2(bl[nt], bL + bo);
        }
#pragma unroll
        for (int mt = 0; mt < 2; mt++)
#pragma unroll
            for (int nt = 0; nt < 4; nt++) {
                MMA(acc[mt][nt], ah[mt], bh[nt]);
                MMA(acc[mt][nt], ah[mt], bl[nt]);
                MMA(acc[mt][nt], al[mt], bh[nt]);
            }
    }
}

__device__ __forceinline__ void store_frags_to_Gs(float* Gs, int lane, int mbase, int nbase,
                                                  float acc[2][4][4]) {
    const int r = lane >> 2, c2 = (lane & 3) * 2;
#pragma unroll
    for (int mt = 0; mt < 2; mt++)
#pragma unroll
        for (int nt = 0; nt < 4; nt++) {
            int m = mbase + mt * 16 + r;
            int n = nbase + nt * 8 + c2;
            Gs[n * 68 + m]           = acc[mt][nt][0];
            Gs[(n + 1) * 68 + m]     = acc[mt][nt][1];
            Gs[n * 68 + m + 8]       = acc[mt][nt][2];
            Gs[(n + 1) * 68 + m + 8] = acc[mt][nt][3];
        }
}

// ---------------- xw GEMM: g_xw2[s][n'][b] = emb_m @ Wx^T + bias (bf16x3) ----------------
__global__ __launch_bounds__(128, 1) void xw_mma() {
    extern __shared__ char smem[];
    const uint32_t sb = smem_u32(smem);
    const int tid = threadIdx.x, lane = tid & 31, w = tid >> 5;
    const int np0 = blockIdx.x * 64;
    const int s = blockIdx.y;
    const __nv_bfloat16* Ah = g_a_hi + (size_t)s * Bz * Ez;
    const __nv_bfloat16* Al = g_a_lo + (size_t)s * Bz * Ez;
    const __nv_bfloat16* Bh = g_wx_hi + (size_t)np0 * Ez;
    const __nv_bfloat16* Bl = g_wx_lo + (size_t)np0 * Ez;

    float acc[2][4][4] = {};
    const int mbase = (w & 1) * 32, nbase = (w >> 1) * 32;

    load_mat(sb, Ah, Ez, tid);
    load_mat(sb + MATB, Al, Ez, tid);
    load_mat(sb + 2 * MATB, Bh, Ez, tid);
    load_mat(sb + 3 * MATB, Bl, Ez, tid);
    CP_COMMIT();

    for (int c = 0; c < 4; c++) {
        if (c < 3) {
            int kc = (c + 1) * 128;
            uint32_t buf = sb + ((c + 1) & 1) * BUFB;
            load_mat(buf, Ah + kc, Ez, tid);
            load_mat(buf + MATB, Al + kc, Ez, tid);
            load_mat(buf + 2 * MATB, Bh + kc, Ez, tid);
            load_mat(buf + 3 * MATB, Bl + kc, Ez, tid);
            CP_COMMIT();
            CP_WAITN(1);
        } else {
            CP_WAITN(0);
        }
        __syncthreads();
        compute_chunk(sb + (c & 1) * BUFB, lane, mbase, nbase, acc);
        __syncthreads();
    }

    float* Gs = (float*)smem;   // [64][68]
    store_frags_to_Gs(Gs, lane, mbase, nbase, acc);
    __syncthreads();

    float* outb = g_xw2 + ((size_t)s * G4 + np0) * Bz;
#pragma unroll
    for (int i = 0; i < 32; i++) {
        int e = i * 128 + tid;               // e = n'local*64 + b
        int nl = e >> 6, b = e & 63;
        outb[e] = Gs[nl * 68 + b] + g_bias2[np0 + nl];
    }
}

// ---------------- persistent LSTM recurrence ----------------
// 128 CTAs x 512 threads (16 warps = 4/SMSP). CTA owns 32 n' (8 h-cols).
// Warps: mh = w&1 (32 batch rows), ksub = w>>1 (one k16 per 128-chunk).
// Partials per ksub go to private Gs strips; epilogue sums 8 strips.
__device__ __forceinline__ void gbar_tree(int t, int tid, int blk) {
    __syncthreads();
    if (tid == 0) {
        int grp = blk >> 4;
        int old;
        asm volatile("atom.add.acq_rel.gpu.global.s32 %0, [%1], 1;"
                     : "=r"(old) : "l"(&g_leaf[grp]) : "memory");
        if (old == 16 * t - 1) {
            int rold;
            asm volatile("atom.add.acq_rel.gpu.global.s32 %0, [%1], 1;"
                         : "=r"(rold) : "l"(&g_root) : "memory");
            if (rold == 8 * t - 1) {
                asm volatile("st.release.gpu.global.s32 [%0], %1;"
                             :: "l"(&g_flag), "r"(t) : "memory");
            }
        }
        int f;
        do {
            asm volatile("ld.acquire.gpu.global.s32 %0, [%1];" : "=r"(f) : "l"(&g_flag));
        } while (f < t);
    }
    __syncthreads();
}

// load one 64x128 bf16 A tile (512 threads, 2 CP16 each)
__device__ __forceinline__ void load_A(uint32_t dst, const __nv_bfloat16* src, int tid) {
#pragma unroll
    for (int i = 0; i < 2; i++) {
        int idx = i * 512 + tid;
        int row = idx >> 4, seg = idx & 15;
        CP16(dst + row * ROWB + seg * 16,
             (const char*)(src + (size_t)row * Hz) + seg * 16);
    }
}

__global__ __launch_bounds__(512, 1) void steps_persistent(const int* __restrict__ seqlen) {
    extern __shared__ char smem[];
    const uint32_t sb = smem_u32(smem);
    const int tid = threadIdx.x, lane = tid & 31, w = tid >> 5;
    const int blk = blockIdx.x;
    const int np0 = blk * 32, c0 = blk * 8;
    const int mh = w & 1;                // batch half (32 rows)
    const int ksub = w >> 1;             // k16 index within each 128-chunk (0..7)
    const int sl_b = __ldg(seqlen + (tid & 63));

    // ---- load W resident: 32 rows x 1024 k, hi+lo (4096 CP16 each) ----
#pragma unroll
    for (int i = 0; i < 8; i++) {
        int idx = i * 512 + tid;
        int row = idx >> 7, seg = idx & 127;
        CP16(sb + W_HI + row * WROWB + seg * 16,
             (const char*)(g_wt_hi + (size_t)(np0 + row) * Hz) + seg * 16);
    }
#pragma unroll
    for (int i = 0; i < 8; i++) {
        int idx = i * 512 + tid;
        int row = idx >> 7, seg = idx & 127;
        CP16(sb + W_LO + row * WROWB + seg * 16,
             (const char*)(g_wt_lo + (size_t)(np0 + row) * Hz) + seg * 16);
    }
    CP_COMMIT();

    float* Gs = (float*)(smem + GS_OFF);                     // [8 ksub][32 n'][68 m]
    __nv_bfloat16* HsH = (__nv_bfloat16*)(smem + HS_OFF);    // [64][8]
    __nv_bfloat16* HsL = (__nv_bfloat16*)(smem + HS_OFF + 1024);

    for (int t = 0; t < Sz; t++) {
        const __nv_bfloat16* h_hi = g_h_hi[t & 1];
        const __nv_bfloat16* h_lo = g_h_lo[t & 1];
        __nv_bfloat16* o_hi = g_h_hi[(t + 1) & 1];
        __nv_bfloat16* o_lo = g_h_lo[(t + 1) & 1];

        // epilogue operand prefetch (xw static, c CTA-local) — before barrier
        const float* xwb = g_xw2 + ((size_t)t * G4 + np0) * Bz;
        float xg[4], cold;
        {
            const int b = tid & 63;
            const int col = tid >> 6;
#pragma unroll
            for (int g = 0; g < 4; g++)
                xg[g] = __ldg(xwb + (col * 4 + g) * Bz + b);
            cold = g_c[(c0 + col) * Bz + b];
        }

        if (t > 0) gbar_tree(t, tid, blk);                   // all CTAs finished t-1

        load_A(sb + ASTG, h_hi, tid);
        load_A(sb + ASTG + MATB, h_lo, tid);
        CP_COMMIT();

        float acc[2][4][4] = {};                             // [mt][nt][4], tile 32x32
#pragma unroll
        for (int c = 0; c < 8; c++) {
            if (c < 7) {
                uint32_t buf = sb + ASTG + (uint32_t)((c + 1) & 1) * ASTGB;
                load_A(buf, h_hi + (c + 1) * 128, tid);
                load_A(buf + MATB, h_lo + (c + 1) * 128, tid);
                CP_COMMIT();
                CP_WAITN(1);
            } else {
                CP_WAITN(0);
            }
            __syncthreads();

            // compute: this warp covers k16 = ksub of chunk c
            {
                const uint32_t abuf = sb + ASTG + (uint32_t)(c & 1) * ASTGB;
                const int arow = lane & 15;
                const int ahalf = (lane >> 4) * 16;
                const int brow = lane & 7;
                const int bhalf = ((lane >> 3) & 1) * 16;
                uint32_t ah[2][4], al[2][4], bh[4][2], bl[4][2];
#pragma unroll
                for (int mt = 0; mt < 2; mt++) {
                    uint32_t ao = (uint32_t)((mh * 32 + mt * 16 + arow) * ROWB)
                                  + ksub * 32 + ahalf;
                    LDSM4(ah[mt], abuf + ao);
                    LDSM4(al[mt], abuf + MATB + ao);
                }
                const uint32_t kwb = (uint32_t)(c * 128 + ksub * 16) * 2 + bhalf;
#pragma unroll
                for (int nt = 0; nt < 4; nt++) {
                    uint32_t bo = (uint32_t)((nt * 8 + brow) * WROWB) + kwb;
                    LDSM2(bh[nt], sb + W_HI + bo);
                    LDSM2(bl[nt], sb + W_LO + bo);
                }
#pragma unroll
                for (int mt = 0; mt < 2; mt++)
#pragma unroll
                    for (int nt = 0; nt < 4; nt++) {
                        MMA(acc[mt][nt], ah[mt], bh[nt]);
                        MMA(acc[mt][nt], ah[mt], bl[nt]);
                        MMA(acc[mt][nt], al[mt], bh[nt]);
                    }
            }
            __syncthreads();
        }

        // write partials to private strip (Gs aliases both stage buffers, dead now)
        {
            float* strip = Gs + ksub * (32 * 68);
            const int r = lane >> 2, c2 = (lane & 3) * 2;
#pragma unroll
            for (int mt = 0; mt < 2; mt++)
#pragma unroll
                for (int nt = 0; nt < 4; nt++) {
                    int m = mh * 32 + mt * 16 + r;
                    int n = nt * 8 + c2;
                    strip[n * 68 + m]           = acc[mt][nt][0];
                    strip[(n + 1) * 68 + m]     = acc[mt][nt][1];
                    strip[n * 68 + m + 8]       = acc[mt][nt][2];
                    strip[(n + 1) * 68 + m + 8] = acc[mt][nt][3];
                }
        }
        __syncthreads();

        // pointwise LSTM: sum 8 ksub strips + xw; one (col,b) per thread
        {
            const int col = tid >> 6, b = tid & 63;
            const bool is_last = (t == sl_b - 1);
            float gg[4];
#pragma unroll
            for (int g = 0; g < 4; g++) {
                int off = (col * 4 + g) * 68 + b;
                float s0 = Gs[off]            + Gs[off + 2176];
                float s1 = Gs[off + 2 * 2176] + Gs[off + 3 * 2176];
                float s2 = Gs[off + 4 * 2176] + Gs[off + 5 * 2176];
                float s3 = Gs[off + 6 * 2176] + Gs[off + 7 * 2176];
                gg[g] = ((s0 + s1) + (s2 + s3)) + xg[g];
            }
            float cn = cold * sigm(gg[2] + 1.0f) + sigm(gg[0]) * tanh_f(gg[1]);
            float hn = tanh_f(cn) * sigm(gg[3]);
            g_c[(c0 + col) * Bz + b] = cn;
            __nv_bfloat16 hi = __float2bfloat16(hn);
            HsH[b * 8 + col] = hi;
            HsL[b * 8 + col] = __float2bfloat16(hn - __bfloat162float(hi));
            if (is_last) g_final[(size_t)b * Hz + c0 + col] = hn;
        }
        __syncthreads();

        // coalesced 16B h writes
        if (tid < 64) {
            *(uint4*)(o_hi + (size_t)tid * Hz + c0) = *(uint4*)(HsH + tid * 8);
        } else if (tid < 128) {
            int b = tid - 64;
            *(uint4*)(o_lo + (size_t)b * Hz + c0) = *(uint4*)(HsL + b * 8);
        }
    }
}

// ---------------- dense = relu(final @ dense_w + dense_b) ----------------
__global__ void dense_kernel(const float* __restrict__ dw, const float* __restrict__ db) {
    int b = blockIdx.x;
    int d = threadIdx.x;    // 512 threads
    const float* f = g_final + (size_t)b * Hz;
    float s0 = 0.f, s1 = 0.f, s2 = 0.f, s3 = 0.f;
#pragma unroll 4
    for (int k = 0; k < Hz; k += 4) {
        s0 += f[k]     * dw[(size_t)(k)     * Dz + d];
        s1 += f[k + 1] * dw[(size_t)(k + 1) * Dz + d];
        s2 += f[k + 2] * dw[(size_t)(k + 2) * Dz + d];
        s3 += f[k + 3] * dw[(size_t)(k + 3) * Dz + d];
    }
    float s = (s0 + s1) + (s2 + s3) + db[d];
    g_dense[(size_t)b * Dz + d] = fmaxf(s, 0.f);
}

// ---------------- logits = dense @ pred_w + pred_b ----------------
__global__ void logits_kernel(const float* __restrict__ pw, const float* __restrict__ pb,
                              float* __restrict__ out) {
    int tid = threadIdx.x;
    if (tid >= Bz * Cz) return;
    int b = tid >> 1;
    int cc = tid & 1;
    const float* dn = g_dense + (size_t)b * Dz;
    float s = 0.f;
#pragma unroll 4
    for (int d = 0; d < Dz; d++) s += dn[d] * pw[(size_t)d * Cz + cc];
    out[b * Cz + cc] = s + pb[cc];
}

// ---------------- launch ----------------
extern "C" void kernel_launch(void* const* d_in, const int* in_sizes, int n_in,
                              void* d_out, int out_size) {
    const int*   X      = (const int*)d_in[0];
    const int*   seqlen = (const int*)d_in[1];
    const float* emb    = (const float*)d_in[2];
    const float* Wf     = (const float*)d_in[3];   // [1536, 4096]
    const float* bias   = (const float*)d_in[4];
    const float* dw     = (const float*)d_in[5];
    const float* db     = (const float*)d_in[6];
    const float* pw     = (const float*)d_in[7];
    const float* pb     = (const float*)d_in[8];
    float* out = (float*)d_out;

    cudaFuncSetAttribute(xw_mma, cudaFuncAttributeMaxDynamicSharedMemorySize, SMEM_XW);
    cudaFuncSetAttribute(steps_persistent, cudaFuncAttributeMaxDynamicSharedMemorySize, SMEM_ST);

    init_kernel<<<(Bz * Hz + 255) / 256, 256>>>();
    prep_tr<<<dim3(G4 / 32, Ez / 32), 256>>>(Wf, Ez, 0);                   // Wx
    prep_tr<<<dim3(G4 / 32, Hz / 32), 256>>>(Wf + (size_t)Ez * G4, Hz, 1); // Wh
    prep_emb<<<Sz * Bz, 128>>>(X, emb);
    prep_bias<<<G4 / 256, 256>>>(bias);

    xw_mma<<<dim3(G4 / 64, Sz), 128, SMEM_XW>>>();

    steps_persistent<<<128, 512, SMEM_ST>>>(seqlen);

    dense_kernel<<<Bz, Dz>>>(dw, db);
    logits_kernel<<<1, 128>>>(pw, pb, out);
}

// round 10
// speedup vs baseline: 1.3276x; 1.0445x over previous
#include <cuda_runtime.h>
#include <cuda_bf16.h>
#include <cuda_fp16.h>
#include <stdint.h>

#define Bz 64
#define Sz 256
#define Ez 512
#define Hz 1024
#define G4 4096   // 4*Hz
#define Dz 512
#define Cz 2

// ---------------- device scratch (no cudaMalloc allowed) ----------------
__device__ __align__(128) float g_xw2[(size_t)Sz * G4 * Bz];        // [s][n'][b]
__device__ __align__(128) __half g_wth_hi[(size_t)G4 * Hz];         // Wh^T fp16 hi [n'][k]
__device__ __align__(128) __half g_wth_lo[(size_t)G4 * Hz];         // Wh^T fp16 lo
__device__ __align__(128) __nv_bfloat16 g_wx_hi[(size_t)G4 * Ez];   // Wx^T bf16 [n'][k]
__device__ __align__(128) __nv_bfloat16 g_wx_lo[(size_t)G4 * Ez];
__device__ __align__(128) __nv_bfloat16 g_a_hi[(size_t)Sz * Bz * Ez]; // gathered emb [m][k]
__device__ __align__(128) __nv_bfloat16 g_a_lo[(size_t)Sz * Bz * Ez];
__device__ __align__(128) __half g_h[2][(size_t)Bz * Hz];           // h fp16 [b][k] ping-pong
__device__ __align__(128) float g_bias2[G4];                        // permuted bias
__device__ __align__(128) float g_c[Hz * Bz];                       // cell [c][b]
__device__ __align__(128) float g_final[(size_t)Bz * Hz];           // [b][h]
__device__ __align__(128) float g_dense[Bz * Dz];
__device__ __align__(128) int g_leaf[8];                            // tree barrier leaves
__device__ int g_root;                                              // tree barrier root
__device__ int g_flag;                                              // release flag

// ================= PTX helpers (non-'a' features only) =================
__device__ __forceinline__ uint32_t smem_u32(const void* p) {
    uint32_t a;
    asm("{ .reg .u64 t; cvta.to.shared.u64 t, %1; cvt.u32.u64 %0, t; }" : "=r"(a) : "l"(p));
    return a;
}
#define CP16(dst, src) \
    asm volatile("cp.async.cg.shared.global [%0], [%1], 16;" :: "r"((uint32_t)(dst)), "l"(src))
#define CP_COMMIT() asm volatile("cp.async.commit_group;" ::: "memory")
#define CP_WAITN(n) asm volatile("cp.async.wait_group %0;" :: "n"(n) : "memory")

#define LDSM4(r, addr) \
    asm volatile("ldmatrix.sync.aligned.m8n8.x4.shared.b16 {%0,%1,%2,%3}, [%4];" \
        : "=r"((r)[0]), "=r"((r)[1]), "=r"((r)[2]), "=r"((r)[3]) : "r"(addr))
#define LDSM2(r, addr) \
    asm volatile("ldmatrix.sync.aligned.m8n8.x2.shared.b16 {%0,%1}, [%2];" \
        : "=r"((r)[0]), "=r"((r)[1]) : "r"(addr))
#define MMA(d, a, b) \
    asm volatile("mma.sync.aligned.m16n8k16.row.col.f32.bf16.bf16.f32 " \
        "{%0,%1,%2,%3},{%4,%5,%6,%7},{%8,%9},{%0,%1,%2,%3};" \
        : "+f"((d)[0]), "+f"((d)[1]), "+f"((d)[2]), "+f"((d)[3]) \
        : "r"((a)[0]), "r"((a)[1]), "r"((a)[2]), "r"((a)[3]), "r"((b)[0]), "r"((b)[1]))
#define MMAH(d, a, b) \
    asm volatile("mma.sync.aligned.m16n8k16.row.col.f32.f16.f16.f32 " \
        "{%0,%1,%2,%3},{%4,%5,%6,%7},{%8,%9},{%0,%1,%2,%3};" \
        : "+f"((d)[0]), "+f"((d)[1]), "+f"((d)[2]), "+f"((d)[3]) \
        : "r"((a)[0]), "r"((a)[1]), "r"((a)[2]), "r"((a)[3]), "r"((b)[0]), "r"((b)[1]))

__device__ __forceinline__ float sigm(float x) { return 1.f / (1.f + __expf(-x)); }
__device__ __forceinline__ float tanh_f(float x) { return 1.f - 2.f / (__expf(2.f * x) + 1.f); }

// ---------------- geometry ----------------
// xw kernel (128 threads, 2-stage, 64x64 tiles)
#define ROWB 272
#define MATB (64 * ROWB)      // 17408
#define BUFB (4 * MATB)       // 69632 (Ah, Al, Bh, Bl)
#define SMEM_XW (2 * BUFB)    // 139264

// persistent step kernel (512 threads): W fp16 resident + 2-stage A(hi only)
#define WROWB 2064                       // 1024 fp16 + 16B pad
#define WMATB (32 * WROWB)               // 66048
#define W_HI 0
#define W_LO WMATB                       // 66048
#define ASTG (2 * WMATB)                 // 132096
#define ASTGB MATB                       // 17408 per stage (hi only)
#define GS_OFF ASTG                      // Gs [8][32][68] f32 = 69632 — aliases A + spare
#define HS_OFF (ASTG + 69632)            // 201728 ; HsH = 64*8*2 = 1024
#define SMEM_ST (HS_OFF + 1024)          // 202752

// ---------------- init: zero h and c, reset barrier ----------------
__global__ void init_kernel() {
    int i = blockIdx.x * blockDim.x + threadIdx.x;
    if (i == 0) { g_root = 0; g_flag = 0; }
    if (i < 8) g_leaf[i] = 0;
    if (i < Bz * Hz) {
        __half z = __float2half(0.f);
        g_h[0][i] = z; g_h[1][i] = z;
        g_c[i] = 0.f;
    }
}

// ---------------- prep: transpose+split W -> [n'=c*4+g][k] ----------------
// sel==0: Wx -> bf16 hi/lo (K=512). sel==1: Wh -> fp16 hi/lo (K=1024).
__global__ __launch_bounds__(256) void prep_tr(const float* __restrict__ src, int K, int sel) {
    __shared__ float tile[32][33];
    int n0 = blockIdx.x * 32, k0 = blockIdx.y * 32;
    int tx = threadIdx.x & 31, ty = threadIdx.x >> 5;   // 32 x 8
#pragma unroll
    for (int r = 0; r < 4; r++)
        tile[ty + r * 8][tx] = src[(size_t)(k0 + ty + r * 8) * G4 + n0 + tx];
    __syncthreads();
#pragma unroll
    for (int r = 0; r < 4; r++) {
        int n = n0 + ty + r * 8;
        int np = (n & 1023) * 4 + (n >> 10);
        float v = tile[tx][ty + r * 8];
        if (sel) {
            __half hi = __float2half_rn(v);
            g_wth_hi[(size_t)np * K + k0 + tx] = hi;
            g_wth_lo[(size_t)np * K + k0 + tx] = __float2half_rn(v - __half2float(hi));
        } else {
            __nv_bfloat16 hi = __float2bfloat16(v);
            g_wx_hi[(size_t)np * K + k0 + tx] = hi;
            g_wx_lo[(size_t)np * K + k0 + tx] = __float2bfloat16(v - __bfloat162float(hi));
        }
    }
}

// ---------------- prep: gather emb rows, split to bf16 hi/lo [m][k] ----------------
__global__ void prep_emb(const int* __restrict__ X, const float* __restrict__ emb) {
    int m = blockIdx.x;                 // m = s*64+b
    int s = m >> 6, b = m & 63;
    int row = X[b * Sz + s];
    const float4* src = (const float4*)(emb + (size_t)row * Ez);
    int k4 = threadIdx.x;
    float4 v = src[k4];
    __nv_bfloat16 hx = __float2bfloat16(v.x), hy = __float2bfloat16(v.y);
    __nv_bfloat16 hz = __float2bfloat16(v.z), hw = __float2bfloat16(v.w);
    __nv_bfloat162* dh = (__nv_bfloat162*)(g_a_hi + (size_t)m * Ez);
    __nv_bfloat162* dl = (__nv_bfloat162*)(g_a_lo + (size_t)m * Ez);
    dh[k4 * 2]     = __nv_bfloat162(hx, hy);
    dh[k4 * 2 + 1] = __nv_bfloat162(hz, hw);
    dl[k4 * 2]     = __nv_bfloat162(__float2bfloat16(v.x - __bfloat162float(hx)),
                                    __float2bfloat16(v.y - __bfloat162float(hy)));
    dl[k4 * 2 + 1] = __nv_bfloat162(__float2bfloat16(v.z - __bfloat162float(hz)),
                                    __float2bfloat16(v.w - __bfloat162float(hw)));
}

__global__ void prep_bias(const float* __restrict__ bias) {
    int n = blockIdx.x * blockDim.x + threadIdx.x;
    if (n < G4) g_bias2[(n & 1023) * 4 + (n >> 10)] = bias[n];
}

// ---------------- xw GEMM building blocks (128 threads) ----------------
__device__ __forceinline__ void load_mat(uint32_t dst, const __nv_bfloat16* src,
                                         int stride_elems, int tid) {
#pragma unroll
    for (int i = 0; i < 8; i++) {
        int idx = i * 128 + tid;
        int row = idx >> 4, seg = idx & 15;
        CP16(dst + row * ROWB + seg * 16,
             (const char*)(src + (size_t)row * stride_elems) + seg * 16);
    }
}

__device__ __forceinline__ void compute_chunk(uint32_t buf, int lane, int mbase, int nbase,
                                              float acc[2][4][4]) {
    const uint32_t aH = buf, aL = buf + MATB, bH = buf + 2 * MATB, bL = buf + 3 * MATB;
    const int g = lane >> 3;
    const int arow = (lane & 7) + ((g & 1) << 3);
    const int ahalf = (g >> 1) * 16;
    const int brow = lane & 7;
    const int bhalf = ((lane >> 3) & 1) * 16;
#pragma unroll
    for (int k16 = 0; k16 < 8; k16++) {
        const uint32_t kb = k16 * 32;
        uint32_t ah[2][4], al[2][4], bh[4][2], bl[4][2];
#pragma unroll
        for (int mt = 0; mt < 2; mt++) {
            uint32_t ao = (uint32_t)((mbase + mt * 16 + arow) * ROWB) + kb + ahalf;
            LDSM4(ah[mt], aH + ao);
            LDSM4(al[mt], aL + ao);
        }
#pragma unroll
        for (int nt = 0; nt < 4; nt++) {
            uint32_t bo = (uint32_t)((nbase + nt * 8 + brow) * ROWB) + kb + bhalf;
            LDSM2(bh[nt], bH + bo);
            LDSM2(bl[nt], bL + bo);
        }
#pragma unroll
        for (int mt = 0; mt < 2; mt++)
#pragma unroll
            for (int nt = 0; nt < 4; nt++) {
                MMA(acc[mt][nt], ah[mt], bh[nt]);
                MMA(acc[mt][nt], ah[mt], bl[nt]);
                MMA(acc[mt][nt], al[mt], bh[nt]);
            }
    }
}

__device__ __forceinline__ void store_frags_to_Gs(float* Gs, int lane, int mbase, int nbase,
                                                  float acc[2][4][4]) {
    const int r = lane >> 2, c2 = (lane & 3) * 2;
#pragma unroll
    for (int mt = 0; mt < 2; mt++)
#pragma unroll
        for (int nt = 0; nt < 4; nt++) {
            int m = mbase + mt * 16 + r;
            int n = nbase + nt * 8 + c2;
            Gs[n * 68 + m]           = acc[mt][nt][0];
            Gs[(n + 1) * 68 + m]     = acc[mt][nt][1];
            Gs[n * 68 + m + 8]       = acc[mt][nt][2];
            Gs[(n + 1) * 68 + m + 8] = acc[mt][nt][3];
        }
}

// ---------------- xw GEMM: g_xw2[s][n'][b] = emb_m @ Wx^T + bias (bf16x3) ----------------
__global__ __launch_bounds__(128, 1) void xw_mma() {
    extern __shared__ char smem[];
    const uint32_t sb = smem_u32(smem);
    const int tid = threadIdx.x, lane = tid & 31, w = tid >> 5;
    const int np0 = blockIdx.x * 64;
    const int s = blockIdx.y;
    const __nv_bfloat16* Ah = g_a_hi + (size_t)s * Bz * Ez;
    const __nv_bfloat16* Al = g_a_lo + (size_t)s * Bz * Ez;
    const __nv_bfloat16* Bh = g_wx_hi + (size_t)np0 * Ez;
    const __nv_bfloat16* Bl = g_wx_lo + (size_t)np0 * Ez;

    float acc[2][4][4] = {};
    const int mbase = (w & 1) * 32, nbase = (w >> 1) * 32;

    load_mat(sb, Ah, Ez, tid);
    load_mat(sb + MATB, Al, Ez, tid);
    load_mat(sb + 2 * MATB, Bh, Ez, tid);
    load_mat(sb + 3 * MATB, Bl, Ez, tid);
    CP_COMMIT();

    for (int c = 0; c < 4; c++) {
        if (c < 3) {
            int kc = (c + 1) * 128;
            uint32_t buf = sb + ((c + 1) & 1) * BUFB;
            load_mat(buf, Ah + kc, Ez, tid);
            load_mat(buf + MATB, Al + kc, Ez, tid);
            load_mat(buf + 2 * MATB, Bh + kc, Ez, tid);
            load_mat(buf + 3 * MATB, Bl + kc, Ez, tid);
            CP_COMMIT();
            CP_WAITN(1);
        } else {
            CP_WAITN(0);
        }
        __syncthreads();
        compute_chunk(sb + (c & 1) * BUFB, lane, mbase, nbase, acc);
        __syncthreads();
    }

    float* Gs = (float*)smem;   // [64][68]
    store_frags_to_Gs(Gs, lane, mbase, nbase, acc);
    __syncthreads();

    float* outb = g_xw2 + ((size_t)s * G4 + np0) * Bz;
#pragma unroll
    for (int i = 0; i < 32; i++) {
        int e = i * 128 + tid;               // e = n'local*64 + b
        int nl = e >> 6, b = e & 63;
        outb[e] = Gs[nl * 68 + b] + g_bias2[np0 + nl];
    }
}

// ---------------- persistent LSTM recurrence ----------------
// 128 CTAs x 512 threads (16 warps). CTA owns 32 n' (8 h-cols). W fp16 split-2 resident.
// gates = h_fp16 @ (W_hi + W_lo): 2 MMA products. Warps: mh = w&1, ksub = w>>1.
__device__ __forceinline__ void gbar_tree(int t, int tid, int blk) {
    __syncthreads();
    if (tid == 0) {
        int grp = blk >> 4;
        int old;
        asm volatile("atom.add.acq_rel.gpu.global.s32 %0, [%1], 1;"
                     : "=r"(old) : "l"(&g_leaf[grp]) : "memory");
        if (old == 16 * t - 1) {
            int rold;
            asm volatile("atom.add.acq_rel.gpu.global.s32 %0, [%1], 1;"
                         : "=r"(rold) : "l"(&g_root) : "memory");
            if (rold == 8 * t - 1) {
                asm volatile("st.release.gpu.global.s32 [%0], %1;"
                             :: "l"(&g_flag), "r"(t) : "memory");
            }
        }
        int f;
        do {
            asm volatile("ld.acquire.gpu.global.s32 %0, [%1];" : "=r"(f) : "l"(&g_flag));
        } while (f < t);
    }
    __syncthreads();
}

// load one 64x128 fp16 A tile (512 threads, 2 CP16 each)
__device__ __forceinline__ void load_A(uint32_t dst, const __half* src, int tid) {
#pragma unroll
    for (int i = 0; i < 2; i++) {
        int idx = i * 512 + tid;
        int row = idx >> 4, seg = idx & 15;
        CP16(dst + row * ROWB + seg * 16,
             (const char*)(src + (size_t)row * Hz) + seg * 16);
    }
}

__global__ __launch_bounds__(512, 1) void steps_persistent(const int* __restrict__ seqlen) {
    extern __shared__ char smem[];
    const uint32_t sb = smem_u32(smem);
    const int tid = threadIdx.x, lane = tid & 31, w = tid >> 5;
    const int blk = blockIdx.x;
    const int np0 = blk * 32, c0 = blk * 8;
    const int mh = w & 1;                // batch half (32 rows)
    const int ksub = w >> 1;             // k16 index within each 128-chunk (0..7)
    const int sl_b = __ldg(seqlen + (tid & 63));

    // ---- load W resident: 32 rows x 1024 k, fp16 hi+lo ----
#pragma unroll
    for (int i = 0; i < 8; i++) {
        int idx = i * 512 + tid;
        int row = idx >> 7, seg = idx & 127;
        CP16(sb + W_HI + row * WROWB + seg * 16,
             (const char*)(g_wth_hi + (size_t)(np0 + row) * Hz) + seg * 16);
    }
#pragma unroll
    for (int i = 0; i < 8; i++) {
        int idx = i * 512 + tid;
        int row = idx >> 7, seg = idx & 127;
        CP16(sb + W_LO + row * WROWB + seg * 16,
             (const char*)(g_wth_lo + (size_t)(np0 + row) * Hz) + seg * 16);
    }
    CP_COMMIT();

    float* Gs = (float*)(smem + GS_OFF);                     // [8 ksub][32 n'][68 m]
    __half* HsH = (__half*)(smem + HS_OFF);                  // [64][8]

    for (int t = 0; t < Sz; t++) {
        const __half* h_in = g_h[t & 1];
        __half* h_out = g_h[(t + 1) & 1];

        // epilogue operand prefetch (xw static, c CTA-local) — before barrier
        const float* xwb = g_xw2 + ((size_t)t * G4 + np0) * Bz;
        float xg[4], cold;
        {
            const int b = tid & 63;
            const int col = tid >> 6;
#pragma unroll
            for (int g = 0; g < 4; g++)
                xg[g] = __ldg(xwb + (col * 4 + g) * Bz + b);
            cold = g_c[(c0 + col) * Bz + b];
        }

        if (t > 0) gbar_tree(t, tid, blk);                   // all CTAs finished t-1

        load_A(sb + ASTG, h_in, tid);
        CP_COMMIT();

        float acc[2][4][4] = {};                             // [mt][nt][4], tile 32x32
#pragma unroll
        for (int c = 0; c < 8; c++) {
            CP_WAITN(0);
            __syncthreads();                                 // stage (c&1) ready; prev consumed
            if (c < 7) {
                load_A(sb + ASTG + (uint32_t)((c + 1) & 1) * ASTGB,
                       h_in + (c + 1) * 128, tid);
                CP_COMMIT();
            }

            // compute: this warp covers k16 = ksub of chunk c
            {
                const uint32_t abuf = sb + ASTG + (uint32_t)(c & 1) * ASTGB;
                const int arow = lane & 15;
                const int ahalf = (lane >> 4) * 16;
                const int brow = lane & 7;
                const int bhalf = ((lane >> 3) & 1) * 16;
                uint32_t ah[2][4], bh[4][2], bl[4][2];
#pragma unroll
                for (int mt = 0; mt < 2; mt++) {
                    uint32_t ao = (uint32_t)((mh * 32 + mt * 16 + arow) * ROWB)
                                  + ksub * 32 + ahalf;
                    LDSM4(ah[mt], abuf + ao);
                }
                const uint32_t kwb = (uint32_t)(c * 128 + ksub * 16) * 2 + bhalf;
#pragma unroll
                for (int nt = 0; nt < 4; nt++) {
                    uint32_t bo = (uint32_t)((nt * 8 + brow) * WROWB) + kwb;
                    LDSM2(bh[nt], sb + W_HI + bo);
                    LDSM2(bl[nt], sb + W_LO + bo);
                }
#pragma unroll
                for (int mt = 0; mt < 2; mt++)
#pragma unroll
                    for (int nt = 0; nt < 4; nt++) {
                        MMAH(acc[mt][nt], ah[mt], bh[nt]);
                        MMAH(acc[mt][nt], ah[mt], bl[nt]);
                    }
            }
        }
        __syncthreads();                                     // last chunk consumed by all

        // write partials to private strip (Gs aliases A stages, dead now)
        {
            float* strip = Gs + ksub * (32 * 68);
            const int r = lane >> 2, c2 = (lane & 3) * 2;
#pragma unroll
            for (int mt = 0; mt < 2; mt++)
#pragma unroll
                for (int nt = 0; nt < 4; nt++) {
                    int m = mh * 32 + mt * 16 + r;
                    int n = nt * 8 + c2;
                    strip[n * 68 + m]           = acc[mt][nt][0];
                    strip[(n + 1) * 68 + m]     = acc[mt][nt][1];
                    strip[n * 68 + m + 8]       = acc[mt][nt][2];
                    strip[(n + 1) * 68 + m + 8] = acc[mt][nt][3];
                }
        }
        __syncthreads();

        // pointwise LSTM: sum 8 ksub strips + xw; one (col,b) per thread
        {
            const int col = tid >> 6, b = tid & 63;
            const bool is_last = (t == sl_b - 1);
            float gg[4];
#pragma unroll
            for (int g = 0; g < 4; g++) {
                int off = (col * 4 + g) * 68 + b;
                float s0 = Gs[off]            + Gs[off + 2176];
                float s1 = Gs[off + 2 * 2176] + Gs[off + 3 * 2176];
                float s2 = Gs[off + 4 * 2176] + Gs[off + 5 * 2176];
                float s3 = Gs[off + 6 * 2176] + Gs[off + 7 * 2176];
                gg[g] = ((s0 + s1) + (s2 + s3)) + xg[g];
            }
            float cn = cold * sigm(gg[2] + 1.0f) + sigm(gg[0]) * tanh_f(gg[1]);
            float hn = tanh_f(cn) * sigm(gg[3]);
            g_c[(c0 + col) * Bz + b] = cn;
            HsH[b * 8 + col] = __float2half_rn(hn);
            if (is_last) g_final[(size_t)b * Hz + c0 + col] = hn;
        }
        __syncthreads();

        // coalesced 16B h writes (8 fp16 per batch row)
        if (tid < 64) {
            *(uint4*)(h_out + (size_t)tid * Hz + c0) = *(uint4*)(HsH + tid * 8);
        }
    }
}

// ---------------- dense = relu(final @ dense_w + dense_b) ----------------
__global__ void dense_kernel(const float* __restrict__ dw, const float* __restrict__ db) {
    int b = blockIdx.x;
    int d = threadIdx.x;    // 512 threads
    const float* f = g_final + (size_t)b * Hz;
    float s0 = 0.f, s1 = 0.f, s2 = 0.f, s3 = 0.f;
#pragma unroll 4
    for (int k = 0; k < Hz; k += 4) {
        s0 += f[k]     * dw[(size_t)(k)     * Dz + d];
        s1 += f[k + 1] * dw[(size_t)(k + 1) * Dz + d];
        s2 += f[k + 2] * dw[(size_t)(k + 2) * Dz + d];
        s3 += f[k + 3] * dw[(size_t)(k + 3) * Dz + d];
    }
    float s = (s0 + s1) + (s2 + s3) + db[d];
    g_dense[(size_t)b * Dz + d] = fmaxf(s, 0.f);
}

// ---------------- logits = dense @ pred_w + pred_b ----------------
__global__ void logits_kernel(const float* __restrict__ pw, const float* __restrict__ pb,
                              float* __restrict__ out) {
    int tid = threadIdx.x;
    if (tid >= Bz * Cz) return;
    int b = tid >> 1;
    int cc = tid & 1;
    const float* dn = g_dense + (size_t)b * Dz;
    float s = 0.f;
#pragma unroll 4
    for (int d = 0; d < Dz; d++) s += dn[d] * pw[(size_t)d * Cz + cc];
    out[b * Cz + cc] = s + pb[cc];
}

// ---------------- launch ----------------
extern "C" void kernel_launch(void* const* d_in, const int* in_sizes, int n_in,
                              void* d_out, int out_size) {
    const int*   X      = (const int*)d_in[0];
    const int*   seqlen = (const int*)d_in[1];
    const float* emb    = (const float*)d_in[2];
    const float* Wf     = (const float*)d_in[3];   // [1536, 4096]
    const float* bias   = (const float*)d_in[4];
    const float* dw     = (const float*)d_in[5];
    const float* db     = (const float*)d_in[6];
    const float* pw     = (const float*)d_in[7];
    const float* pb     = (const float*)d_in[8];
    float* out = (float*)d_out;

    cudaFuncSetAttribute(xw_mma, cudaFuncAttributeMaxDynamicSharedMemorySize, SMEM_XW);
    cudaFuncSetAttribute(steps_persistent, cudaFuncAttributeMaxDynamicSharedMemorySize, SMEM_ST);

    init_kernel<<<(Bz * Hz + 255) / 256, 256>>>();
    prep_tr<<<dim3(G4 / 32, Ez / 32), 256>>>(Wf, Ez, 0);                   // Wx -> bf16
    prep_tr<<<dim3(G4 / 32, Hz / 32), 256>>>(Wf + (size_t)Ez * G4, Hz, 1); // Wh -> fp16
    prep_emb<<<Sz * Bz, 128>>>(X, emb);
    prep_bias<<<G4 / 256, 256>>>(bias);

    xw_mma<<<dim3(G4 / 64, Sz), 128, SMEM_XW>>>();

    steps_persistent<<<128, 512, SMEM_ST>>>(seqlen);

    dense_kernel<<<Bz, Dz>>>(dw, db);
    logits_kernel<<<1, 128>>>(pw, pb, out);
}

// round 12
// speedup vs baseline: 1.5202x; 1.1451x over previous
#include <cuda_runtime.h>
#include <cuda_bf16.h>
#include <cuda_fp16.h>
#include <stdint.h>

#define Bz 64
#define Sz 256
#define Ez 512
#define Hz 1024
#define G4 4096   // 4*Hz
#define Dz 512
#define Cz 2

// ---------------- device scratch (no cudaMalloc allowed) ----------------
__device__ __align__(128) float g_xw2[(size_t)Sz * G4 * Bz];     // [s][n'][b]
__device__ __align__(128) __half g_wth_hi[(size_t)G4 * Hz];      // Wh^T fp16 hi [n'][k]
__device__ __align__(128) __half g_wth_lo[(size_t)G4 * Hz];      // Wh^T fp16 lo
__device__ __align__(128) __half g_wxh_hi[(size_t)G4 * Ez];      // Wx^T fp16 hi [n'][k]
__device__ __align__(128) __half g_wxh_lo[(size_t)G4 * Ez];      // Wx^T fp16 lo
__device__ __align__(128) __half g_af[(size_t)Sz * Bz * Ez];     // gathered emb fp16 [m][k]
__device__ __align__(128) __half g_h[2][(size_t)Bz * Hz];        // h fp16 [b][k] ping-pong
__device__ __align__(128) float g_bias2[G4];                     // permuted bias
__device__ __align__(128) float g_c[Hz * Bz];                    // cell [c][b]
__device__ __align__(128) float g_final[(size_t)Bz * Hz];        // [b][h]
__device__ __align__(128) float g_dense[Bz * Dz];
__device__ __align__(128) int g_leaf[8];                         // tree barrier leaves
__device__ int g_root;                                           // tree barrier root
__device__ int g_flag;                                           // release flag

// ================= PTX helpers (non-'a' features only) =================
__device__ __forceinline__ uint32_t smem_u32(const void* p) {
    uint32_t a;
    asm("{ .reg .u64 t; cvta.to.shared.u64 t, %1; cvt.u32.u64 %0, t; }" : "=r"(a) : "l"(p));
    return a;
}
#define CP16(dst, src) \
    asm volatile("cp.async.cg.shared.global [%0], [%1], 16;" :: "r"((uint32_t)(dst)), "l"(src))
#define CP_COMMIT() asm volatile("cp.async.commit_group;" ::: "memory")
#define CP_WAITN(n) asm volatile("cp.async.wait_group %0;" :: "n"(n) : "memory")

#define LDSM4(r, addr) \
    asm volatile("ldmatrix.sync.aligned.m8n8.x4.shared.b16 {%0,%1,%2,%3}, [%4];" \
        : "=r"((r)[0]), "=r"((r)[1]), "=r"((r)[2]), "=r"((r)[3]) : "r"(addr))
#define LDSM2(r, addr) \
    asm volatile("ldmatrix.sync.aligned.m8n8.x2.shared.b16 {%0,%1}, [%2];" \
        : "=r"((r)[0]), "=r"((r)[1]) : "r"(addr))
#define MMAH(d, a, b) \
    asm volatile("mma.sync.aligned.m16n8k16.row.col.f32.f16.f16.f32 " \
        "{%0,%1,%2,%3},{%4,%5,%6,%7},{%8,%9},{%0,%1,%2,%3};" \
        : "+f"((d)[0]), "+f"((d)[1]), "+f"((d)[2]), "+f"((d)[3]) \
        : "r"((a)[0]), "r"((a)[1]), "r"((a)[2]), "r"((a)[3]), "r"((b)[0]), "r"((b)[1]))

__device__ __forceinline__ float sigm(float x) { return 1.f / (1.f + __expf(-x)); }
__device__ __forceinline__ float tanh_f(float x) { return 1.f - 2.f / (__expf(2.f * x) + 1.f); }

// ---------------- geometry ----------------
#define ROWB 272
#define MATB (64 * ROWB)      // 17408 — one 64x128 fp16 tile

// xw kernel (128 threads): resident Wx tile + 2-stage A
#define XB_ROWB 1040                     // 512 fp16 + 16B pad
#define XB_MAT (64 * XB_ROWB)            // 66560
#define XB_HI 0
#define XB_LO XB_MAT                     // 66560
#define XA_OFF (2 * XB_MAT)              // 133120
#define XGS_OFF XA_OFF                   // Gs [64][68] f32 = 17408 — aliases A stage 0
#define SMEM_XW (XA_OFF + 2 * MATB)      // 167936

// persistent step kernel (512 threads): W fp16 resident + 2-stage A
#define WROWB 2064                       // 1024 fp16 + 16B pad
#define WMATB (32 * WROWB)               // 66048
#define W_HI 0
#define W_LO WMATB                       // 66048
#define ASTG (2 * WMATB)                 // 132096
#define ASTGB MATB                       // 17408 per stage
#define GS_OFF ASTG                      // Gs [8][32][68] f32 = 69632 — aliases A + spare
#define HS_OFF (ASTG + 69632)            // 201728 ; HsH = 1024
#define SMEM_ST (HS_OFF + 1024)          // 202752

// ---------------- init: zero h and c, reset barrier ----------------
__global__ void init_kernel() {
    int i = blockIdx.x * blockDim.x + threadIdx.x;
    if (i == 0) { g_root = 0; g_flag = 0; }
    if (i < 8) g_leaf[i] = 0;
    if (i < Bz * Hz) {
        __half z = __float2half(0.f);
        g_h[0][i] = z; g_h[1][i] = z;
        g_c[i] = 0.f;
    }
}

// ---------------- prep: transpose+split W -> [n'=c*4+g][k] fp16 hi/lo ----------------
// sel==0: Wx (K=512) -> g_wxh;  sel==1: Wh (K=1024) -> g_wth
__global__ __launch_bounds__(256) void prep_tr(const float* __restrict__ src, int K, int sel) {
    __shared__ float tile[32][33];
    int n0 = blockIdx.x * 32, k0 = blockIdx.y * 32;
    int tx = threadIdx.x & 31, ty = threadIdx.x >> 5;   // 32 x 8
#pragma unroll
    for (int r = 0; r < 4; r++)
        tile[ty + r * 8][tx] = src[(size_t)(k0 + ty + r * 8) * G4 + n0 + tx];
    __syncthreads();
    __half* dh = sel ? g_wth_hi : g_wxh_hi;
    __half* dl = sel ? g_wth_lo : g_wxh_lo;
#pragma unroll
    for (int r = 0; r < 4; r++) {
        int n = n0 + ty + r * 8;
        int np = (n & 1023) * 4 + (n >> 10);
        float v = tile[tx][ty + r * 8];
        __half hi = __float2half_rn(v);
        dh[(size_t)np * K + k0 + tx] = hi;
        dl[(size_t)np * K + k0 + tx] = __float2half_rn(v - __half2float(hi));
    }
}

// ---------------- prep: gather emb rows -> fp16 [m][k] ----------------
__global__ void prep_emb(const int* __restrict__ X, const float* __restrict__ emb) {
    int m = blockIdx.x;                 // m = s*64+b
    int s = m >> 6, b = m & 63;
    int row = X[b * Sz + s];
    const float4* src = (const float4*)(emb + (size_t)row * Ez);
    int k4 = threadIdx.x;               // 128 threads
    float4 v = src[k4];
    __half2* dh = (__half2*)(g_af + (size_t)m * Ez);
    dh[k4 * 2]     = __floats2half2_rn(v.x, v.y);
    dh[k4 * 2 + 1] = __floats2half2_rn(v.z, v.w);
}

__global__ void prep_bias(const float* __restrict__ bias) {
    int n = blockIdx.x * blockDim.x + threadIdx.x;
    if (n < G4) g_bias2[(n & 1023) * 4 + (n >> 10)] = bias[n];
}

// ---------------- xw GEMM: g_xw2[s][n'][b] = emb_fp16 @ (Wx_hi + Wx_lo)^T + bias ----------
// grid (64 n'-blocks, 64 s-groups); CTA keeps its Wx tile resident, loops 4 s values.
// A chunk tile = 64 rows x 128 fp16 = 256 B/row = 16 segs/row; 1024 CP16s per tile.
__global__ __launch_bounds__(128, 1) void xw_mma() {
    extern __shared__ char smem[];
    const uint32_t sb = smem_u32(smem);
    const int tid = threadIdx.x, lane = tid & 31, w = tid >> 5;
    const int np0 = blockIdx.x * 64;
    const int sg = blockIdx.y * 4;
    const int mbase = (w & 1) * 32, nbase = (w >> 1) * 32;

    // resident Wx tile: 64 n' x 512 k fp16 (1024 B/row = 64 segs), hi + lo
#pragma unroll
    for (int i = 0; i < 32; i++) {
        int idx = i * 128 + tid;
        int row = idx >> 6, seg = idx & 63;
        CP16(sb + XB_HI + row * XB_ROWB + seg * 16,
             (const char*)(g_wxh_hi + (size_t)(np0 + row) * Ez) + seg * 16);
    }
#pragma unroll
    for (int i = 0; i < 32; i++) {
        int idx = i * 128 + tid;
        int row = idx >> 6, seg = idx & 63;
        CP16(sb + XB_LO + row * XB_ROWB + seg * 16,
             (const char*)(g_wxh_lo + (size_t)(np0 + row) * Ez) + seg * 16);
    }
    CP_COMMIT();

    float* Gs = (float*)(smem + XGS_OFF);          // [64 n'][68 m], aliases A stage 0

    for (int si = 0; si < 4; si++) {
        const int s = sg + si;
        const __half* Af = g_af + (size_t)s * Bz * Ez;

        // A chunk 0 -> stage 0 (row = idx>>4, seg = idx&15)
#pragma unroll
        for (int i = 0; i < 8; i++) {
            int idx = i * 128 + tid;
            int row = idx >> 4, seg = idx & 15;
            CP16(sb + XA_OFF + row * ROWB + seg * 16,
                 (const char*)(Af + (size_t)row * Ez) + seg * 16);
        }
        CP_COMMIT();

        float acc[2][4][4] = {};
#pragma unroll
        for (int c = 0; c < 4; c++) {
            CP_WAITN(0);
            __syncthreads();
            if (c < 3) {
#pragma unroll
                for (int i = 0; i < 8; i++) {
                    int idx = i * 128 + tid;
                    int row = idx >> 4, seg = idx & 15;
                    CP16(sb + XA_OFF + (uint32_t)((c + 1) & 1) * MATB + row * ROWB + seg * 16,
                         (const char*)(Af + (size_t)row * Ez + (c + 1) * 128) + seg * 16);
                }
                CP_COMMIT();
            }
            // compute chunk c from stage (c&1) + resident B
            const uint32_t abuf = sb + XA_OFF + (uint32_t)(c & 1) * MATB;
            const int arow = lane & 15;
            const int ahalf = (lane >> 4) * 16;
            const int brow = lane & 7;
            const int bhalf = ((lane >> 3) & 1) * 16;
#pragma unroll
            for (int k16 = 0; k16 < 8; k16++) {
                uint32_t ah[2][4], bh[4][2], bl[4][2];
#pragma unroll
                for (int mt = 0; mt < 2; mt++) {
                    uint32_t ao = (uint32_t)((mbase + mt * 16 + arow) * ROWB) + k16 * 32 + ahalf;
                    LDSM4(ah[mt], abuf + ao);
                }
                const uint32_t kwb = (uint32_t)(c * 256 + k16 * 32) + bhalf;
#pragma unroll
                for (int nt = 0; nt < 4; nt++) {
                    uint32_t bo = (uint32_t)((nbase + nt * 8 + brow) * XB_ROWB) + kwb;
                    LDSM2(bh[nt], sb + XB_HI + bo);
                    LDSM2(bl[nt], sb + XB_LO + bo);
                }
#pragma unroll
                for (int mt = 0; mt < 2; mt++)
#pragma unroll
                    for (int nt = 0; nt < 4; nt++) {
                        MMAH(acc[mt][nt], ah[mt], bh[nt]);
                        MMAH(acc[mt][nt], ah[mt], bl[nt]);
                    }
            }
        }
        __syncthreads();                           // all compute done; stage 0 (Gs alias) free

        // stage gates
        {
            const int r = lane >> 2, c2 = (lane & 3) * 2;
#pragma unroll
            for (int mt = 0; mt < 2; mt++)
#pragma unroll
                for (int nt = 0; nt < 4; nt++) {
                    int m = mbase + mt * 16 + r;
                    int n = nbase + nt * 8 + c2;
                    Gs[n * 68 + m]           = acc[mt][nt][0];
                    Gs[(n + 1) * 68 + m]     = acc[mt][nt][1];
                    Gs[n * 68 + m + 8]       = acc[mt][nt][2];
                    Gs[(n + 1) * 68 + m + 8] = acc[mt][nt][3];
                }
        }
        __syncthreads();

        float* outb = g_xw2 + ((size_t)s * G4 + np0) * Bz;
#pragma unroll
        for (int i = 0; i < 32; i++) {
            int e = i * 128 + tid;                 // e = n'local*64 + b
            int nl = e >> 6, b = e & 63;
            outb[e] = Gs[nl * 68 + b] + g_bias2[np0 + nl];
        }
        __syncthreads();                           // before next si reuses stage 0
    }
}

// ---------------- persistent LSTM recurrence ----------------
// 128 CTAs x 512 threads (16 warps). CTA owns 32 n' (8 h-cols). W fp16 split-2 resident.
__device__ __forceinline__ void gbar_tree(int t, int tid, int blk) {
    __syncthreads();
    if (tid == 0) {
        int grp = blk >> 4;
        int old;
        asm volatile("atom.add.acq_rel.gpu.global.s32 %0, [%1], 1;"
                     : "=r"(old) : "l"(&g_leaf[grp]) : "memory");
        if (old == 16 * t - 1) {
            int rold;
            asm volatile("atom.add.acq_rel.gpu.global.s32 %0, [%1], 1;"
                         : "=r"(rold) : "l"(&g_root) : "memory");
            if (rold == 8 * t - 1) {
                asm volatile("st.release.gpu.global.s32 [%0], %1;"
                             :: "l"(&g_flag), "r"(t) : "memory");
            }
        }
        int f;
        do {
            asm volatile("ld.acquire.gpu.global.s32 %0, [%1];" : "=r"(f) : "l"(&g_flag));
        } while (f < t);
    }
    __syncthreads();
}

// load one 64x128 fp16 A tile (512 threads, 2 CP16 each)
__device__ __forceinline__ void load_A(uint32_t dst, const __half* src, int tid) {
#pragma unroll
    for (int i = 0; i < 2; i++) {
        int idx = i * 512 + tid;
        int row = idx >> 4, seg = idx & 15;
        CP16(dst + row * ROWB + seg * 16,
             (const char*)(src + (size_t)row * Hz) + seg * 16);
    }
}

__global__ __launch_bounds__(512, 1) void steps_persistent(const int* __restrict__ seqlen) {
    extern __shared__ char smem[];
    const uint32_t sb = smem_u32(smem);
    const int tid = threadIdx.x, lane = tid & 31, w = tid >> 5;
    const int blk = blockIdx.x;
    const int np0 = blk * 32, c0 = blk * 8;
    const int mh = w & 1;                // batch half (32 rows)
    const int ksub = w >> 1;             // k16 index within each 128-chunk (0..7)
    const int sl_b = __ldg(seqlen + (tid & 63));

    // ---- load W resident: 32 rows x 1024 k, fp16 hi+lo ----
#pragma unroll
    for (int i = 0; i < 8; i++) {
        int idx = i * 512 + tid;
        int row = idx >> 7, seg = idx & 127;
        CP16(sb + W_HI + row * WROWB + seg * 16,
             (const char*)(g_wth_hi + (size_t)(np0 + row) * Hz) + seg * 16);
    }
#pragma unroll
    for (int i = 0; i < 8; i++) {
        int idx = i * 512 + tid;
        int row = idx >> 7, seg = idx & 127;
        CP16(sb + W_LO + row * WROWB + seg * 16,
             (const char*)(g_wth_lo + (size_t)(np0 + row) * Hz) + seg * 16);
    }
    CP_COMMIT();

    float* Gs = (float*)(smem + GS_OFF);                     // [8 ksub][32 n'][68 m]
    __half* HsH = (__half*)(smem + HS_OFF);                  // [64][8]

    for (int t = 0; t < Sz; t++) {
        const __half* h_in = g_h[t & 1];
        __half* h_out = g_h[(t + 1) & 1];

        // epilogue operand prefetch — before barrier
        const float* xwb = g_xw2 + ((size_t)t * G4 + np0) * Bz;
        float xg[4], cold;
        {
            const int b = tid & 63;
            const int col = tid >> 6;
#pragma unroll
            for (int g = 0; g < 4; g++)
                xg[g] = __ldg(xwb + (col * 4 + g) * Bz + b);
            cold = g_c[(c0 + col) * Bz + b];
        }

        if (t > 0) gbar_tree(t, tid, blk);                   // all CTAs finished t-1

        load_A(sb + ASTG, h_in, tid);
        CP_COMMIT();

        float acc[2][4][4] = {};                             // [mt][nt][4], tile 32x32
#pragma unroll
        for (int c = 0; c < 8; c++) {
            CP_WAITN(0);
            __syncthreads();
            if (c < 7) {
                load_A(sb + ASTG + (uint32_t)((c + 1) & 1) * ASTGB,
                       h_in + (c + 1) * 128, tid);
                CP_COMMIT();
            }
            // compute: this warp covers k16 = ksub of chunk c
            {
                const uint32_t abuf = sb + ASTG + (uint32_t)(c & 1) * ASTGB;
                const int arow = lane & 15;
                const int ahalf = (lane >> 4) * 16;
                const int brow = lane & 7;
                const int bhalf = ((lane >> 3) & 1) * 16;
                uint32_t ah[2][4], bh[4][2], bl[4][2];
#pragma unroll
                for (int mt = 0; mt < 2; mt++) {
                    uint32_t ao = (uint32_t)((mh * 32 + mt * 16 + arow) * ROWB)
                                  + ksub * 32 + ahalf;
                    LDSM4(ah[mt], abuf + ao);
                }
                const uint32_t kwb = (uint32_t)(c * 128 + ksub * 16) * 2 + bhalf;
#pragma unroll
                for (int nt = 0; nt < 4; nt++) {
                    uint32_t bo = (uint32_t)((nt * 8 + brow) * WROWB) + kwb;
                    LDSM2(bh[nt], sb + W_HI + bo);
                    LDSM2(bl[nt], sb + W_LO + bo);
                }
#pragma unroll
                for (int mt = 0; mt < 2; mt++)
#pragma unroll
                    for (int nt = 0; nt < 4; nt++) {
                        MMAH(acc[mt][nt], ah[mt], bh[nt]);
                        MMAH(acc[mt][nt], ah[mt], bl[nt]);
                    }
            }
        }
        __syncthreads();                                     // last chunk consumed by all

        // write partials to private strip (Gs aliases A stages, dead now)
        {
            float* strip = Gs + ksub * (32 * 68);
            const int r = lane >> 2, c2 = (lane & 3) * 2;
#pragma unroll
            for (int mt = 0; mt < 2; mt++)
#pragma unroll
                for (int nt = 0; nt < 4; nt++) {
                    int m = mh * 32 + mt * 16 + r;
                    int n = nt * 8 + c2;
                    strip[n * 68 + m]           = acc[mt][nt][0];
                    strip[(n + 1) * 68 + m]     = acc[mt][nt][1];
                    strip[n * 68 + m + 8]       = acc[mt][nt][2];
                    strip[(n + 1) * 68 + m + 8] = acc[mt][nt][3];
                }
        }
        __syncthreads();

        // pointwise LSTM: sum 8 ksub strips + xw; one (col,b) per thread
        {
            const int col = tid >> 6, b = tid & 63;
            const bool is_last = (t == sl_b - 1);
            float gg[4];
#pragma unroll
            for (int g = 0; g < 4; g++) {
                int off = (col * 4 + g) * 68 + b;
                float s0 = Gs[off]            + Gs[off + 2176];
                float s1 = Gs[off + 2 * 2176] + Gs[off + 3 * 2176];
                float s2 = Gs[off + 4 * 2176] + Gs[off + 5 * 2176];
                float s3 = Gs[off + 6 * 2176] + Gs[off + 7 * 2176];
                gg[g] = ((s0 + s1) + (s2 + s3)) + xg[g];
            }
            float cn = cold * sigm(gg[2] + 1.0f) + sigm(gg[0]) * tanh_f(gg[1]);
            float hn = tanh_f(cn) * sigm(gg[3]);
            g_c[(c0 + col) * Bz + b] = cn;
            HsH[b * 8 + col] = __float2half_rn(hn);
            if (is_last) g_final[(size_t)b * Hz + c0 + col] = hn;
        }
        __syncthreads();

        // coalesced 16B h writes (8 fp16 per batch row)
        if (tid < 64) {
            *(uint4*)(h_out + (size_t)tid * Hz + c0) = *(uint4*)(HsH + tid * 8);
        }
    }
}

// ---------------- dense = relu(final @ dense_w + dense_b) ----------------
__global__ void dense_kernel(const float* __restrict__ dw, const float* __restrict__ db) {
    int b = blockIdx.x;
    int d = threadIdx.x;    // 512 threads
    const float* f = g_final + (size_t)b * Hz;
    float s0 = 0.f, s1 = 0.f, s2 = 0.f, s3 = 0.f;
#pragma unroll 4
    for (int k = 0; k < Hz; k += 4) {
        s0 += f[k]     * dw[(size_t)(k)     * Dz + d];
        s1 += f[k + 1] * dw[(size_t)(k + 1) * Dz + d];
        s2 += f[k + 2] * dw[(size_t)(k + 2) * Dz + d];
        s3 += f[k + 3] * dw[(size_t)(k + 3) * Dz + d];
    }
    float s = (s0 + s1) + (s2 + s3) + db[d];
    g_dense[(size_t)b * Dz + d] = fmaxf(s, 0.f);
}

// ---------------- logits = dense @ pred_w + pred_b ----------------
__global__ void logits_kernel(const float* __restrict__ pw, const float* __restrict__ pb,
                              float* __restrict__ out) {
    int tid = threadIdx.x;
    if (tid >= Bz * Cz) return;
    int b = tid >> 1;
    int cc = tid & 1;
    const float* dn = g_dense + (size_t)b * Dz;
    float s = 0.f;
#pragma unroll 4
    for (int d = 0; d < Dz; d++) s += dn[d] * pw[(size_t)d * Cz + cc];
    out[b * Cz + cc] = s + pb[cc];
}

// ---------------- launch ----------------
extern "C" void kernel_launch(void* const* d_in, const int* in_sizes, int n_in,
                              void* d_out, int out_size) {
    const int*   X      = (const int*)d_in[0];
    const int*   seqlen = (const int*)d_in[1];
    const float* emb    = (const float*)d_in[2];
    const float* Wf     = (const float*)d_in[3];   // [1536, 4096]
    const float* bias   = (const float*)d_in[4];
    const float* dw     = (const float*)d_in[5];
    const float* db     = (const float*)d_in[6];
    const float* pw     = (const float*)d_in[7];
    const float* pb     = (const float*)d_in[8];
    float* out = (float*)d_out;

    cudaFuncSetAttribute(xw_mma, cudaFuncAttributeMaxDynamicSharedMemorySize, SMEM_XW);
    cudaFuncSetAttribute(steps_persistent, cudaFuncAttributeMaxDynamicSharedMemorySize, SMEM_ST);

    init_kernel<<<(Bz * Hz + 255) / 256, 256>>>();
    prep_tr<<<dim3(G4 / 32, Ez / 32), 256>>>(Wf, Ez, 0);                   // Wx -> fp16 hi/lo
    prep_tr<<<dim3(G4 / 32, Hz / 32), 256>>>(Wf + (size_t)Ez * G4, Hz, 1); // Wh -> fp16 hi/lo
    prep_emb<<<Sz * Bz, 128>>>(X, emb);
    prep_bias<<<G4 / 256, 256>>>(bias);

    xw_mma<<<dim3(G4 / 64, Sz / 4), 128, SMEM_XW>>>();

    steps_persistent<<<128, 512, SMEM_ST>>>(seqlen);

    dense_kernel<<<Bz, Dz>>>(dw, db);
    logits_kernel<<<1, 128>>>(pw, pb, out);
}

// round 13
// speedup vs baseline: 1.6275x; 1.0706x over previous
#include <cuda_runtime.h>
#include <cuda_bf16.h>
#include <cuda_fp16.h>
#include <stdint.h>

#define Bz 64
#define Sz 256
#define Ez 512
#define Hz 1024
#define G4 4096   // 4*Hz
#define Dz 512
#define Cz 2

// ---------------- device scratch (no cudaMalloc allowed) ----------------
__device__ __align__(128) float g_xw2[(size_t)Sz * G4 * Bz];     // [s][n'][b]
__device__ __align__(128) __half g_wth[(size_t)G4 * Hz];         // Wh^T fp16 [n'][k]
__device__ __align__(128) __half g_wxh[(size_t)G4 * Ez];         // Wx^T fp16 [n'][k]
__device__ __align__(128) __half g_af[(size_t)Sz * Bz * Ez];     // gathered emb fp16 [m][k]
__device__ __align__(128) __half g_h[2][(size_t)Bz * Hz];        // h fp16 [b][k] ping-pong
__device__ __align__(128) float g_bias2[G4];                     // permuted bias
__device__ __align__(128) float g_c[Hz * Bz];                    // cell [c][b]
__device__ __align__(128) float g_final[(size_t)Bz * Hz];        // [b][h]
__device__ __align__(128) float g_dense[Bz * Dz];
__device__ __align__(128) int g_leaf[8];                         // tree barrier leaves
__device__ int g_root;                                           // tree barrier root
__device__ int g_flag;                                           // release flag

// ================= PTX helpers (non-'a' features only) =================
__device__ __forceinline__ uint32_t smem_u32(const void* p) {
    uint32_t a;
    asm("{ .reg .u64 t; cvta.to.shared.u64 t, %1; cvt.u32.u64 %0, t; }" : "=r"(a) : "l"(p));
    return a;
}
#define CP16(dst, src) \
    asm volatile("cp.async.cg.shared.global [%0], [%1], 16;" :: "r"((uint32_t)(dst)), "l"(src))
#define CP_COMMIT() asm volatile("cp.async.commit_group;" ::: "memory")
#define CP_WAITN(n) asm volatile("cp.async.wait_group %0;" :: "n"(n) : "memory")

#define LDSM4(r, addr) \
    asm volatile("ldmatrix.sync.aligned.m8n8.x4.shared.b16 {%0,%1,%2,%3}, [%4];" \
        : "=r"((r)[0]), "=r"((r)[1]), "=r"((r)[2]), "=r"((r)[3]) : "r"(addr))
#define LDSM2(r, addr) \
    asm volatile("ldmatrix.sync.aligned.m8n8.x2.shared.b16 {%0,%1}, [%2];" \
        : "=r"((r)[0]), "=r"((r)[1]) : "r"(addr))
#define MMAH(d, a, b) \
    asm volatile("mma.sync.aligned.m16n8k16.row.col.f32.f16.f16.f32 " \
        "{%0,%1,%2,%3},{%4,%5,%6,%7},{%8,%9},{%0,%1,%2,%3};" \
        : "+f"((d)[0]), "+f"((d)[1]), "+f"((d)[2]), "+f"((d)[3]) \
        : "r"((a)[0]), "r"((a)[1]), "r"((a)[2]), "r"((a)[3]), "r"((b)[0]), "r"((b)[1]))

__device__ __forceinline__ float sigm(float x) { return 1.f / (1.f + __expf(-x)); }
__device__ __forceinline__ float tanh_f(float x) { return 1.f - 2.f / (__expf(2.f * x) + 1.f); }

// ---------------- geometry ----------------
#define ROWB 272
#define MATB (64 * ROWB)      // 17408 — one 64x128 fp16 tile

// xw kernel (128 threads): resident Wx tile (hi only) + 2-stage A
#define XB_ROWB 1040                     // 512 fp16 + 16B pad
#define XB_MAT (64 * XB_ROWB)            // 66560
#define XA_OFF XB_MAT                    // 66560
#define XGS_OFF XA_OFF                   // Gs [64][68] f32 = 17408 — aliases A stage 0
#define SMEM_XW (XA_OFF + 2 * MATB)      // 101376

// persistent step kernel (512 threads): W fp16 resident (hi only) + 2-stage A
#define WROWB 2064                       // 1024 fp16 + 16B pad
#define WMATB (32 * WROWB)               // 66048
#define ASTG WMATB                       // 66048
#define ASTGB MATB                       // 17408 per stage
#define GS_OFF ASTG                      // Gs [8][32][68] f32 = 69632 — aliases stages + spare
#define HS_OFF (ASTG + 69632)            // 135680 ; HsH = 1024
#define SMEM_ST (HS_OFF + 1024)          // 136704

// ---------------- init: zero h and c, reset barrier ----------------
__global__ void init_kernel() {
    int i = blockIdx.x * blockDim.x + threadIdx.x;
    if (i == 0) { g_root = 0; g_flag = 0; }
    if (i < 8) g_leaf[i] = 0;
    if (i < Bz * Hz) {
        __half z = __float2half(0.f);
        g_h[0][i] = z; g_h[1][i] = z;
        g_c[i] = 0.f;
    }
}

// ---------------- prep: transpose W -> [n'=c*4+g][k] fp16 ----------------
// sel==0: Wx (K=512) -> g_wxh;  sel==1: Wh (K=1024) -> g_wth
__global__ __launch_bounds__(256) void prep_tr(const float* __restrict__ src, int K, int sel) {
    __shared__ float tile[32][33];
    int n0 = blockIdx.x * 32, k0 = blockIdx.y * 32;
    int tx = threadIdx.x & 31, ty = threadIdx.x >> 5;   // 32 x 8
#pragma unroll
    for (int r = 0; r < 4; r++)
        tile[ty + r * 8][tx] = src[(size_t)(k0 + ty + r * 8) * G4 + n0 + tx];
    __syncthreads();
    __half* dh = sel ? g_wth : g_wxh;
#pragma unroll
    for (int r = 0; r < 4; r++) {
        int n = n0 + ty + r * 8;
        int np = (n & 1023) * 4 + (n >> 10);
        dh[(size_t)np * K + k0 + tx] = __float2half_rn(tile[tx][ty + r * 8]);
    }
}

// ---------------- prep: gather emb rows -> fp16 [m][k] ----------------
__global__ void prep_emb(const int* __restrict__ X, const float* __restrict__ emb) {
    int m = blockIdx.x;                 // m = s*64+b
    int s = m >> 6, b = m & 63;
    int row = X[b * Sz + s];
    const float4* src = (const float4*)(emb + (size_t)row * Ez);
    int k4 = threadIdx.x;               // 128 threads
    float4 v = src[k4];
    __half2* dh = (__half2*)(g_af + (size_t)m * Ez);
    dh[k4 * 2]     = __floats2half2_rn(v.x, v.y);
    dh[k4 * 2 + 1] = __floats2half2_rn(v.z, v.w);
}

__global__ void prep_bias(const float* __restrict__ bias) {
    int n = blockIdx.x * blockDim.x + threadIdx.x;
    if (n < G4) g_bias2[(n & 1023) * 4 + (n >> 10)] = bias[n];
}

// ---------------- xw GEMM: g_xw2[s][n'][b] = emb_fp16 @ Wx_fp16^T + bias ----------
// grid (64 n'-blocks, 64 s-groups); CTA keeps its Wx tile resident, loops 4 s values.
__global__ __launch_bounds__(128, 2) void xw_mma() {
    extern __shared__ char smem[];
    const uint32_t sb = smem_u32(smem);
    const int tid = threadIdx.x, lane = tid & 31, w = tid >> 5;
    const int np0 = blockIdx.x * 64;
    const int sg = blockIdx.y * 4;
    const int mbase = (w & 1) * 32, nbase = (w >> 1) * 32;

    // resident Wx tile: 64 n' x 512 k fp16 (1024 B/row = 64 segs)
#pragma unroll
    for (int i = 0; i < 32; i++) {
        int idx = i * 128 + tid;
        int row = idx >> 6, seg = idx & 63;
        CP16(sb + row * XB_ROWB + seg * 16,
             (const char*)(g_wxh + (size_t)(np0 + row) * Ez) + seg * 16);
    }
    CP_COMMIT();

    float* Gs = (float*)(smem + XGS_OFF);          // [64 n'][68 m], aliases A stage 0

    for (int si = 0; si < 4; si++) {
        const int s = sg + si;
        const __half* Af = g_af + (size_t)s * Bz * Ez;

        // A chunk 0 -> stage 0 (row = idx>>4, seg = idx&15)
#pragma unroll
        for (int i = 0; i < 8; i++) {
            int idx = i * 128 + tid;
            int row = idx >> 4, seg = idx & 15;
            CP16(sb + XA_OFF + row * ROWB + seg * 16,
                 (const char*)(Af + (size_t)row * Ez) + seg * 16);
        }
        CP_COMMIT();

        float acc[2][4][4] = {};
#pragma unroll
        for (int c = 0; c < 4; c++) {
            CP_WAITN(0);
            __syncthreads();
            if (c < 3) {
#pragma unroll
                for (int i = 0; i < 8; i++) {
                    int idx = i * 128 + tid;
                    int row = idx >> 4, seg = idx & 15;
                    CP16(sb + XA_OFF + (uint32_t)((c + 1) & 1) * MATB + row * ROWB + seg * 16,
                         (const char*)(Af + (size_t)row * Ez + (c + 1) * 128) + seg * 16);
                }
                CP_COMMIT();
            }
            // compute chunk c from stage (c&1) + resident B
            const uint32_t abuf = sb + XA_OFF + (uint32_t)(c & 1) * MATB;
            const int arow = lane & 15;
            const int ahalf = (lane >> 4) * 16;
            const int brow = lane & 7;
            const int bhalf = ((lane >> 3) & 1) * 16;
#pragma unroll
            for (int k16 = 0; k16 < 8; k16++) {
                uint32_t ah[2][4], bh[4][2];
#pragma unroll
                for (int mt = 0; mt < 2; mt++) {
                    uint32_t ao = (uint32_t)((mbase + mt * 16 + arow) * ROWB) + k16 * 32 + ahalf;
                    LDSM4(ah[mt], abuf + ao);
                }
                const uint32_t kwb = (uint32_t)(c * 256 + k16 * 32) + bhalf;
#pragma unroll
                for (int nt = 0; nt < 4; nt++) {
                    uint32_t bo = (uint32_t)((nbase + nt * 8 + brow) * XB_ROWB) + kwb;
                    LDSM2(bh[nt], sb + bo);
                }
#pragma unroll
                for (int mt = 0; mt < 2; mt++)
#pragma unroll
                    for (int nt = 0; nt < 4; nt++)
                        MMAH(acc[mt][nt], ah[mt], bh[nt]);
            }
        }
        __syncthreads();                           // compute done; stage 0 (Gs alias) free

        // stage gates
        {
            const int r = lane >> 2, c2 = (lane & 3) * 2;
#pragma unroll
            for (int mt = 0; mt < 2; mt++)
#pragma unroll
                for (int nt = 0; nt < 4; nt++) {
                    int m = mbase + mt * 16 + r;
                    int n = nbase + nt * 8 + c2;
                    Gs[n * 68 + m]           = acc[mt][nt][0];
                    Gs[(n + 1) * 68 + m]     = acc[mt][nt][1];
                    Gs[n * 68 + m + 8]       = acc[mt][nt][2];
                    Gs[(n + 1) * 68 + m + 8] = acc[mt][nt][3];
                }
        }
        __syncthreads();

        float* outb = g_xw2 + ((size_t)s * G4 + np0) * Bz;
#pragma unroll
        for (int i = 0; i < 32; i++) {
            int e = i * 128 + tid;                 // e = n'local*64 + b
            int nl = e >> 6, b = e & 63;
            outb[e] = Gs[nl * 68 + b] + g_bias2[np0 + nl];
        }
        __syncthreads();                           // before next si reuses stage 0
    }
}

// ---------------- persistent LSTM recurrence ----------------
// 128 CTAs x 512 threads (16 warps). CTA owns 32 n' (8 h-cols). W fp16 resident.
__device__ __forceinline__ void gbar_tree(int t, int tid, int blk) {
    __syncthreads();
    if (tid == 0) {
        int grp = blk >> 4;
        int old;
        asm volatile("atom.add.acq_rel.gpu.global.s32 %0, [%1], 1;"
                     : "=r"(old) : "l"(&g_leaf[grp]) : "memory");
        if (old == 16 * t - 1) {
            int rold;
            asm volatile("atom.add.acq_rel.gpu.global.s32 %0, [%1], 1;"
                         : "=r"(rold) : "l"(&g_root) : "memory");
            if (rold == 8 * t - 1) {
                asm volatile("st.release.gpu.global.s32 [%0], %1;"
                             :: "l"(&g_flag), "r"(t) : "memory");
            }
        }
        int f;
        do {
            asm volatile("ld.acquire.gpu.global.s32 %0, [%1];" : "=r"(f) : "l"(&g_flag));
        } while (f < t);
    }
    __syncthreads();
}

// load one 64x128 fp16 A tile (512 threads, 2 CP16 each)
__device__ __forceinline__ void load_A(uint32_t dst, const __half* src, int tid) {
#pragma unroll
    for (int i = 0; i < 2; i++) {
        int idx = i * 512 + tid;
        int row = idx >> 4, seg = idx & 15;
        CP16(dst + row * ROWB + seg * 16,
             (const char*)(src + (size_t)row * Hz) + seg * 16);
    }
}

__global__ __launch_bounds__(512, 1) void steps_persistent(const int* __restrict__ seqlen) {
    extern __shared__ char smem[];
    const uint32_t sb = smem_u32(smem);
    const int tid = threadIdx.x, lane = tid & 31, w = tid >> 5;
    const int blk = blockIdx.x;
    const int np0 = blk * 32, c0 = blk * 8;
    const int mh = w & 1;                // batch half (32 rows)
    const int ksub = w >> 1;             // k16 index within each 128-chunk (0..7)
    const int sl_b = __ldg(seqlen + (tid & 63));

    // ---- load W resident: 32 rows x 1024 k fp16 ----
#pragma unroll
    for (int i = 0; i < 8; i++) {
        int idx = i * 512 + tid;
        int row = idx >> 7, seg = idx & 127;
        CP16(sb + row * WROWB + seg * 16,
             (const char*)(g_wth + (size_t)(np0 + row) * Hz) + seg * 16);
    }
    CP_COMMIT();

    float* Gs = (float*)(smem + GS_OFF);                     // [8 ksub][32 n'][68 m]
    __half* HsH = (__half*)(smem + HS_OFF);                  // [64][8]

    for (int t = 0; t < Sz; t++) {
        const __half* h_in = g_h[t & 1];
        __half* h_out = g_h[(t + 1) & 1];

        // epilogue operand prefetch — before barrier
        const float* xwb = g_xw2 + ((size_t)t * G4 + np0) * Bz;
        float xg[4], cold;
        {
            const int b = tid & 63;
            const int col = tid >> 6;
#pragma unroll
            for (int g = 0; g < 4; g++)
                xg[g] = __ldg(xwb + (col * 4 + g) * Bz + b);
            cold = g_c[(c0 + col) * Bz + b];
        }

        if (t > 0) gbar_tree(t, tid, blk);                   // all CTAs finished t-1

        load_A(sb + ASTG, h_in, tid);
        CP_COMMIT();

        float acc[2][4][4] = {};                             // [mt][nt][4], tile 32x32
#pragma unroll
        for (int c = 0; c < 8; c++) {
            CP_WAITN(0);
            __syncthreads();
            if (c < 7) {
                load_A(sb + ASTG + (uint32_t)((c + 1) & 1) * ASTGB,
                       h_in + (c + 1) * 128, tid);
                CP_COMMIT();
            }
            // compute: this warp covers k16 = ksub of chunk c
            {
                const uint32_t abuf = sb + ASTG + (uint32_t)(c & 1) * ASTGB;
                const int arow = lane & 15;
                const int ahalf = (lane >> 4) * 16;
                const int brow = lane & 7;
                const int bhalf = ((lane >> 3) & 1) * 16;
                uint32_t ah[2][4], bh[4][2];
#pragma unroll
                for (int mt = 0; mt < 2; mt++) {
                    uint32_t ao = (uint32_t)((mh * 32 + mt * 16 + arow) * ROWB)
                                  + ksub * 32 + ahalf;
                    LDSM4(ah[mt], abuf + ao);
                }
                const uint32_t kwb = (uint32_t)(c * 128 + ksub * 16) * 2 + bhalf;
#pragma unroll
                for (int nt = 0; nt < 4; nt++) {
                    uint32_t bo = (uint32_t)((nt * 8 + brow) * WROWB) + kwb;
                    LDSM2(bh[nt], sb + bo);
                }
#pragma unroll
                for (int mt = 0; mt < 2; mt++)
#pragma unroll
                    for (int nt = 0; nt < 4; nt++)
                        MMAH(acc[mt][nt], ah[mt], bh[nt]);
            }
        }
        __syncthreads();                                     // last chunk consumed by all

        // write partials to private strip (Gs aliases A stages, dead now)
        {
            float* strip = Gs + ksub * (32 * 68);
            const int r = lane >> 2, c2 = (lane & 3) * 2;
#pragma unroll
            for (int mt = 0; mt < 2; mt++)
#pragma unroll
                for (int nt = 0; nt < 4; nt++) {
                    int m = mh * 32 + mt * 16 + r;
                    int n = nt * 8 + c2;
                    strip[n * 68 + m]           = acc[mt][nt][0];
                    strip[(n + 1) * 68 + m]     = acc[mt][nt][1];
                    strip[n * 68 + m + 8]       = acc[mt][nt][2];
                    strip[(n + 1) * 68 + m + 8] = acc[mt][nt][3];
                }
        }
        __syncthreads();

        // pointwise LSTM: sum 8 ksub strips + xw; one (col,b) per thread
        {
            const int col = tid >> 6, b = tid & 63;
            const bool is_last = (t == sl_b - 1);
            float gg[4];
#pragma unroll
            for (int g = 0; g < 4; g++) {
                int off = (col * 4 + g) * 68 + b;
                float s0 = Gs[off]            + Gs[off + 2176];
                float s1 = Gs[off + 2 * 2176] + Gs[off + 3 * 2176];
                float s2 = Gs[off + 4 * 2176] + Gs[off + 5 * 2176];
                float s3 = Gs[off + 6 * 2176] + Gs[off + 7 * 2176];
                gg[g] = ((s0 + s1) + (s2 + s3)) + xg[g];
            }
            float cn = cold * sigm(gg[2] + 1.0f) + sigm(gg[0]) * tanh_f(gg[1]);
            float hn = tanh_f(cn) * sigm(gg[3]);
            g_c[(c0 + col) * Bz + b] = cn;
            HsH[b * 8 + col] = __float2half_rn(hn);
            if (is_last) g_final[(size_t)b * Hz + c0 + col] = hn;
        }
        __syncthreads();

        // coalesced 16B h writes (8 fp16 per batch row)
        if (tid < 64) {
            *(uint4*)(h_out + (size_t)tid * Hz + c0) = *(uint4*)(HsH + tid * 8);
        }
    }
}

// ---------------- dense = relu(final @ dense_w + dense_b) ----------------
__global__ void dense_kernel(const float* __restrict__ dw, const float* __restrict__ db) {
    int b = blockIdx.x;
    int d = threadIdx.x;    // 512 threads
    const float* f = g_final + (size_t)b * Hz;
    float s0 = 0.f, s1 = 0.f, s2 = 0.f, s3 = 0.f;
#pragma unroll 4
    for (int k = 0; k < Hz; k += 4) {
        s0 += f[k]     * dw[(size_t)(k)     * Dz + d];
        s1 += f[k + 1] * dw[(size_t)(k + 1) * Dz + d];
        s2 += f[k + 2] * dw[(size_t)(k + 2) * Dz + d];
        s3 += f[k + 3] * dw[(size_t)(k + 3) * Dz + d];
    }
    float s = (s0 + s1) + (s2 + s3) + db[d];
    g_dense[(size_t)b * Dz + d] = fmaxf(s, 0.f);
}

// ---------------- logits = dense @ pred_w + pred_b ----------------
__global__ void logits_kernel(const float* __restrict__ pw, const float* __restrict__ pb,
                              float* __restrict__ out) {
    int tid = threadIdx.x;
    if (tid >= Bz * Cz) return;
    int b = tid >> 1;
    int cc = tid & 1;
    const float* dn = g_dense + (size_t)b * Dz;
    float s = 0.f;
#pragma unroll 4
    for (int d = 0; d < Dz; d++) s += dn[d] * pw[(size_t)d * Cz + cc];
    out[b * Cz + cc] = s + pb[cc];
}

// ---------------- launch ----------------
extern "C" void kernel_launch(void* const* d_in, const int* in_sizes, int n_in,
                              void* d_out, int out_size) {
    const int*   X      = (const int*)d_in[0];
    const int*   seqlen = (const int*)d_in[1];
    const float* emb    = (const float*)d_in[2];
    const float* Wf     = (const float*)d_in[3];   // [1536, 4096]
    const float* bias   = (const float*)d_in[4];
    const float* dw     = (const float*)d_in[5];
    const float* db     = (const float*)d_in[6];
    const float* pw     = (const float*)d_in[7];
    const float* pb     = (const float*)d_in[8];
    float* out = (float*)d_out;

    cudaFuncSetAttribute(xw_mma, cudaFuncAttributeMaxDynamicSharedMemorySize, SMEM_XW);
    cudaFuncSetAttribute(steps_persistent, cudaFuncAttributeMaxDynamicSharedMemorySize, SMEM_ST);

    init_kernel<<<(Bz * Hz + 255) / 256, 256>>>();
    prep_tr<<<dim3(G4 / 32, Ez / 32), 256>>>(Wf, Ez, 0);                   // Wx -> fp16
    prep_tr<<<dim3(G4 / 32, Hz / 32), 256>>>(Wf + (size_t)Ez * G4, Hz, 1); // Wh -> fp16
    prep_emb<<<Sz * Bz, 128>>>(X, emb);
    prep_bias<<<G4 / 256, 256>>>(bias);

    xw_mma<<<dim3(G4 / 64, Sz / 4), 128, SMEM_XW>>>();

    steps_persistent<<<128, 512, SMEM_ST>>>(seqlen);

    dense_kernel<<<Bz, Dz>>>(dw, db);
    logits_kernel<<<1, 128>>>(pw, pb, out);
}

// round 14
// speedup vs baseline: 1.8852x; 1.1583x over previous
#include <cuda_runtime.h>
#include <cuda_bf16.h>
#include <cuda_fp16.h>
#include <stdint.h>

#define Bz 64
#define Sz 256
#define Ez 512
#define Hz 1024
#define G4 4096   // 4*Hz
#define Dz 512
#define Cz 2

// ---------------- device scratch (no cudaMalloc allowed) ----------------
__device__ __align__(128) float g_xw2[(size_t)Sz * G4 * Bz];     // [s][n'][b]
__device__ __align__(128) __half g_wth[(size_t)G4 * Hz];         // Wh^T fp16 [n'][k]
__device__ __align__(128) __half g_wxh[(size_t)G4 * Ez];         // Wx^T fp16 [n'][k]
__device__ __align__(128) __half g_af[(size_t)Sz * Bz * Ez];     // gathered emb fp16 [m][k]
__device__ __align__(128) __half g_h[2][(size_t)Bz * Hz];        // h fp16 [b][k] ping-pong
__device__ __align__(128) float g_bias2[G4];                     // permuted bias
__device__ __align__(128) float g_c[Hz * Bz];                    // cell [c][b]
__device__ __align__(128) float g_final[(size_t)Bz * Hz];        // [b][h]
__device__ __align__(128) float g_dense[Bz * Dz];
__device__ __align__(128) int g_leaf[8];                         // tree barrier leaves
__device__ int g_root;                                           // tree barrier root
__device__ int g_flag;                                           // release flag

// ================= PTX helpers (non-'a' features only) =================
__device__ __forceinline__ uint32_t smem_u32(const void* p) {
    uint32_t a;
    asm("{ .reg .u64 t; cvta.to.shared.u64 t, %1; cvt.u32.u64 %0, t; }" : "=r"(a) : "l"(p));
    return a;
}
#define CP16(dst, src) \
    asm volatile("cp.async.cg.shared.global [%0], [%1], 16;" :: "r"((uint32_t)(dst)), "l"(src))
#define CP_COMMIT() asm volatile("cp.async.commit_group;" ::: "memory")
#define CP_WAITN(n) asm volatile("cp.async.wait_group %0;" :: "n"(n) : "memory")

#define LDSM4(r, addr) \
    asm volatile("ldmatrix.sync.aligned.m8n8.x4.shared.b16 {%0,%1,%2,%3}, [%4];" \
        : "=r"((r)[0]), "=r"((r)[1]), "=r"((r)[2]), "=r"((r)[3]) : "r"(addr))
#define LDSM2(r, addr) \
    asm volatile("ldmatrix.sync.aligned.m8n8.x2.shared.b16 {%0,%1}, [%2];" \
        : "=r"((r)[0]), "=r"((r)[1]) : "r"(addr))
#define MMAH(d, a, b) \
    asm volatile("mma.sync.aligned.m16n8k16.row.col.f32.f16.f16.f32 " \
        "{%0,%1,%2,%3},{%4,%5,%6,%7},{%8,%9},{%0,%1,%2,%3};" \
        : "+f"((d)[0]), "+f"((d)[1]), "+f"((d)[2]), "+f"((d)[3]) \
        : "r"((a)[0]), "r"((a)[1]), "r"((a)[2]), "r"((a)[3]), "r"((b)[0]), "r"((b)[1]))

__device__ __forceinline__ float sigm(float x) { return 1.f / (1.f + __expf(-x)); }
__device__ __forceinline__ float tanh_f(float x) { return 1.f - 2.f / (__expf(2.f * x) + 1.f); }

// ---------------- geometry ----------------
#define ROWB 272
#define MATB (64 * ROWB)      // 17408 — one 64x128 fp16 tile

// xw kernel (128 threads): resident Wx tile + 2-stage A
#define XB_ROWB 1040                     // 512 fp16 + 16B pad
#define XB_MAT (64 * XB_ROWB)            // 66560
#define XA_OFF XB_MAT                    // 66560
#define XGS_OFF XA_OFF                   // Gs [64][68] f32 = 17408 — aliases A stage 0
#define SMEM_XW (XA_OFF + 2 * MATB)      // 101376

// persistent step kernel (512 threads): W resident + FULL h tile (one-shot load)
#define WROWB 2064                       // 1024 fp16 + 16B pad
#define WMATB (32 * WROWB)               // 66048
#define H_OFF WMATB                      // 66048 ; h tile 64 rows x 2064B = 132096
#define HROWB 2064
#define GS_OFF H_OFF                     // Gs [8][32][68] f32 = 69632 — aliases h tile
#define HS_OFF (H_OFF + 64 * HROWB)      // 198144 ; HsH = 1024
#define SMEM_ST (HS_OFF + 1024)          // 199168

// ---------------- init: zero h and c, reset barrier ----------------
__global__ void init_kernel() {
    int i = blockIdx.x * blockDim.x + threadIdx.x;
    if (i == 0) { g_root = 0; g_flag = 0; }
    if (i < 8) g_leaf[i] = 0;
    if (i < Bz * Hz) {
        __half z = __float2half(0.f);
        g_h[0][i] = z; g_h[1][i] = z;
        g_c[i] = 0.f;
    }
}

// ---------------- prep: transpose W -> [n'=c*4+g][k] fp16 ----------------
__global__ __launch_bounds__(256) void prep_tr(const float* __restrict__ src, int K, int sel) {
    __shared__ float tile[32][33];
    int n0 = blockIdx.x * 32, k0 = blockIdx.y * 32;
    int tx = threadIdx.x & 31, ty = threadIdx.x >> 5;   // 32 x 8
#pragma unroll
    for (int r = 0; r < 4; r++)
        tile[ty + r * 8][tx] = src[(size_t)(k0 + ty + r * 8) * G4 + n0 + tx];
    __syncthreads();
    __half* dh = sel ? g_wth : g_wxh;
#pragma unroll
    for (int r = 0; r < 4; r++) {
        int n = n0 + ty + r * 8;
        int np = (n & 1023) * 4 + (n >> 10);
        dh[(size_t)np * K + k0 + tx] = __float2half_rn(tile[tx][ty + r * 8]);
    }
}

// ---------------- prep: gather emb rows -> fp16 [m][k] ----------------
__global__ void prep_emb(const int* __restrict__ X, const float* __restrict__ emb) {
    int m = blockIdx.x;                 // m = s*64+b
    int s = m >> 6, b = m & 63;
    int row = X[b * Sz + s];
    const float4* src = (const float4*)(emb + (size_t)row * Ez);
    int k4 = threadIdx.x;               // 128 threads
    float4 v = src[k4];
    __half2* dh = (__half2*)(g_af + (size_t)m * Ez);
    dh[k4 * 2]     = __floats2half2_rn(v.x, v.y);
    dh[k4 * 2 + 1] = __floats2half2_rn(v.z, v.w);
}

__global__ void prep_bias(const float* __restrict__ bias) {
    int n = blockIdx.x * blockDim.x + threadIdx.x;
    if (n < G4) g_bias2[(n & 1023) * 4 + (n >> 10)] = bias[n];
}

// ---------------- xw GEMM: g_xw2[s][n'][b] = emb_fp16 @ Wx_fp16^T + bias ----------
__global__ __launch_bounds__(128, 2) void xw_mma() {
    extern __shared__ char smem[];
    const uint32_t sb = smem_u32(smem);
    const int tid = threadIdx.x, lane = tid & 31, w = tid >> 5;
    const int np0 = blockIdx.x * 64;
    const int sg = blockIdx.y * 4;
    const int mbase = (w & 1) * 32, nbase = (w >> 1) * 32;

    // resident Wx tile: 64 n' x 512 k fp16
#pragma unroll
    for (int i = 0; i < 32; i++) {
        int idx = i * 128 + tid;
        int row = idx >> 6, seg = idx & 63;
        CP16(sb + row * XB_ROWB + seg * 16,
             (const char*)(g_wxh + (size_t)(np0 + row) * Ez) + seg * 16);
    }
    CP_COMMIT();

    float* Gs = (float*)(smem + XGS_OFF);          // [64 n'][68 m], aliases A stage 0

    for (int si = 0; si < 4; si++) {
        const int s = sg + si;
        const __half* Af = g_af + (size_t)s * Bz * Ez;

#pragma unroll
        for (int i = 0; i < 8; i++) {
            int idx = i * 128 + tid;
            int row = idx >> 4, seg = idx & 15;
            CP16(sb + XA_OFF + row * ROWB + seg * 16,
                 (const char*)(Af + (size_t)row * Ez) + seg * 16);
        }
        CP_COMMIT();

        float acc[2][4][4] = {};
#pragma unroll
        for (int c = 0; c < 4; c++) {
            CP_WAITN(0);
            __syncthreads();
            if (c < 3) {
#pragma unroll
                for (int i = 0; i < 8; i++) {
                    int idx = i * 128 + tid;
                    int row = idx >> 4, seg = idx & 15;
                    CP16(sb + XA_OFF + (uint32_t)((c + 1) & 1) * MATB + row * ROWB + seg * 16,
                         (const char*)(Af + (size_t)row * Ez + (c + 1) * 128) + seg * 16);
                }
                CP_COMMIT();
            }
            const uint32_t abuf = sb + XA_OFF + (uint32_t)(c & 1) * MATB;
            const int arow = lane & 15;
            const int ahalf = (lane >> 4) * 16;
            const int brow = lane & 7;
            const int bhalf = ((lane >> 3) & 1) * 16;
#pragma unroll
            for (int k16 = 0; k16 < 8; k16++) {
                uint32_t ah[2][4], bh[4][2];
#pragma unroll
                for (int mt = 0; mt < 2; mt++) {
                    uint32_t ao = (uint32_t)((mbase + mt * 16 + arow) * ROWB) + k16 * 32 + ahalf;
                    LDSM4(ah[mt], abuf + ao);
                }
                const uint32_t kwb = (uint32_t)(c * 256 + k16 * 32) + bhalf;
#pragma unroll
                for (int nt = 0; nt < 4; nt++) {
                    uint32_t bo = (uint32_t)((nbase + nt * 8 + brow) * XB_ROWB) + kwb;
                    LDSM2(bh[nt], sb + bo);
                }
#pragma unroll
                for (int mt = 0; mt < 2; mt++)
#pragma unroll
                    for (int nt = 0; nt < 4; nt++)
                        MMAH(acc[mt][nt], ah[mt], bh[nt]);
            }
        }
        __syncthreads();

        {
            const int r = lane >> 2, c2 = (lane & 3) * 2;
#pragma unroll
            for (int mt = 0; mt < 2; mt++)
#pragma unroll
                for (int nt = 0; nt < 4; nt++) {
                    int m = mbase + mt * 16 + r;
                    int n = nbase + nt * 8 + c2;
                    Gs[n * 68 + m]           = acc[mt][nt][0];
                    Gs[(n + 1) * 68 + m]     = acc[mt][nt][1];
                    Gs[n * 68 + m + 8]       = acc[mt][nt][2];
                    Gs[(n + 1) * 68 + m + 8] = acc[mt][nt][3];
                }
        }
        __syncthreads();

        float* outb = g_xw2 + ((size_t)s * G4 + np0) * Bz;
#pragma unroll
        for (int i = 0; i < 32; i++) {
            int e = i * 128 + tid;
            int nl = e >> 6, b = e & 63;
            outb[e] = Gs[nl * 68 + b] + g_bias2[np0 + nl];
        }
        __syncthreads();
    }
}

// ---------------- persistent LSTM recurrence ----------------
// 128 CTAs x 512 threads. CTA owns 32 n' (8 h-cols). W fp16 resident.
// One-shot full-h load per step: no chunk pipeline, minimal syncs.
__device__ __forceinline__ void gbar_tree(int t, int tid, int blk) {
    __syncthreads();
    if (tid == 0) {
        int grp = blk >> 4;
        int old;
        asm volatile("atom.add.acq_rel.gpu.global.s32 %0, [%1], 1;"
                     : "=r"(old) : "l"(&g_leaf[grp]) : "memory");
        if (old == 16 * t - 1) {
            int rold;
            asm volatile("atom.add.acq_rel.gpu.global.s32 %0, [%1], 1;"
                         : "=r"(rold) : "l"(&g_root) : "memory");
            if (rold == 8 * t - 1) {
                asm volatile("st.release.gpu.global.s32 [%0], %1;"
                             :: "l"(&g_flag), "r"(t) : "memory");
            }
        }
        int f;
        do {
            asm volatile("ld.acquire.gpu.global.s32 %0, [%1];" : "=r"(f) : "l"(&g_flag));
        } while (f < t);
    }
    __syncthreads();
}

__global__ __launch_bounds__(512, 1) void steps_persistent(const int* __restrict__ seqlen) {
    extern __shared__ char smem[];
    const uint32_t sb = smem_u32(smem);
    const int tid = threadIdx.x, lane = tid & 31, w = tid >> 5;
    const int blk = blockIdx.x;
    const int np0 = blk * 32, c0 = blk * 8;
    const int mh = w & 1;                // batch half (32 rows)
    const int ksub = w >> 1;             // k16 phase (0..7); covers kk = c*8+ksub
    const int sl_b = __ldg(seqlen + (tid & 63));

    // ---- load W resident: 32 rows x 1024 k fp16 ----
#pragma unroll
    for (int i = 0; i < 8; i++) {
        int idx = i * 512 + tid;
        int row = idx >> 7, seg = idx & 127;
        CP16(sb + row * WROWB + seg * 16,
             (const char*)(g_wth + (size_t)(np0 + row) * Hz) + seg * 16);
    }
    CP_COMMIT();

    float* Gs = (float*)(smem + GS_OFF);                     // [8 ksub][32 n'][68 m]
    __half* HsH = (__half*)(smem + HS_OFF);                  // [64][8]

    for (int t = 0; t < Sz; t++) {
        const __half* h_in = g_h[t & 1];
        __half* h_out = g_h[(t + 1) & 1];

        // epilogue operand prefetch — before barrier
        const float* xwb = g_xw2 + ((size_t)t * G4 + np0) * Bz;
        float xg[4], cold;
        {
            const int b = tid & 63;
            const int col = tid >> 6;
#pragma unroll
            for (int g = 0; g < 4; g++)
                xg[g] = __ldg(xwb + (col * 4 + g) * Bz + b);
            cold = g_c[(c0 + col) * Bz + b];
        }

        if (t > 0) gbar_tree(t, tid, blk);                   // all CTAs finished t-1

        // one-shot full h load: 64 rows x 1024 fp16 (2048 B = 128 segs per row)
#pragma unroll
        for (int i = 0; i < 16; i++) {
            int idx = i * 512 + tid;                         // 0..8191
            int row = idx >> 7, seg = idx & 127;
            CP16(sb + H_OFF + row * HROWB + seg * 16,
                 (const char*)(h_in + (size_t)row * Hz) + seg * 16);
        }
        CP_COMMIT();
        CP_WAITN(0);
        __syncthreads();

        // all 64 MMAs per warp, uninterrupted
        float acc[2][4][4] = {};                             // [mt][nt][4], tile 32x32
        {
            const int arow = lane & 15;
            const int ahalf = (lane >> 4) * 16;
            const int brow = lane & 7;
            const int bhalf = ((lane >> 3) & 1) * 16;
#pragma unroll
            for (int c = 0; c < 8; c++) {
                const int kk = c * 8 + ksub;                 // global k16 index 0..63
                uint32_t ah[2][4], bh[4][2];
#pragma unroll
                for (int mt = 0; mt < 2; mt++) {
                    uint32_t ao = (uint32_t)((mh * 32 + mt * 16 + arow) * HROWB)
                                  + kk * 32 + ahalf;
                    LDSM4(ah[mt], sb + H_OFF + ao);
                }
                const uint32_t kwb = (uint32_t)kk * 32 + bhalf;
#pragma unroll
                for (int nt = 0; nt < 4; nt++) {
                    uint32_t bo = (uint32_t)((nt * 8 + brow) * WROWB) + kwb;
                    LDSM2(bh[nt], sb + bo);
                }
#pragma unroll
                for (int mt = 0; mt < 2; mt++)
#pragma unroll
                    for (int nt = 0; nt < 4; nt++)
                        MMAH(acc[mt][nt], ah[mt], bh[nt]);
            }
        }
        __syncthreads();                                     // all h reads done

        // write partials to private strip (Gs aliases h tile, dead now)
        {
            float* strip = Gs + ksub * (32 * 68);
            const int r = lane >> 2, c2 = (lane & 3) * 2;
#pragma unroll
            for (int mt = 0; mt < 2; mt++)
#pragma unroll
                for (int nt = 0; nt < 4; nt++) {
                    int m = mh * 32 + mt * 16 + r;
                    int n = nt * 8 + c2;
                    strip[n * 68 + m]           = acc[mt][nt][0];
                    strip[(n + 1) * 68 + m]     = acc[mt][nt][1];
                    strip[n * 68 + m + 8]       = acc[mt][nt][2];
                    strip[(n + 1) * 68 + m + 8] = acc[mt][nt][3];
                }
        }
        __syncthreads();

        // pointwise LSTM: sum 8 ksub strips + xw; one (col,b) per thread
        {
            const int col = tid >> 6, b = tid & 63;
            const bool is_last = (t == sl_b - 1);
            float gg[4];
#pragma unroll
            for (int g = 0; g < 4; g++) {
                int off = (col * 4 + g) * 68 + b;
                float s0 = Gs[off]            + Gs[off + 2176];
                float s1 = Gs[off + 2 * 2176] + Gs[off + 3 * 2176];
                float s2 = Gs[off + 4 * 2176] + Gs[off + 5 * 2176];
                float s3 = Gs[off + 6 * 2176] + Gs[off + 7 * 2176];
                gg[g] = ((s0 + s1) + (s2 + s3)) + xg[g];
            }
            float cn = cold * sigm(gg[2] + 1.0f) + sigm(gg[0]) * tanh_f(gg[1]);
            float hn = tanh_f(cn) * sigm(gg[3]);
            g_c[(c0 + col) * Bz + b] = cn;
            HsH[b * 8 + col] = __float2half_rn(hn);
            if (is_last) g_final[(size_t)b * Hz + c0 + col] = hn;
        }
        __syncthreads();

        // coalesced 16B h writes (8 fp16 per batch row)
        if (tid < 64) {
            *(uint4*)(h_out + (size_t)tid * Hz + c0) = *(uint4*)(HsH + tid * 8);
        }
    }
}

// ---------------- dense = relu(final @ dense_w + dense_b) ----------------
__global__ void dense_kernel(const float* __restrict__ dw, const float* __restrict__ db) {
    int b = blockIdx.x;
    int d = threadIdx.x;    // 512 threads
    const float* f = g_final + (size_t)b * Hz;
    float s0 = 0.f, s1 = 0.f, s2 = 0.f, s3 = 0.f;
#pragma unroll 4
    for (int k = 0; k < Hz; k += 4) {
        s0 += f[k]     * dw[(size_t)(k)     * Dz + d];
        s1 += f[k + 1] * dw[(size_t)(k + 1) * Dz + d];
        s2 += f[k + 2] * dw[(size_t)(k + 2) * Dz + d];
        s3 += f[k + 3] * dw[(size_t)(k + 3) * Dz + d];
    }
    float s = (s0 + s1) + (s2 + s3) + db[d];
    g_dense[(size_t)b * Dz + d] = fmaxf(s, 0.f);
}

// ---------------- logits = dense @ pred_w + pred_b ----------------
__global__ void logits_kernel(const float* __restrict__ pw, const float* __restrict__ pb,
                              float* __restrict__ out) {
    int tid = threadIdx.x;
    if (tid >= Bz * Cz) return;
    int b = tid >> 1;
    int cc = tid & 1;
    const float* dn = g_dense + (size_t)b * Dz;
    float s = 0.f;
#pragma unroll 4
    for (int d = 0; d < Dz; d++) s += dn[d] * pw[(size_t)d * Cz + cc];
    out[b * Cz + cc] = s + pb[cc];
}

// ---------------- launch ----------------
extern "C" void kernel_launch(void* const* d_in, const int* in_sizes, int n_in,
                              void* d_out, int out_size) {
    const int*   X      = (const int*)d_in[0];
    const int*   seqlen = (const int*)d_in[1];
    const float* emb    = (const float*)d_in[2];
    const float* Wf     = (const float*)d_in[3];   // [1536, 4096]
    const float* bias   = (const float*)d_in[4];
    const float* dw     = (const float*)d_in[5];
    const float* db     = (const float*)d_in[6];
    const float* pw     = (const float*)d_in[7];
    const float* pb     = (const float*)d_in[8];
    float* out = (float*)d_out;

    cudaFuncSetAttribute(xw_mma, cudaFuncAttributeMaxDynamicSharedMemorySize, SMEM_XW);
    cudaFuncSetAttribute(steps_persistent, cudaFuncAttributeMaxDynamicSharedMemorySize, SMEM_ST);

    init_kernel<<<(Bz * Hz + 255) / 256, 256>>>();
    prep_tr<<<dim3(G4 / 32, Ez / 32), 256>>>(Wf, Ez, 0);                   // Wx -> fp16
    prep_tr<<<dim3(G4 / 32, Hz / 32), 256>>>(Wf + (size_t)Ez * G4, Hz, 1); // Wh -> fp16
    prep_emb<<<Sz * Bz, 128>>>(X, emb);
    prep_bias<<<G4 / 256, 256>>>(bias);

    xw_mma<<<dim3(G4 / 64, Sz / 4), 128, SMEM_XW>>>();

    steps_persistent<<<128, 512, SMEM_ST>>>(seqlen);

    dense_kernel<<<Bz, Dz>>>(dw, db);
    logits_kernel<<<1, 128>>>(pw, pb, out);
}

// round 15
// speedup vs baseline: 1.8907x; 1.0029x over previous
#include <cuda_runtime.h>
#include <cuda_bf16.h>
#include <cuda_fp16.h>
#include <stdint.h>

#define Bz 64
#define Sz 256
#define Ez 512
#define Hz 1024
#define G4 4096   // 4*Hz
#define Dz 512
#define Cz 2

// ---------------- device scratch (no cudaMalloc allowed) ----------------
__device__ __align__(128) float g_xw2[(size_t)Sz * G4 * Bz];     // [s][n'][b]
__device__ __align__(128) __half g_wth[(size_t)G4 * Hz];         // Wh^T fp16 [n'][k]
__device__ __align__(128) __half g_wxh[(size_t)G4 * Ez];         // Wx^T fp16 [n'][k]
__device__ __align__(128) __half g_af[(size_t)Sz * Bz * Ez];     // gathered emb fp16 [m][k]
__device__ __align__(128) __half g_h[2][(size_t)Bz * Hz];        // h fp16 [b][k] ping-pong
__device__ __align__(128) float g_bias2[G4];                     // permuted bias
__device__ __align__(128) float g_c[Hz * Bz];                    // cell [c][b]
__device__ __align__(128) float g_final[(size_t)Bz * Hz];        // [b][h]
__device__ __align__(128) float g_dense[Bz * Dz];
__device__ __align__(128) int g_leaf[8];                         // tree barrier leaves
__device__ int g_root;                                           // tree barrier root
__device__ int g_flag;                                           // release flag

// ================= PTX helpers (non-'a' features only) =================
__device__ __forceinline__ uint32_t smem_u32(const void* p) {
    uint32_t a;
    asm("{ .reg .u64 t; cvta.to.shared.u64 t, %1; cvt.u32.u64 %0, t; }" : "=r"(a) : "l"(p));
    return a;
}
#define CP16(dst, src) \
    asm volatile("cp.async.cg.shared.global [%0], [%1], 16;" :: "r"((uint32_t)(dst)), "l"(src))
#define CP_COMMIT() asm volatile("cp.async.commit_group;" ::: "memory")
#define CP_WAITN(n) asm volatile("cp.async.wait_group %0;" :: "n"(n) : "memory")

#define LDSM4(r, addr) \
    asm volatile("ldmatrix.sync.aligned.m8n8.x4.shared.b16 {%0,%1,%2,%3}, [%4];" \
        : "=r"((r)[0]), "=r"((r)[1]), "=r"((r)[2]), "=r"((r)[3]) : "r"(addr))
#define LDSM2(r, addr) \
    asm volatile("ldmatrix.sync.aligned.m8n8.x2.shared.b16 {%0,%1}, [%2];" \
        : "=r"((r)[0]), "=r"((r)[1]) : "r"(addr))
#define MMAH(d, a, b) \
    asm volatile("mma.sync.aligned.m16n8k16.row.col.f32.f16.f16.f32 " \
        "{%0,%1,%2,%3},{%4,%5,%6,%7},{%8,%9},{%0,%1,%2,%3};" \
        : "+f"((d)[0]), "+f"((d)[1]), "+f"((d)[2]), "+f"((d)[3]) \
        : "r"((a)[0]), "r"((a)[1]), "r"((a)[2]), "r"((a)[3]), "r"((b)[0]), "r"((b)[1]))

__device__ __forceinline__ float sigm(float x) { return 1.f / (1.f + __expf(-x)); }
__device__ __forceinline__ float tanh_f(float x) { return 1.f - 2.f / (__expf(2.f * x) + 1.f); }

// ---------------- geometry ----------------
#define ROWB 272
#define MATB (64 * ROWB)      // 17408 — one 64x128 fp16 tile

// xw kernel (128 threads): resident Wx tile + 2-stage A
#define XB_ROWB 1040                     // 512 fp16 + 16B pad
#define XB_MAT (64 * XB_ROWB)            // 66560
#define XA_OFF XB_MAT                    // 66560
#define XGS_OFF XA_OFF                   // Gs [64][68] f32 = 17408 — aliases A stage 0
#define SMEM_XW (XA_OFF + 2 * MATB)      // 101376

// persistent step kernel (512 threads): W resident + FULL h tile (2-group load)
#define WROWB 2064                       // 1024 fp16 + 16B pad
#define WMATB (32 * WROWB)               // 66048
#define H_OFF WMATB                      // 66048 ; h tile 64 rows x 2064B = 132096
#define HROWB 2064
#define GS_OFF H_OFF                     // Gs [8][32][68] f32 = 69632 — aliases h tile
#define HS_OFF (H_OFF + 64 * HROWB)      // 198144 ; HsH = 1024
#define SMEM_ST (HS_OFF + 1024)          // 199168

// ---------------- init: zero h and c, reset barrier ----------------
__global__ void init_kernel() {
    int i = blockIdx.x * blockDim.x + threadIdx.x;
    if (i == 0) { g_root = 0; g_flag = 0; }
    if (i < 8) g_leaf[i] = 0;
    if (i < Bz * Hz) {
        __half z = __float2half(0.f);
        g_h[0][i] = z; g_h[1][i] = z;
        g_c[i] = 0.f;
    }
}

// ---------------- prep: transpose W -> [n'=c*4+g][k] fp16 ----------------
__global__ __launch_bounds__(256) void prep_tr(const float* __restrict__ src, int K, int sel) {
    __shared__ float tile[32][33];
    int n0 = blockIdx.x * 32, k0 = blockIdx.y * 32;
    int tx = threadIdx.x & 31, ty = threadIdx.x >> 5;   // 32 x 8
#pragma unroll
    for (int r = 0; r < 4; r++)
        tile[ty + r * 8][tx] = src[(size_t)(k0 + ty + r * 8) * G4 + n0 + tx];
    __syncthreads();
    __half* dh = sel ? g_wth : g_wxh;
#pragma unroll
    for (int r = 0; r < 4; r++) {
        int n = n0 + ty + r * 8;
        int np = (n & 1023) * 4 + (n >> 10);
        dh[(size_t)np * K + k0 + tx] = __float2half_rn(tile[tx][ty + r * 8]);
    }
}

// ---------------- prep: gather emb rows -> fp16 [m][k] ----------------
__global__ void prep_emb(const int* __restrict__ X, const float* __restrict__ emb) {
    int m = blockIdx.x;                 // m = s*64+b
    int s = m >> 6, b = m & 63;
    int row = X[b * Sz + s];
    const float4* src = (const float4*)(emb + (size_t)row * Ez);
    int k4 = threadIdx.x;               // 128 threads
    float4 v = src[k4];
    __half2* dh = (__half2*)(g_af + (size_t)m * Ez);
    dh[k4 * 2]     = __floats2half2_rn(v.x, v.y);
    dh[k4 * 2 + 1] = __floats2half2_rn(v.z, v.w);
}

__global__ void prep_bias(const float* __restrict__ bias) {
    int n = blockIdx.x * blockDim.x + threadIdx.x;
    if (n < G4) g_bias2[(n & 1023) * 4 + (n >> 10)] = bias[n];
}

// ---------------- xw GEMM: g_xw2[s][n'][b] = emb_fp16 @ Wx_fp16^T + bias ----------
__global__ __launch_bounds__(128, 2) void xw_mma() {
    extern __shared__ char smem[];
    const uint32_t sb = smem_u32(smem);
    const int tid = threadIdx.x, lane = tid & 31, w = tid >> 5;
    const int np0 = blockIdx.x * 64;
    const int sg = blockIdx.y * 4;
    const int mbase = (w & 1) * 32, nbase = (w >> 1) * 32;

    // resident Wx tile: 64 n' x 512 k fp16
#pragma unroll
    for (int i = 0; i < 32; i++) {
        int idx = i * 128 + tid;
        int row = idx >> 6, seg = idx & 63;
        CP16(sb + row * XB_ROWB + seg * 16,
             (const char*)(g_wxh + (size_t)(np0 + row) * Ez) + seg * 16);
    }
    CP_COMMIT();

    float* Gs = (float*)(smem + XGS_OFF);          // [64 n'][68 m], aliases A stage 0

    for (int si = 0; si < 4; si++) {
        const int s = sg + si;
        const __half* Af = g_af + (size_t)s * Bz * Ez;

#pragma unroll
        for (int i = 0; i < 8; i++) {
            int idx = i * 128 + tid;
            int row = idx >> 4, seg = idx & 15;
            CP16(sb + XA_OFF + row * ROWB + seg * 16,
                 (const char*)(Af + (size_t)row * Ez) + seg * 16);
        }
        CP_COMMIT();

        float acc[2][4][4] = {};
#pragma unroll
        for (int c = 0; c < 4; c++) {
            CP_WAITN(0);
            __syncthreads();
            if (c < 3) {
#pragma unroll
                for (int i = 0; i < 8; i++) {
                    int idx = i * 128 + tid;
                    int row = idx >> 4, seg = idx & 15;
                    CP16(sb + XA_OFF + (uint32_t)((c + 1) & 1) * MATB + row * ROWB + seg * 16,
                         (const char*)(Af + (size_t)row * Ez + (c + 1) * 128) + seg * 16);
                }
                CP_COMMIT();
            }
            const uint32_t abuf = sb + XA_OFF + (uint32_t)(c & 1) * MATB;
            const int arow = lane & 15;
            const int ahalf = (lane >> 4) * 16;
            const int brow = lane & 7;
            const int bhalf = ((lane >> 3) & 1) * 16;
#pragma unroll
            for (int k16 = 0; k16 < 8; k16++) {
                uint32_t ah[2][4], bh[4][2];
#pragma unroll
                for (int mt = 0; mt < 2; mt++) {
                    uint32_t ao = (uint32_t)((mbase + mt * 16 + arow) * ROWB) + k16 * 32 + ahalf;
                    LDSM4(ah[mt], abuf + ao);
                }
                const uint32_t kwb = (uint32_t)(c * 256 + k16 * 32) + bhalf;
#pragma unroll
                for (int nt = 0; nt < 4; nt++) {
                    uint32_t bo = (uint32_t)((nbase + nt * 8 + brow) * XB_ROWB) + kwb;
                    LDSM2(bh[nt], sb + bo);
                }
#pragma unroll
                for (int mt = 0; mt < 2; mt++)
#pragma unroll
                    for (int nt = 0; nt < 4; nt++)
                        MMAH(acc[mt][nt], ah[mt], bh[nt]);
            }
        }
        __syncthreads();

        {
            const int r = lane >> 2, c2 = (lane & 3) * 2;
#pragma unroll
            for (int mt = 0; mt < 2; mt++)
#pragma unroll
                for (int nt = 0; nt < 4; nt++) {
                    int m = mbase + mt * 16 + r;
                    int n = nbase + nt * 8 + c2;
                    Gs[n * 68 + m]           = acc[mt][nt][0];
                    Gs[(n + 1) * 68 + m]     = acc[mt][nt][1];
                    Gs[n * 68 + m + 8]       = acc[mt][nt][2];
                    Gs[(n + 1) * 68 + m + 8] = acc[mt][nt][3];
                }
        }
        __syncthreads();

        float* outb = g_xw2 + ((size_t)s * G4 + np0) * Bz;
#pragma unroll
        for (int i = 0; i < 32; i++) {
            int e = i * 128 + tid;
            int nl = e >> 6, b = e & 63;
            outb[e] = Gs[nl * 68 + b] + g_bias2[np0 + nl];
        }
        __syncthreads();
    }
}

// ---------------- persistent LSTM recurrence ----------------
// 128 CTAs x 512 threads. CTA owns 32 n' (8 h-cols). W fp16 resident.
// h loaded in two K-halves (separate cp.async groups) so half-1 streams under
// half-0 MMAs.
__device__ __forceinline__ void gbar_tree(int t, int tid, int blk) {
    __syncthreads();
    if (tid == 0) {
        int grp = blk >> 4;
        int old;
        asm volatile("atom.add.acq_rel.gpu.global.s32 %0, [%1], 1;"
                     : "=r"(old) : "l"(&g_leaf[grp]) : "memory");
        if (old == 16 * t - 1) {
            int rold;
            asm volatile("atom.add.acq_rel.gpu.global.s32 %0, [%1], 1;"
                         : "=r"(rold) : "l"(&g_root) : "memory");
            if (rold == 8 * t - 1) {
                asm volatile("st.release.gpu.global.s32 [%0], %1;"
                             :: "l"(&g_flag), "r"(t) : "memory");
            }
        }
        int f;
        do {
            asm volatile("ld.acquire.gpu.global.s32 %0, [%1];" : "=r"(f) : "l"(&g_flag));
        } while (f < t);
    }
    __syncthreads();
}

__global__ __launch_bounds__(512, 1) void steps_persistent(const int* __restrict__ seqlen) {
    extern __shared__ char smem[];
    const uint32_t sb = smem_u32(smem);
    const int tid = threadIdx.x, lane = tid & 31, w = tid >> 5;
    const int blk = blockIdx.x;
    const int np0 = blk * 32, c0 = blk * 8;
    const int mh = w & 1;                // batch half (32 rows)
    const int ksub = w >> 1;             // k16 phase (0..7); covers kk = c*8+ksub
    const int sl_b = __ldg(seqlen + (tid & 63));

    // ---- load W resident: 32 rows x 1024 k fp16 ----
#pragma unroll
    for (int i = 0; i < 8; i++) {
        int idx = i * 512 + tid;
        int row = idx >> 7, seg = idx & 127;
        CP16(sb + row * WROWB + seg * 16,
             (const char*)(g_wth + (size_t)(np0 + row) * Hz) + seg * 16);
    }
    CP_COMMIT();

    float* Gs = (float*)(smem + GS_OFF);                     // [8 ksub][32 n'][68 m]
    __half* HsH = (__half*)(smem + HS_OFF);                  // [64][8]

    for (int t = 0; t < Sz; t++) {
        const __half* h_in = g_h[t & 1];
        __half* h_out = g_h[(t + 1) & 1];

        // epilogue operand prefetch — before barrier
        const float* xwb = g_xw2 + ((size_t)t * G4 + np0) * Bz;
        float xg[4], cold;
        {
            const int b = tid & 63;
            const int col = tid >> 6;
#pragma unroll
            for (int g = 0; g < 4; g++)
                xg[g] = __ldg(xwb + (col * 4 + g) * Bz + b);
            cold = g_c[(c0 + col) * Bz + b];
        }

        if (t > 0) gbar_tree(t, tid, blk);                   // all CTAs finished t-1

        // h load in two K-halves: group0 = segs 0..63 (k 0..511), group1 = segs 64..127
#pragma unroll
        for (int i = 0; i < 8; i++) {
            int idx = i * 512 + tid;                         // 0..4095
            int row = idx >> 6, seg = idx & 63;
            CP16(sb + H_OFF + row * HROWB + seg * 16,
                 (const char*)(h_in + (size_t)row * Hz) + seg * 16);
        }
        CP_COMMIT();
#pragma unroll
        for (int i = 0; i < 8; i++) {
            int idx = i * 512 + tid;
            int row = idx >> 6, seg = 64 + (idx & 63);
            CP16(sb + H_OFF + row * HROWB + seg * 16,
                 (const char*)(h_in + (size_t)row * Hz) + seg * 16);
        }
        CP_COMMIT();

        float acc[2][4][4] = {};                             // [mt][nt][4], tile 32x32
        const int arow = lane & 15;
        const int ahalf = (lane >> 4) * 16;
        const int brow = lane & 7;
        const int bhalf = ((lane >> 3) & 1) * 16;

        // half 0: kk < 32 (c = 0..3)
        CP_WAITN(1);
        __syncthreads();
#pragma unroll
        for (int c = 0; c < 4; c++) {
            const int kk = c * 8 + ksub;
            uint32_t ah[2][4], bh[4][2];
#pragma unroll
            for (int mt = 0; mt < 2; mt++) {
                uint32_t ao = (uint32_t)((mh * 32 + mt * 16 + arow) * HROWB)
                              + kk * 32 + ahalf;
                LDSM4(ah[mt], sb + H_OFF + ao);
            }
            const uint32_t kwb = (uint32_t)kk * 32 + bhalf;
#pragma unroll
            for (int nt = 0; nt < 4; nt++) {
                uint32_t bo = (uint32_t)((nt * 8 + brow) * WROWB) + kwb;
                LDSM2(bh[nt], sb + bo);
            }
#pragma unroll
            for (int mt = 0; mt < 2; mt++)
#pragma unroll
                for (int nt = 0; nt < 4; nt++)
                    MMAH(acc[mt][nt], ah[mt], bh[nt]);
        }

        // half 1: kk >= 32 (c = 4..7)
        CP_WAITN(0);
        __syncthreads();
#pragma unroll
        for (int c = 4; c < 8; c++) {
            const int kk = c * 8 + ksub;
            uint32_t ah[2][4], bh[4][2];
#pragma unroll
            for (int mt = 0; mt < 2; mt++) {
                uint32_t ao = (uint32_t)((mh * 32 + mt * 16 + arow) * HROWB)
                              + kk * 32 + ahalf;
                LDSM4(ah[mt], sb + H_OFF + ao);
            }
            const uint32_t kwb = (uint32_t)kk * 32 + bhalf;
#pragma unroll
            for (int nt = 0; nt < 4; nt++) {
                uint32_t bo = (uint32_t)((nt * 8 + brow) * WROWB) + kwb;
                LDSM2(bh[nt], sb + bo);
            }
#pragma unroll
            for (int mt = 0; mt < 2; mt++)
#pragma unroll
                for (int nt = 0; nt < 4; nt++)
                    MMAH(acc[mt][nt], ah[mt], bh[nt]);
        }
        __syncthreads();                                     // all h reads done

        // write partials to private strip (Gs aliases h tile, dead now)
        {
            float* strip = Gs + ksub * (32 * 68);
            const int r = lane >> 2, c2 = (lane & 3) * 2;
#pragma unroll
            for (int mt = 0; mt < 2; mt++)
#pragma unroll
                for (int nt = 0; nt < 4; nt++) {
                    int m = mh * 32 + mt * 16 + r;
                    int n = nt * 8 + c2;
                    strip[n * 68 + m]           = acc[mt][nt][0];
                    strip[(n + 1) * 68 + m]     = acc[mt][nt][1];
                    strip[n * 68 + m + 8]       = acc[mt][nt][2];
                    strip[(n + 1) * 68 + m + 8] = acc[mt][nt][3];
                }
        }
        __syncthreads();

        // pointwise LSTM: sum 8 ksub strips + xw; one (col,b) per thread
        {
            const int col = tid >> 6, b = tid & 63;
            const bool is_last = (t == sl_b - 1);
            float gg[4];
#pragma unroll
            for (int g = 0; g < 4; g++) {
                int off = (col * 4 + g) * 68 + b;
                float s0 = Gs[off]            + Gs[off + 2176];
                float s1 = Gs[off + 2 * 2176] + Gs[off + 3 * 2176];
                float s2 = Gs[off + 4 * 2176] + Gs[off + 5 * 2176];
                float s3 = Gs[off + 6 * 2176] + Gs[off + 7 * 2176];
                gg[g] = ((s0 + s1) + (s2 + s3)) + xg[g];
            }
            float cn = cold * sigm(gg[2] + 1.0f) + sigm(gg[0]) * tanh_f(gg[1]);
            float hn = tanh_f(cn) * sigm(gg[3]);
            g_c[(c0 + col) * Bz + b] = cn;
            HsH[b * 8 + col] = __float2half_rn(hn);
            if (is_last) g_final[(size_t)b * Hz + c0 + col] = hn;
        }
        __syncthreads();

        // coalesced 16B h writes (8 fp16 per batch row)
        if (tid < 64) {
            *(uint4*)(h_out + (size_t)tid * Hz + c0) = *(uint4*)(HsH + tid * 8);
        }
    }
}

// ---------------- dense = relu(final @ dense_w + dense_b) ----------------
__global__ void dense_kernel(const float* __restrict__ dw, const float* __restrict__ db) {
    int b = blockIdx.x;
    int d = threadIdx.x;    // 512 threads
    const float* f = g_final + (size_t)b * Hz;
    float s0 = 0.f, s1 = 0.f, s2 = 0.f, s3 = 0.f;
#pragma unroll 4
    for (int k = 0; k < Hz; k += 4) {
        s0 += f[k]     * dw[(size_t)(k)     * Dz + d];
        s1 += f[k + 1] * dw[(size_t)(k + 1) * Dz + d];
        s2 += f[k + 2] * dw[(size_t)(k + 2) * Dz + d];
        s3 += f[k + 3] * dw[(size_t)(k + 3) * Dz + d];
    }
    float s = (s0 + s1) + (s2 + s3) + db[d];
    g_dense[(size_t)b * Dz + d] = fmaxf(s, 0.f);
}

// ---------------- logits = dense @ pred_w + pred_b ----------------
__global__ void logits_kernel(const float* __restrict__ pw, const float* __restrict__ pb,
                              float* __restrict__ out) {
    int tid = threadIdx.x;
    if (tid >= Bz * Cz) return;
    int b = tid >> 1;
    int cc = tid & 1;
    const float* dn = g_dense + (size_t)b * Dz;
    float s = 0.f;
#pragma unroll 4
    for (int d = 0; d < Dz; d++) s += dn[d] * pw[(size_t)d * Cz + cc];
    out[b * Cz + cc] = s + pb[cc];
}

// ---------------- launch ----------------
extern "C" void kernel_launch(void* const* d_in, const int* in_sizes, int n_in,
                              void* d_out, int out_size) {
    const int*   X      = (const int*)d_in[0];
    const int*   seqlen = (const int*)d_in[1];
    const float* emb    = (const float*)d_in[2];
    const float* Wf     = (const float*)d_in[3];   // [1536, 4096]
    const float* bias   = (const float*)d_in[4];
    const float* dw     = (const float*)d_in[5];
    const float* db     = (const float*)d_in[6];
    const float* pw     = (const float*)d_in[7];
    const float* pb     = (const float*)d_in[8];
    float* out = (float*)d_out;

    cudaFuncSetAttribute(xw_mma, cudaFuncAttributeMaxDynamicSharedMemorySize, SMEM_XW);
    cudaFuncSetAttribute(steps_persistent, cudaFuncAttributeMaxDynamicSharedMemorySize, SMEM_ST);

    init_kernel<<<(Bz * Hz + 255) / 256, 256>>>();
    prep_tr<<<dim3(G4 / 32, Ez / 32), 256>>>(Wf, Ez, 0);                   // Wx -> fp16
    prep_tr<<<dim3(G4 / 32, Hz / 32), 256>>>(Wf + (size_t)Ez * G4, Hz, 1); // Wh -> fp16
    prep_emb<<<Sz * Bz, 128>>>(X, emb);
    prep_bias<<<G4 / 256, 256>>>(bias);

    xw_mma<<<dim3(G4 / 64, Sz / 4), 128, SMEM_XW>>>();

    steps_persistent<<<128, 512, SMEM_ST>>>(seqlen);

    dense_kernel<<<Bz, Dz>>>(dw, db);
    logits_kernel<<<1, 128>>>(pw, pb, out);
}

// round 16
// speedup vs baseline: 2.0522x; 1.0854x over previous
#include <cuda_runtime.h>
#include <cuda_bf16.h>
#include <cuda_fp16.h>
#include <stdint.h>

#define Bz 64
#define Sz 256
#define Ez 512
#define Hz 1024
#define G4 4096   // 4*Hz
#define Dz 512
#define Cz 2

// ---------------- device scratch (no cudaMalloc allowed) ----------------
__device__ __align__(128) float g_xw2[(size_t)Sz * G4 * Bz];     // [s][n'][b-sorted]
__device__ __align__(128) __half g_wth[(size_t)G4 * Hz];         // Wh^T fp16 [n'][k]
__device__ __align__(128) __half g_wxh[(size_t)G4 * Ez];         // Wx^T fp16 [n'][k]
__device__ __align__(128) __half g_af[(size_t)Sz * Bz * Ez];     // gathered emb fp16 [m][k] (sorted rows)
__device__ __align__(128) __half g_h[2][(size_t)Bz * Hz];        // h fp16 [b-sorted][k] ping-pong
__device__ __align__(128) float g_bias2[G4];                     // permuted bias
__device__ __align__(128) float g_c[Hz * Bz];                    // cell [c][b-sorted]
__device__ __align__(128) float g_final[(size_t)Bz * Hz];        // [b-ORIGINAL][h]
__device__ __align__(128) float g_dense[Bz * Dz];
__device__ __align__(128) int g_leaf[8];                         // tree barrier leaves
__device__ int g_root;                                           // tree barrier root
__device__ int g_flag;                                           // release flag
__device__ __align__(128) int g_perm[Bz];                        // sorted pos -> original b
__device__ __align__(128) int g_slsort[Bz];                      // seqlen sorted descending
__device__ __align__(128) int g_active[Sz];                      // active(t) = #{b: sl_b > t}
__device__ int g_tmax;

// ================= PTX helpers (non-'a' features only) =================
__device__ __forceinline__ uint32_t smem_u32(const void* p) {
    uint32_t a;
    asm("{ .reg .u64 t; cvta.to.shared.u64 t, %1; cvt.u32.u64 %0, t; }" : "=r"(a) : "l"(p));
    return a;
}
#define CP16(dst, src) \
    asm volatile("cp.async.cg.shared.global [%0], [%1], 16;" :: "r"((uint32_t)(dst)), "l"(src))
#define CP_COMMIT() asm volatile("cp.async.commit_group;" ::: "memory")
#define CP_WAITN(n) asm volatile("cp.async.wait_group %0;" :: "n"(n) : "memory")

#define LDSM4(r, addr) \
    asm volatile("ldmatrix.sync.aligned.m8n8.x4.shared.b16 {%0,%1,%2,%3}, [%4];" \
        : "=r"((r)[0]), "=r"((r)[1]), "=r"((r)[2]), "=r"((r)[3]) : "r"(addr))
#define LDSM2(r, addr) \
    asm volatile("ldmatrix.sync.aligned.m8n8.x2.shared.b16 {%0,%1}, [%2];" \
        : "=r"((r)[0]), "=r"((r)[1]) : "r"(addr))
#define MMAH(d, a, b) \
    asm volatile("mma.sync.aligned.m16n8k16.row.col.f32.f16.f16.f32 " \
        "{%0,%1,%2,%3},{%4,%5,%6,%7},{%8,%9},{%0,%1,%2,%3};" \
        : "+f"((d)[0]), "+f"((d)[1]), "+f"((d)[2]), "+f"((d)[3]) \
        : "r"((a)[0]), "r"((a)[1]), "r"((a)[2]), "r"((a)[3]), "r"((b)[0]), "r"((b)[1]))

__device__ __forceinline__ float sigm(float x) { return 1.f / (1.f + __expf(-x)); }
__device__ __forceinline__ float tanh_f(float x) { return 1.f - 2.f / (__expf(2.f * x) + 1.f); }

// ---------------- geometry ----------------
#define ROWB 272
#define MATB (64 * ROWB)      // 17408 — one 64x128 fp16 tile

// xw kernel (128 threads): resident Wx tile + 2-stage A
#define XB_ROWB 1040                     // 512 fp16 + 16B pad
#define XB_MAT (64 * XB_ROWB)            // 66560
#define XA_OFF XB_MAT                    // 66560
#define XGS_OFF XA_OFF                   // Gs [64][68] f32 = 17408 — aliases A stage 0
#define SMEM_XW (XA_OFF + 2 * MATB)      // 101376

// persistent step kernel (512 threads): W resident + FULL h tile
#define WROWB 2064                       // 1024 fp16 + 16B pad
#define WMATB (32 * WROWB)               // 66048
#define H_OFF WMATB                      // 66048 ; h tile 64 rows x 2064B = 132096
#define HROWB 2064
#define GS_OFF H_OFF                     // Gs [8][32][68] f32 = 69632 — aliases h tile
#define HS_OFF (H_OFF + 64 * HROWB)      // 198144 ; HsH = 1024
#define SMEM_ST (HS_OFF + 1024)          // 199168

// ---------------- init: zero h and c, reset barrier ----------------
__global__ void init_kernel() {
    int i = blockIdx.x * blockDim.x + threadIdx.x;
    if (i == 0) { g_root = 0; g_flag = 0; }
    if (i < 8) g_leaf[i] = 0;
    if (i < Bz * Hz) {
        __half z = __float2half(0.f);
        g_h[0][i] = z; g_h[1][i] = z;
        g_c[i] = 0.f;
    }
}

// ---------------- prep: sort batch by seqlen desc, active counts, tmax --------
__global__ void prep_sort(const int* __restrict__ seqlen) {
    __shared__ int sl[Bz];
    int i = threadIdx.x;          // 64 threads
    sl[i] = seqlen[i];
    __syncthreads();
    int mysl = sl[i];
    int rank = 0;
#pragma unroll
    for (int j = 0; j < Bz; j++) {
        int o = sl[j];
        if (o > mysl || (o == mysl && j < i)) rank++;
    }
    g_perm[rank] = i;
    g_slsort[rank] = mysl;
    for (int t = i; t < Sz; t += Bz) {
        int cnt = 0;
#pragma unroll
        for (int j = 0; j < Bz; j++) cnt += (sl[j] > t) ? 1 : 0;
        g_active[t] = cnt;
    }
    if (i == 0) {
        int mx = 0;
#pragma unroll
        for (int j = 0; j < Bz; j++) mx = max(mx, sl[j]);
        g_tmax = mx;
    }
}

// ---------------- prep: transpose W -> [n'=c*4+g][k] fp16 ----------------
__global__ __launch_bounds__(256) void prep_tr(const float* __restrict__ src, int K, int sel) {
    __shared__ float tile[32][33];
    int n0 = blockIdx.x * 32, k0 = blockIdx.y * 32;
    int tx = threadIdx.x & 31, ty = threadIdx.x >> 5;   // 32 x 8
#pragma unroll
    for (int r = 0; r < 4; r++)
        tile[ty + r * 8][tx] = src[(size_t)(k0 + ty + r * 8) * G4 + n0 + tx];
    __syncthreads();
    __half* dh = sel ? g_wth : g_wxh;
#pragma unroll
    for (int r = 0; r < 4; r++) {
        int n = n0 + ty + r * 8;
        int np = (n & 1023) * 4 + (n >> 10);
        dh[(size_t)np * K + k0 + tx] = __float2half_rn(tile[tx][ty + r * 8]);
    }
}

// ---------------- prep: gather emb rows (sorted batch order) -> fp16 [m][k] ----
__global__ void prep_emb(const int* __restrict__ X, const float* __restrict__ emb) {
    int m = blockIdx.x;                 // m = s*64 + r (r = sorted position)
    int s = m >> 6, r = m & 63;
    int b = g_perm[r];
    int row = X[b * Sz + s];
    const float4* src = (const float4*)(emb + (size_t)row * Ez);
    int k4 = threadIdx.x;               // 128 threads
    float4 v = src[k4];
    __half2* dh = (__half2*)(g_af + (size_t)m * Ez);
    dh[k4 * 2]     = __floats2half2_rn(v.x, v.y);
    dh[k4 * 2 + 1] = __floats2half2_rn(v.z, v.w);
}

__global__ void prep_bias(const float* __restrict__ bias) {
    int n = blockIdx.x * blockDim.x + threadIdx.x;
    if (n < G4) g_bias2[(n & 1023) * 4 + (n >> 10)] = bias[n];
}

// ---------------- xw GEMM with active-row masking ----------
__global__ __launch_bounds__(128, 2) void xw_mma() {
    extern __shared__ char smem[];
    const uint32_t sb = smem_u32(smem);
    const int tid = threadIdx.x, lane = tid & 31, w = tid >> 5;
    const int np0 = blockIdx.x * 64;
    const int sg = blockIdx.y * 4;
    const int mbase = (w & 1) * 32, nbase = (w >> 1) * 32;

    // resident Wx tile: 64 n' x 512 k fp16
#pragma unroll
    for (int i = 0; i < 32; i++) {
        int idx = i * 128 + tid;
        int row = idx >> 6, seg = idx & 63;
        CP16(sb + row * XB_ROWB + seg * 16,
             (const char*)(g_wxh + (size_t)(np0 + row) * Ez) + seg * 16);
    }
    CP_COMMIT();

    float* Gs = (float*)(smem + XGS_OFF);          // [64 n'][68 m], aliases A stage 0

    for (int si = 0; si < 4; si++) {
        const int s = sg + si;
        const int act = g_active[s];
        if (act == 0) continue;                    // uniform per CTA
        const bool m0 = (mbase < act);
        const bool m1 = (mbase + 16 < act);
        const __half* Af = g_af + (size_t)s * Bz * Ez;

#pragma unroll
        for (int i = 0; i < 8; i++) {
            int idx = i * 128 + tid;
            int row = idx >> 4, seg = idx & 15;
            CP16(sb + XA_OFF + row * ROWB + seg * 16,
                 (const char*)(Af + (size_t)row * Ez) + seg * 16);
        }
        CP_COMMIT();

        float acc[2][4][4] = {};
#pragma unroll
        for (int c = 0; c < 4; c++) {
            CP_WAITN(0);
            __syncthreads();
            if (c < 3) {
#pragma unroll
                for (int i = 0; i < 8; i++) {
                    int idx = i * 128 + tid;
                    int row = idx >> 4, seg = idx & 15;
                    CP16(sb + XA_OFF + (uint32_t)((c + 1) & 1) * MATB + row * ROWB + seg * 16,
                         (const char*)(Af + (size_t)row * Ez + (c + 1) * 128) + seg * 16);
                }
                CP_COMMIT();
            }
            if (m0) {
                const uint32_t abuf = sb + XA_OFF + (uint32_t)(c & 1) * MATB;
                const int arow = lane & 15;
                const int ahalf = (lane >> 4) * 16;
                const int brow = lane & 7;
                const int bhalf = ((lane >> 3) & 1) * 16;
#pragma unroll
                for (int k16 = 0; k16 < 8; k16++) {
                    uint32_t ah[2][4], bh[4][2];
                    uint32_t ao0 = (uint32_t)((mbase + arow) * ROWB) + k16 * 32 + ahalf;
                    LDSM4(ah[0], abuf + ao0);
                    if (m1) LDSM4(ah[1], abuf + ao0 + 16 * ROWB);
                    const uint32_t kwb = (uint32_t)(c * 256 + k16 * 32) + bhalf;
#pragma unroll
                    for (int nt = 0; nt < 4; nt++) {
                        uint32_t bo = (uint32_t)((nbase + nt * 8 + brow) * XB_ROWB) + kwb;
                        LDSM2(bh[nt], sb + bo);
                    }
#pragma unroll
                    for (int nt = 0; nt < 4; nt++) MMAH(acc[0][nt], ah[0], bh[nt]);
                    if (m1) {
#pragma unroll
                        for (int nt = 0; nt < 4; nt++) MMAH(acc[1][nt], ah[1], bh[nt]);
                    }
                }
            }
        }
        __syncthreads();

        {
            const int r = lane >> 2, c2 = (lane & 3) * 2;
#pragma unroll
            for (int mt = 0; mt < 2; mt++)
#pragma unroll
                for (int nt = 0; nt < 4; nt++) {
                    int m = mbase + mt * 16 + r;
                    int n = nbase + nt * 8 + c2;
                    Gs[n * 68 + m]           = acc[mt][nt][0];
                    Gs[(n + 1) * 68 + m]     = acc[mt][nt][1];
                    Gs[n * 68 + m + 8]       = acc[mt][nt][2];
                    Gs[(n + 1) * 68 + m + 8] = acc[mt][nt][3];
                }
        }
        __syncthreads();

        float* outb = g_xw2 + ((size_t)s * G4 + np0) * Bz;
#pragma unroll
        for (int i = 0; i < 32; i++) {
            int e = i * 128 + tid;
            int nl = e >> 6, b = e & 63;
            outb[e] = Gs[nl * 68 + b] + g_bias2[np0 + nl];
        }
        __syncthreads();
    }
}

// ---------------- persistent LSTM recurrence with active-row masking ----------
__device__ __forceinline__ void gbar_tree(int t, int tid, int blk) {
    __syncthreads();
    if (tid == 0) {
        int grp = blk >> 4;
        int old;
        asm volatile("atom.add.acq_rel.gpu.global.s32 %0, [%1], 1;"
                     : "=r"(old) : "l"(&g_leaf[grp]) : "memory");
        if (old == 16 * t - 1) {
            int rold;
            asm volatile("atom.add.acq_rel.gpu.global.s32 %0, [%1], 1;"
                         : "=r"(rold) : "l"(&g_root) : "memory");
            if (rold == 8 * t - 1) {
                asm volatile("st.release.gpu.global.s32 [%0], %1;"
                             :: "l"(&g_flag), "r"(t) : "memory");
            }
        }
        int f;
        do {
            asm volatile("ld.acquire.gpu.global.s32 %0, [%1];" : "=r"(f) : "l"(&g_flag));
        } while (f < t);
    }
    __syncthreads();
}

__global__ __launch_bounds__(512, 1) void steps_persistent() {
    extern __shared__ char smem[];
    const uint32_t sb = smem_u32(smem);
    const int tid = threadIdx.x, lane = tid & 31, w = tid >> 5;
    const int blk = blockIdx.x;
    const int np0 = blk * 32, c0 = blk * 8;
    const int mh = w & 1;                // batch half (32 rows)
    const int ksub = w >> 1;             // k16 phase (0..7); covers kk = c*8+ksub
    const int bidx = tid & 63;
    const int sl_b = g_slsort[bidx];     // seqlen for sorted row bidx
    const int ob   = g_perm[bidx];       // original batch index
    const int tmax = g_tmax;

    // ---- load W resident: 32 rows x 1024 k fp16 ----
#pragma unroll
    for (int i = 0; i < 8; i++) {
        int idx = i * 512 + tid;
        int row = idx >> 7, seg = idx & 127;
        CP16(sb + row * WROWB + seg * 16,
             (const char*)(g_wth + (size_t)(np0 + row) * Hz) + seg * 16);
    }
    CP_COMMIT();

    float* Gs = (float*)(smem + GS_OFF);                     // [8 ksub][32 n'][68 m]
    __half* HsH = (__half*)(smem + HS_OFF);                  // [64][8]

    for (int t = 0; t < tmax; t++) {
        const __half* h_in = g_h[t & 1];
        __half* h_out = g_h[(t + 1) & 1];
        const int act = __ldg(&g_active[t]);                 // rows b < act are live

        // epilogue operand prefetch — before barrier
        const float* xwb = g_xw2 + ((size_t)t * G4 + np0) * Bz;
        float xg[4], cold;
        {
            const int col = tid >> 6;
#pragma unroll
            for (int g = 0; g < 4; g++)
                xg[g] = __ldg(xwb + (col * 4 + g) * Bz + bidx);
            cold = g_c[(c0 + col) * Bz + bidx];
        }

        if (t > 0) gbar_tree(t, tid, blk);                   // all CTAs finished t-1

        // one-shot h load for live rows only
#pragma unroll
        for (int i = 0; i < 16; i++) {
            int idx = i * 512 + tid;                         // 0..8191
            int row = idx >> 7, seg = idx & 127;
            if (row < act)
                CP16(sb + H_OFF + row * HROWB + seg * 16,
                     (const char*)(h_in + (size_t)row * Hz) + seg * 16);
        }
        CP_COMMIT();
        CP_WAITN(0);
        __syncthreads();

        float acc[2][4][4] = {};                             // [mt][nt][4], tile 32x32
        const bool m0 = (mh * 32) < act;
        const bool m1 = (mh * 32 + 16) < act;
        if (m0) {
            const int arow = lane & 15;
            const int ahalf = (lane >> 4) * 16;
            const int brow = lane & 7;
            const int bhalf = ((lane >> 3) & 1) * 16;
#pragma unroll
            for (int c = 0; c < 8; c++) {
                const int kk = c * 8 + ksub;                 // global k16 index 0..63
                uint32_t ah[2][4], bh[4][2];
                uint32_t ao0 = (uint32_t)((mh * 32 + arow) * HROWB) + kk * 32 + ahalf;
                LDSM4(ah[0], sb + H_OFF + ao0);
                if (m1) LDSM4(ah[1], sb + H_OFF + ao0 + 16 * HROWB);
                const uint32_t kwb = (uint32_t)kk * 32 + bhalf;
#pragma unroll
                for (int nt = 0; nt < 4; nt++) {
                    uint32_t bo = (uint32_t)((nt * 8 + brow) * WROWB) + kwb;
                    LDSM2(bh[nt], sb + bo);
                }
#pragma unroll
                for (int nt = 0; nt < 4; nt++) MMAH(acc[0][nt], ah[0], bh[nt]);
                if (m1) {
#pragma unroll
                    for (int nt = 0; nt < 4; nt++) MMAH(acc[1][nt], ah[1], bh[nt]);
                }
            }
        }
        __syncthreads();                                     // all h reads done

        // write live partials to private strip (Gs aliases h tile, dead now)
        if (m0) {
            float* strip = Gs + ksub * (32 * 68);
            const int r = lane >> 2, c2 = (lane & 3) * 2;
#pragma unroll
            for (int mt = 0; mt < 2; mt++) {
                if (mt == 1 && !m1) break;
#pragma unroll
                for (int nt = 0; nt < 4; nt++) {
                    int m = mh * 32 + mt * 16 + r;
                    int n = nt * 8 + c2;
                    strip[n * 68 + m]           = acc[mt][nt][0];
                    strip[(n + 1) * 68 + m]     = acc[mt][nt][1];
                    strip[n * 68 + m + 8]       = acc[mt][nt][2];
                    strip[(n + 1) * 68 + m + 8] = acc[mt][nt][3];
                }
            }
        }
        __syncthreads();

        // pointwise LSTM for live rows only
        if (bidx < act) {
            const int col = tid >> 6;
            float gg[4];
#pragma unroll
            for (int g = 0; g < 4; g++) {
                int off = (col * 4 + g) * 68 + bidx;
                float s0 = Gs[off]            + Gs[off + 2176];
                float s1 = Gs[off + 2 * 2176] + Gs[off + 3 * 2176];
                float s2 = Gs[off + 4 * 2176] + Gs[off + 5 * 2176];
                float s3 = Gs[off + 6 * 2176] + Gs[off + 7 * 2176];
                gg[g] = ((s0 + s1) + (s2 + s3)) + xg[g];
            }
            float cn = cold * sigm(gg[2] + 1.0f) + sigm(gg[0]) * tanh_f(gg[1]);
            float hn = tanh_f(cn) * sigm(gg[3]);
            g_c[(c0 + col) * Bz + bidx] = cn;
            HsH[bidx * 8 + col] = __float2half_rn(hn);
            if (t == sl_b - 1) g_final[(size_t)ob * Hz + c0 + col] = hn;
        }
        __syncthreads();

        // coalesced 16B h writes for live rows
        if (tid < 64 && tid < act) {
            *(uint4*)(h_out + (size_t)tid * Hz + c0) = *(uint4*)(HsH + tid * 8);
        }
    }
}

// ---------------- dense = relu(final @ dense_w + dense_b) ----------------
__global__ void dense_kernel(const float* __restrict__ dw, const float* __restrict__ db) {
    int b = blockIdx.x;
    int d = threadIdx.x;    // 512 threads
    const float* f = g_final + (size_t)b * Hz;
    float s0 = 0.f, s1 = 0.f, s2 = 0.f, s3 = 0.f;
#pragma unroll 4
    for (int k = 0; k < Hz; k += 4) {
        s0 += f[k]     * dw[(size_t)(k)     * Dz + d];
        s1 += f[k + 1] * dw[(size_t)(k + 1) * Dz + d];
        s2 += f[k + 2] * dw[(size_t)(k + 2) * Dz + d];
        s3 += f[k + 3] * dw[(size_t)(k + 3) * Dz + d];
    }
    float s = (s0 + s1) + (s2 + s3) + db[d];
    g_dense[(size_t)b * Dz + d] = fmaxf(s, 0.f);
}

// ---------------- logits = dense @ pred_w + pred_b ----------------
__global__ void logits_kernel(const float* __restrict__ pw, const float* __restrict__ pb,
                              float* __restrict__ out) {
    int tid = threadIdx.x;
    if (tid >= Bz * Cz) return;
    int b = tid >> 1;
    int cc = tid & 1;
    const float* dn = g_dense + (size_t)b * Dz;
    float s = 0.f;
#pragma unroll 4
    for (int d = 0; d < Dz; d++) s += dn[d] * pw[(size_t)d * Cz + cc];
    out[b * Cz + cc] = s + pb[cc];
}

// ---------------- launch ----------------
extern "C" void kernel_launch(void* const* d_in, const int* in_sizes, int n_in,
                              void* d_out, int out_size) {
    const int*   X      = (const int*)d_in[0];
    const int*   seqlen = (const int*)d_in[1];
    const float* emb    = (const float*)d_in[2];
    const float* Wf     = (const float*)d_in[3];   // [1536, 4096]
    const float* bias   = (const float*)d_in[4];
    const float* dw     = (const float*)d_in[5];
    const float* db     = (const float*)d_in[6];
    const float* pw     = (const float*)d_in[7];
    const float* pb     = (const float*)d_in[8];
    float* out = (float*)d_out;

    cudaFuncSetAttribute(xw_mma, cudaFuncAttributeMaxDynamicSharedMemorySize, SMEM_XW);
    cudaFuncSetAttribute(steps_persistent, cudaFuncAttributeMaxDynamicSharedMemorySize, SMEM_ST);

    init_kernel<<<(Bz * Hz + 255) / 256, 256>>>();
    prep_sort<<<1, Bz>>>(seqlen);
    prep_tr<<<dim3(G4 / 32, Ez / 32), 256>>>(Wf, Ez, 0);                   // Wx -> fp16
    prep_tr<<<dim3(G4 / 32, Hz / 32), 256>>>(Wf + (size_t)Ez * G4, Hz, 1); // Wh -> fp16
    prep_emb<<<Sz * Bz, 128>>>(X, emb);
    prep_bias<<<G4 / 256, 256>>>(bias);

    xw_mma<<<dim3(G4 / 64, Sz / 4), 128, SMEM_XW>>>();

    steps_persistent<<<128, 512, SMEM_ST>>>();

    dense_kernel<<<Bz, Dz>>>(dw, db);
    logits_kernel<<<1, 128>>>(pw, pb, out);
}

// round 17
// speedup vs baseline: 2.6801x; 1.3060x over previous
#include <cuda_runtime.h>
#include <cuda_bf16.h>
#include <cuda_fp16.h>
#include <stdint.h>

#define Bz 64
#define Sz 256
#define Ez 512
#define Hz 1024
#define G4 4096   // 4*Hz
#define Dz 512
#define Cz 2

// ---------------- device scratch (no cudaMalloc allowed) ----------------
__device__ __align__(128) float g_xw2[(size_t)Sz * G4 * Bz];     // [s][n'][b-sorted]
__device__ __align__(128) __half g_wth[(size_t)G4 * Hz];         // Wh^T fp16 [n'][k]
__device__ __align__(128) __half g_wxh[(size_t)G4 * Ez];         // Wx^T fp16 [n'][k]
__device__ __align__(128) __half g_af[(size_t)Sz * Bz * Ez];     // gathered emb fp16 [m][k] (sorted rows)
__device__ __align__(128) __half g_h[2][(size_t)Bz * Hz];        // h fp16 [b-sorted][k] ping-pong
__device__ __align__(128) float g_bias2[G4];                     // permuted bias
__device__ __align__(128) float g_c[Hz * Bz];                    // cell [c][b-sorted]
__device__ __align__(128) float g_final[(size_t)Bz * Hz];        // [b-ORIGINAL][h]
__device__ __align__(128) float g_dense[Bz * Dz];
__device__ int g_cnt;                                            // monotonic barrier counter
__device__ __align__(128) int g_perm[Bz];                        // sorted pos -> original b
__device__ __align__(128) int g_slsort[Bz];                      // seqlen sorted descending
__device__ __align__(128) int g_active[Sz];                      // active(t) = #{b: sl_b > t}
__device__ int g_tmax;

// ================= PTX helpers (non-'a' features only) =================
__device__ __forceinline__ uint32_t smem_u32(const void* p) {
    uint32_t a;
    asm("{ .reg .u64 t; cvta.to.shared.u64 t, %1; cvt.u32.u64 %0, t; }" : "=r"(a) : "l"(p));
    return a;
}
#define CP16(dst, src) \
    asm volatile("cp.async.cg.shared.global [%0], [%1], 16;" :: "r"((uint32_t)(dst)), "l"(src))
#define CP_COMMIT() asm volatile("cp.async.commit_group;" ::: "memory")
#define CP_WAITN(n) asm volatile("cp.async.wait_group %0;" :: "n"(n) : "memory")

#define LDSM4(r, addr) \
    asm volatile("ldmatrix.sync.aligned.m8n8.x4.shared.b16 {%0,%1,%2,%3}, [%4];" \
        : "=r"((r)[0]), "=r"((r)[1]), "=r"((r)[2]), "=r"((r)[3]) : "r"(addr))
#define LDSM2(r, addr) \
    asm volatile("ldmatrix.sync.aligned.m8n8.x2.shared.b16 {%0,%1}, [%2];" \
        : "=r"((r)[0]), "=r"((r)[1]) : "r"(addr))
#define MMAH(d, a, b) \
    asm volatile("mma.sync.aligned.m16n8k16.row.col.f32.f16.f16.f32 " \
        "{%0,%1,%2,%3},{%4,%5,%6,%7},{%8,%9},{%0,%1,%2,%3};" \
        : "+f"((d)[0]), "+f"((d)[1]), "+f"((d)[2]), "+f"((d)[3]) \
        : "r"((a)[0]), "r"((a)[1]), "r"((a)[2]), "r"((a)[3]), "r"((b)[0]), "r"((b)[1]))

__device__ __forceinline__ float ex2f(float x) {
    float r; asm("ex2.approx.f32 %0, %1;" : "=f"(r) : "f"(x)); return r;
}
__device__ __forceinline__ float rcpf(float x) {
    float r; asm("rcp.approx.f32 %0, %1;" : "=f"(r) : "f"(x)); return r;
}
__device__ __forceinline__ float sigm(float x) { return 1.f / (1.f + __expf(-x)); }

// ---------------- geometry ----------------
#define ROWB 272
#define MATB (64 * ROWB)      // 17408 — one 64x128 fp16 tile

// xw kernel (128 threads): resident Wx tile + 2-stage A
#define XB_ROWB 1040                     // 512 fp16 + 16B pad
#define XB_MAT (64 * XB_ROWB)            // 66560
#define XA_OFF XB_MAT                    // 66560
#define XGS_OFF XA_OFF                   // Gs [64][68] f32 = 17408 — aliases A stage 0
#define SMEM_XW (XA_OFF + 2 * MATB)      // 101376

// persistent step kernel (512 threads): W resident + FULL h tile
#define WROWB 2064                       // 1024 fp16 + 16B pad
#define WMATB (32 * WROWB)               // 66048
#define H_OFF WMATB                      // 66048 ; h tile 64 rows x 2064B = 132096
#define HROWB 2064
#define GS_OFF H_OFF                     // Gs [8][32][68] f32 = 69632 — aliases h tile
#define HS_OFF (H_OFF + 64 * HROWB)      // 198144 ; HsH = 1024
#define SMEM_ST (HS_OFF + 1024)          // 199168

// ---------------- init: zero h and c, reset barrier ----------------
__global__ void init_kernel() {
    int i = blockIdx.x * blockDim.x + threadIdx.x;
    if (i == 0) g_cnt = 0;
    if (i < Bz * Hz) {
        __half z = __float2half(0.f);
        g_h[0][i] = z; g_h[1][i] = z;
        g_c[i] = 0.f;
    }
}

// ---------------- prep: sort batch by seqlen desc, active counts, tmax --------
__global__ void prep_sort(const int* __restrict__ seqlen) {
    __shared__ int sl[Bz];
    int i = threadIdx.x;          // 64 threads
    sl[i] = seqlen[i];
    __syncthreads();
    int mysl = sl[i];
    int rank = 0;
#pragma unroll
    for (int j = 0; j < Bz; j++) {
        int o = sl[j];
        if (o > mysl || (o == mysl && j < i)) rank++;
    }
    g_perm[rank] = i;
    g_slsort[rank] = mysl;
    for (int t = i; t < Sz; t += Bz) {
        int cnt = 0;
#pragma unroll
        for (int j = 0; j < Bz; j++) cnt += (sl[j] > t) ? 1 : 0;
        g_active[t] = cnt;
    }
    if (i == 0) {
        int mx = 0;
#pragma unroll
        for (int j = 0; j < Bz; j++) mx = max(mx, sl[j]);
        g_tmax = mx;
    }
}

// ---------------- prep: transpose W -> [n'=c*4+g][k] fp16 ----------------
__global__ __launch_bounds__(256) void prep_tr(const float* __restrict__ src, int K, int sel) {
    __shared__ float tile[32][33];
    int n0 = blockIdx.x * 32, k0 = blockIdx.y * 32;
    int tx = threadIdx.x & 31, ty = threadIdx.x >> 5;   // 32 x 8
#pragma unroll
    for (int r = 0; r < 4; r++)
        tile[ty + r * 8][tx] = src[(size_t)(k0 + ty + r * 8) * G4 + n0 + tx];
    __syncthreads();
    __half* dh = sel ? g_wth : g_wxh;
#pragma unroll
    for (int r = 0; r < 4; r++) {
        int n = n0 + ty + r * 8;
        int np = (n & 1023) * 4 + (n >> 10);
        dh[(size_t)np * K + k0 + tx] = __float2half_rn(tile[tx][ty + r * 8]);
    }
}

// ---------------- prep: gather emb rows (sorted batch order) -> fp16 [m][k] ----
__global__ void prep_emb(const int* __restrict__ X, const float* __restrict__ emb) {
    int m = blockIdx.x;                 // m = s*64 + r (r = sorted position)
    int s = m >> 6, r = m & 63;
    int b = g_perm[r];
    int row = X[b * Sz + s];
    const float4* src = (const float4*)(emb + (size_t)row * Ez);
    int k4 = threadIdx.x;               // 128 threads
    float4 v = src[k4];
    __half2* dh = (__half2*)(g_af + (size_t)m * Ez);
    dh[k4 * 2]     = __floats2half2_rn(v.x, v.y);
    dh[k4 * 2 + 1] = __floats2half2_rn(v.z, v.w);
}

__global__ void prep_bias(const float* __restrict__ bias) {
    int n = blockIdx.x * blockDim.x + threadIdx.x;
    if (n < G4) g_bias2[(n & 1023) * 4 + (n >> 10)] = bias[n];
}

// ---------------- xw GEMM with active-row masking ----------
__global__ __launch_bounds__(128, 2) void xw_mma() {
    extern __shared__ char smem[];
    const uint32_t sb = smem_u32(smem);
    const int tid = threadIdx.x, lane = tid & 31, w = tid >> 5;
    const int np0 = blockIdx.x * 64;
    const int sg = blockIdx.y * 4;
    const int mbase = (w & 1) * 32, nbase = (w >> 1) * 32;

    // resident Wx tile: 64 n' x 512 k fp16
#pragma unroll
    for (int i = 0; i < 32; i++) {
        int idx = i * 128 + tid;
        int row = idx >> 6, seg = idx & 63;
        CP16(sb + row * XB_ROWB + seg * 16,
             (const char*)(g_wxh + (size_t)(np0 + row) * Ez) + seg * 16);
    }
    CP_COMMIT();

    float* Gs = (float*)(smem + XGS_OFF);          // [64 n'][68 m], aliases A stage 0

    for (int si = 0; si < 4; si++) {
        const int s = sg + si;
        const int act = g_active[s];
        if (act == 0) continue;                    // uniform per CTA
        const bool m0 = (mbase < act);
        const bool m1 = (mbase + 16 < act);
        const __half* Af = g_af + (size_t)s * Bz * Ez;

#pragma unroll
        for (int i = 0; i < 8; i++) {
            int idx = i * 128 + tid;
            int row = idx >> 4, seg = idx & 15;
            CP16(sb + XA_OFF + row * ROWB + seg * 16,
                 (const char*)(Af + (size_t)row * Ez) + seg * 16);
        }
        CP_COMMIT();

        float acc[2][4][4] = {};
#pragma unroll
        for (int c = 0; c < 4; c++) {
            CP_WAITN(0);
            __syncthreads();
            if (c < 3) {
#pragma unroll
                for (int i = 0; i < 8; i++) {
                    int idx = i * 128 + tid;
                    int row = idx >> 4, seg = idx & 15;
                    CP16(sb + XA_OFF + (uint32_t)((c + 1) & 1) * MATB + row * ROWB + seg * 16,
                         (const char*)(Af + (size_t)row * Ez + (c + 1) * 128) + seg * 16);
                }
                CP_COMMIT();
            }
            if (m0) {
                const uint32_t abuf = sb + XA_OFF + (uint32_t)(c & 1) * MATB;
                const int arow = lane & 15;
                const int ahalf = (lane >> 4) * 16;
                const int brow = lane & 7;
                const int bhalf = ((lane >> 3) & 1) * 16;
#pragma unroll
                for (int k16 = 0; k16 < 8; k16++) {
                    uint32_t ah[2][4], bh[4][2];
                    uint32_t ao0 = (uint32_t)((mbase + arow) * ROWB) + k16 * 32 + ahalf;
                    LDSM4(ah[0], abuf + ao0);
                    if (m1) LDSM4(ah[1], abuf + ao0 + 16 * ROWB);
                    const uint32_t kwb = (uint32_t)(c * 256 + k16 * 32) + bhalf;
#pragma unroll
                    for (int nt = 0; nt < 4; nt++) {
                        uint32_t bo = (uint32_t)((nbase + nt * 8 + brow) * XB_ROWB) + kwb;
                        LDSM2(bh[nt], sb + bo);
                    }
#pragma unroll
                    for (int nt = 0; nt < 4; nt++) MMAH(acc[0][nt], ah[0], bh[nt]);
                    if (m1) {
#pragma unroll
                        for (int nt = 0; nt < 4; nt++) MMAH(acc[1][nt], ah[1], bh[nt]);
                    }
                }
            }
        }
        __syncthreads();

        {
            const int r = lane >> 2, c2 = (lane & 3) * 2;
#pragma unroll
            for (int mt = 0; mt < 2; mt++)
#pragma unroll
                for (int nt = 0; nt < 4; nt++) {
                    int m = mbase + mt * 16 + r;
                    int n = nbase + nt * 8 + c2;
                    Gs[n * 68 + m]           = acc[mt][nt][0];
                    Gs[(n + 1) * 68 + m]     = acc[mt][nt][1];
                    Gs[n * 68 + m + 8]       = acc[mt][nt][2];
                    Gs[(n + 1) * 68 + m + 8] = acc[mt][nt][3];
                }
        }
        __syncthreads();

        float* outb = g_xw2 + ((size_t)s * G4 + np0) * Bz;
#pragma unroll
        for (int i = 0; i < 32; i++) {
            int e = i * 128 + tid;
            int nl = e >> 6, b = e & 63;
            outb[e] = Gs[nl * 68 + b] + g_bias2[np0 + nl];
        }
        __syncthreads();
    }
}

// ---------------- persistent LSTM recurrence with active-row masking ----------
__device__ __forceinline__ void gbar(int t, int tid) {
    __syncthreads();
    if (tid == 0) {
        asm volatile("red.add.release.gpu.global.s32 [%0], 1;"
                     :: "l"(&g_cnt) : "memory");
        int f;
        const int target = 128 * t;
        do {
            asm volatile("ld.acquire.gpu.global.s32 %0, [%1];" : "=r"(f) : "l"(&g_cnt));
        } while (f < target);
    }
    __syncthreads();
}

__global__ __launch_bounds__(512, 1) void steps_persistent() {
    extern __shared__ char smem[];
    const uint32_t sb = smem_u32(smem);
    const int tid = threadIdx.x, lane = tid & 31, w = tid >> 5;
    const int blk = blockIdx.x;
    const int np0 = blk * 32, c0 = blk * 8;
    const int mh = w & 1;                // batch half (32 rows)
    const int ksub = w >> 1;             // k16 phase (0..7); covers kk = c*8+ksub
    const int bidx = tid & 63;
    const int sl_b = g_slsort[bidx];     // seqlen for sorted row bidx
    const int ob   = g_perm[bidx];       // original batch index
    const int tmax = g_tmax;
    const float LOG2E = 1.4426950408889634f;

    // ---- load W resident: 32 rows x 1024 k fp16 ----
#pragma unroll
    for (int i = 0; i < 8; i++) {
        int idx = i * 512 + tid;
        int row = idx >> 7, seg = idx & 127;
        CP16(sb + row * WROWB + seg * 16,
             (const char*)(g_wth + (size_t)(np0 + row) * Hz) + seg * 16);
    }
    CP_COMMIT();

    float* Gs = (float*)(smem + GS_OFF);                     // [8 ksub][32 n'][68 m]
    __half* HsH = (__half*)(smem + HS_OFF);                  // [64][8]

    for (int t = 0; t < tmax; t++) {
        const __half* h_in = g_h[t & 1];
        __half* h_out = g_h[(t + 1) & 1];
        const int act = __ldg(&g_active[t]);                 // rows b < act are live

        // epilogue operand prefetch — before barrier
        const float* xwb = g_xw2 + ((size_t)t * G4 + np0) * Bz;
        float xg[4], cold;
        {
            const int col = tid >> 6;
#pragma unroll
            for (int g = 0; g < 4; g++)
                xg[g] = __ldg(xwb + (col * 4 + g) * Bz + bidx);
            cold = g_c[(c0 + col) * Bz + bidx];
        }

        if (t > 0) gbar(t, tid);                             // all CTAs finished t-1

        // one-shot h load for live rows only
#pragma unroll
        for (int i = 0; i < 16; i++) {
            int idx = i * 512 + tid;                         // 0..8191
            int row = idx >> 7, seg = idx & 127;
            if (row < act)
                CP16(sb + H_OFF + row * HROWB + seg * 16,
                     (const char*)(h_in + (size_t)row * Hz) + seg * 16);
        }
        CP_COMMIT();
        CP_WAITN(0);
        __syncthreads();

        float acc[2][4][4] = {};                             // [mt][nt][4], tile 32x32
        const bool m0 = (mh * 32) < act;
        const bool m1 = (mh * 32 + 16) < act;
        if (m0) {
            const int arow = lane & 15;
            const int ahalf = (lane >> 4) * 16;
            const int brow = lane & 7;
            const int bhalf = ((lane >> 3) & 1) * 16;
#pragma unroll
            for (int c = 0; c < 8; c++) {
                const int kk = c * 8 + ksub;                 // global k16 index 0..63
                uint32_t ah[2][4], bh[4][2];
                uint32_t ao0 = (uint32_t)((mh * 32 + arow) * HROWB) + kk * 32 + ahalf;
                LDSM4(ah[0], sb + H_OFF + ao0);
                if (m1) LDSM4(ah[1], sb + H_OFF + ao0 + 16 * HROWB);
                const uint32_t kwb = (uint32_t)kk * 32 + bhalf;
#pragma unroll
                for (int nt = 0; nt < 4; nt++) {
                    uint32_t bo = (uint32_t)((nt * 8 + brow) * WROWB) + kwb;
                    LDSM2(bh[nt], sb + bo);
                }
#pragma unroll
                for (int nt = 0; nt < 4; nt++) MMAH(acc[0][nt], ah[0], bh[nt]);
                if (m1) {
#pragma unroll
                    for (int nt = 0; nt < 4; nt++) MMAH(acc[1][nt], ah[1], bh[nt]);
                }
            }
        }
        __syncthreads();                                     // all h reads done

        // write live partials to private strip (Gs aliases h tile, dead now)
        if (m0) {
            float* strip = Gs + ksub * (32 * 68);
            const int r = lane >> 2, c2 = (lane & 3) * 2;
#pragma unroll
            for (int mt = 0; mt < 2; mt++) {
                if (mt == 1 && !m1) break;
#pragma unroll
                for (int nt = 0; nt < 4; nt++) {
                    int m = mh * 32 + mt * 16 + r;
                    int n = nt * 8 + c2;
                    strip[n * 68 + m]           = acc[mt][nt][0];
                    strip[(n + 1) * 68 + m]     = acc[mt][nt][1];
                    strip[n * 68 + m + 8]       = acc[mt][nt][2];
                    strip[(n + 1) * 68 + m + 8] = acc[mt][nt][3];
                }
            }
        }
        __syncthreads();

        // pointwise LSTM for live rows (MUFU-lean: 5 ex2 + 3 rcp)
        if (bidx < act) {
            const int col = tid >> 6;
            float gg[4];
#pragma unroll
            for (int g = 0; g < 4; g++) {
                int off = (col * 4 + g) * 68 + bidx;
                float s0 = Gs[off]            + Gs[off + 2176];
                float s1 = Gs[off + 2 * 2176] + Gs[off + 3 * 2176];
                float s2 = Gs[off + 4 * 2176] + Gs[off + 5 * 2176];
                float s3 = Gs[off + 6 * 2176] + Gs[off + 7 * 2176];
                gg[g] = ((s0 + s1) + (s2 + s3)) + xg[g];
            }
            // sigm(f+1), sigm(i)*tanh(j), tanh(cn)*sigm(o) with shared reciprocals
            float a  = ex2f(-LOG2E * gg[0]);                       // e^{-i}
            float jc = fminf(fmaxf(gg[1], -15.f), 15.f);
            float bb = ex2f(2.f * LOG2E * jc);                     // e^{2j}
            float e1 = ex2f(-LOG2E * (gg[2] + 1.f));               // e^{-(f+1)}
            float cn = cold * rcpf(1.f + e1)
                     + (bb - 1.f) * rcpf((1.f + a) * (bb + 1.f));
            float cc2 = fminf(fmaxf(cn, -15.f), 15.f);
            float d  = ex2f(2.f * LOG2E * cc2);                    // e^{2cn}
            float e2 = ex2f(-LOG2E * gg[3]);                       // e^{-o}
            float hn = (d - 1.f) * rcpf((d + 1.f) * (1.f + e2));
            g_c[(c0 + col) * Bz + bidx] = cn;
            HsH[bidx * 8 + col] = __float2half_rn(hn);
            if (t == sl_b - 1) g_final[(size_t)ob * Hz + c0 + col] = hn;
        }
        __syncthreads();

        // coalesced 16B h writes for live rows
        if (tid < 64 && tid < act) {
            *(uint4*)(h_out + (size_t)tid * Hz + c0) = *(uint4*)(HsH + tid * 8);
        }
    }
}

// ---------------- dense = relu(final @ dense_w + dense_b) ----------------
__global__ void dense_kernel(const float* __restrict__ dw, const float* __restrict__ db) {
    int b = blockIdx.x;
    int d = threadIdx.x;    // 512 threads
    const float* f = g_final + (size_t)b * Hz;
    float s0 = 0.f, s1 = 0.f, s2 = 0.f, s3 = 0.f;
#pragma unroll 4
    for (int k = 0; k < Hz; k += 4) {
        s0 += f[k]     * dw[(size_t)(k)     * Dz + d];
        s1 += f[k + 1] * dw[(size_t)(k + 1) * Dz + d];
        s2 += f[k + 2] * dw[(size_t)(k + 2) * Dz + d];
        s3 += f[k + 3] * dw[(size_t)(k + 3) * Dz + d];
    }
    float s = (s0 + s1) + (s2 + s3) + db[d];
    g_dense[(size_t)b * Dz + d] = fmaxf(s, 0.f);
}

// ---------------- logits = dense @ pred_w + pred_b ----------------
__global__ void logits_kernel(const float* __restrict__ pw, const float* __restrict__ pb,
                              float* __restrict__ out) {
    int tid = threadIdx.x;
    if (tid >= Bz * Cz) return;
    int b = tid >> 1;
    int cc = tid & 1;
    const float* dn = g_dense + (size_t)b * Dz;
    float s = 0.f;
#pragma unroll 4
    for (int d = 0; d < Dz; d++) s += dn[d] * pw[(size_t)d * Cz + cc];
    out[b * Cz + cc] = s + pb[cc];
}

// ---------------- launch ----------------
extern "C" void kernel_launch(void* const* d_in, const int* in_sizes, int n_in,
                              void* d_out, int out_size) {
    const int*   X      = (const int*)d_in[0];
    const int*   seqlen = (const int*)d_in[1];
    const float* emb    = (const float*)d_in[2];
    const float* Wf     = (const float*)d_in[3];   // [1536, 4096]
    const float* bias   = (const float*)d_in[4];
    const float* dw     = (const float*)d_in[5];
    const float* db     = (const float*)d_in[6];
    const float* pw     = (const float*)d_in[7];
    const float* pb     = (const float*)d_in[8];
    float* out = (float*)d_out;

    cudaFuncSetAttribute(xw_mma, cudaFuncAttributeMaxDynamicSharedMemorySize, SMEM_XW);
    cudaFuncSetAttribute(steps_persistent, cudaFuncAttributeMaxDynamicSharedMemorySize, SMEM_ST);

    init_kernel<<<(Bz * Hz + 255) / 256, 256>>>();
    prep_sort<<<1, Bz>>>(seqlen);
    prep_tr<<<dim3(G4 / 32, Ez / 32), 256>>>(Wf, Ez, 0);                   // Wx -> fp16
    prep_tr<<<dim3(G4 / 32, Hz / 32), 256>>>(Wf + (size_t)Ez * G4, Hz, 1); // Wh -> fp16
    prep_emb<<<Sz * Bz, 128>>>(X, emb);
    prep_bias<<<G4 / 256, 256>>>(bias);

    xw_mma<<<dim3(G4 / 64, Sz / 4), 128, SMEM_XW>>>();

    steps_persistent<<<128, 512, SMEM_ST>>>();

    dense_kernel<<<Bz, Dz>>>(dw, db);
    logits_kernel<<<1, 128>>>(pw, pb, out);
}